// round 1
// baseline (speedup 1.0000x reference)
#include <cuda_runtime.h>
#include <math.h>

// Problem constants
#define Hh   16
#define Kh   64
#define Dd   1024
#define Mf   4096
#define Ss   2048
#define Bb   4
#define NTOK (Ss*Bb)      // 8192
#define BH   (Bb*Hh)      // 64
#define EPSL 1e-5f

// ---------------- scratch (device globals: allocation-free) ----------------
__device__ float g_q[(size_t)NTOK*Dd];
__device__ float g_k[(size_t)NTOK*Dd];
__device__ float g_v[(size_t)NTOK*Dd];
__device__ float g_scores[(size_t)BH*Ss*Ss];       // 1 GiB
__device__ float g_av[(size_t)NTOK*Dd];
__device__ float g_attn[(size_t)NTOK*Dd];          // proj + residual (pre-LN1)
__device__ float g_u[(size_t)NTOK*Dd];             // LN1 output
__device__ float g_h1[(size_t)NTOK*Mf];            // FFN hidden
__device__ float g_z[(size_t)NTOK*Dd];             // FFN out + residual (pre-LN2)

// ---------------- generic tiled SGEMM ----------------
// C[M,N] = alpha * A @ op(B)  (+ bias[n]) (+ add[m,n]) (+ relu)
// TRANS_B=true : B is [N,Kd] row-major (compute A @ B^T)
// TRANS_B=false: B is [Kd,N] row-major (compute A @ B)
// All of Md%64==0, Nd%64==0, Kd%16==0 hold for every call here.
template<bool TRANS_B>
__global__ void sgemm_kernel(const float* __restrict__ A,
                             const float* __restrict__ B,
                             float* __restrict__ C,
                             int Md, int Nd, int Kd,
                             long lda, long ldb, long ldc,
                             long sA, long sB, long sC,
                             float alpha,
                             const float* __restrict__ add, long ldadd, long sAdd,
                             const float* __restrict__ bias,
                             int doRelu)
{
    const int BM = 64, BN = 64, BK = 16;
    __shared__ float As[BK][BM + 1];
    __shared__ float Bs[BK][BN + 1];

    const int bz = blockIdx.z;
    A += (size_t)bz * sA;
    B += (size_t)bz * sB;
    C += (size_t)bz * sC;
    if (add) add += (size_t)bz * sAdd;

    const int m0  = blockIdx.y * BM;
    const int n0  = blockIdx.x * BN;
    const int tid = threadIdx.x;          // 256 threads
    const int tx  = tid & 15;
    const int ty  = tid >> 4;

    float acc[4][4] = {};

    for (int k0 = 0; k0 < Kd; k0 += BK) {
        // ---- load A tile: 64 rows x 16 k  (16-thread coalesced rows) ----
        #pragma unroll
        for (int i = 0; i < 4; i++) {
            int idx = tid + i * 256;
            int m = idx >> 4;
            int k = idx & 15;
            As[k][m] = A[(size_t)(m0 + m) * lda + (k0 + k)];
        }
        // ---- load B tile ----
        #pragma unroll
        for (int i = 0; i < 4; i++) {
            int idx = tid + i * 256;
            if (TRANS_B) {
                int n = idx >> 4;
                int k = idx & 15;
                Bs[k][n] = B[(size_t)(n0 + n) * ldb + (k0 + k)];
            } else {
                int n = idx & 63;
                int k = idx >> 6;
                Bs[k][n] = B[(size_t)(k0 + k) * ldb + (n0 + n)];
            }
        }
        __syncthreads();

        #pragma unroll
        for (int kk = 0; kk < BK; kk++) {
            float a[4], b[4];
            #pragma unroll
            for (int i = 0; i < 4; i++) a[i] = As[kk][ty * 4 + i];
            #pragma unroll
            for (int j = 0; j < 4; j++) b[j] = Bs[kk][tx * 4 + j];
            #pragma unroll
            for (int i = 0; i < 4; i++)
                #pragma unroll
                for (int j = 0; j < 4; j++)
                    acc[i][j] += a[i] * b[j];
        }
        __syncthreads();
    }

    #pragma unroll
    for (int i = 0; i < 4; i++) {
        int m = m0 + ty * 4 + i;
        #pragma unroll
        for (int j = 0; j < 4; j++) {
            int n = n0 + tx * 4 + j;
            float v = acc[i][j] * alpha;
            if (bias) v += bias[n];
            if (add)  v += add[(size_t)m * ldadd + n];
            if (doRelu) v = fmaxf(v, 0.0f);
            C[(size_t)m * ldc + n] = v;
        }
    }
}

// ---------------- softmax over last dim with additive mask ----------------
// grid: (Ss, BH) ; block: 256 ; row length Ss = 2048 (8 per thread)
__global__ void softmax_mask_kernel(float* __restrict__ scores,
                                    const float* __restrict__ mask)
{
    const int s  = blockIdx.x;
    const int bh = blockIdx.y;
    float* row        = scores + ((size_t)bh * Ss + s) * Ss;
    const float* mrow = mask + (size_t)s * Ss;
    const int tid = threadIdx.x;

    float vals[8];
    float mx = -INFINITY;
    #pragma unroll
    for (int i = 0; i < 8; i++) {
        int t = tid + i * 256;
        vals[i] = row[t] + mrow[t];
        mx = fmaxf(mx, vals[i]);
    }
    __shared__ float red[256];
    red[tid] = mx; __syncthreads();
    for (int off = 128; off > 0; off >>= 1) {
        if (tid < off) red[tid] = fmaxf(red[tid], red[tid + off]);
        __syncthreads();
    }
    mx = red[0];
    __syncthreads();

    float sum = 0.0f;
    #pragma unroll
    for (int i = 0; i < 8; i++) { vals[i] = __expf(vals[i] - mx); sum += vals[i]; }
    red[tid] = sum; __syncthreads();
    for (int off = 128; off > 0; off >>= 1) {
        if (tid < off) red[tid] += red[tid + off];
        __syncthreads();
    }
    float inv = 1.0f / red[0];
    #pragma unroll
    for (int i = 0; i < 8; i++) row[tid + i * 256] = vals[i] * inv;
}

// ---------------- layernorm over D=1024 ----------------
// grid: NTOK ; block: 256 (4 per thread)
__global__ void layernorm_kernel(const float* __restrict__ in,
                                 float* __restrict__ out,
                                 const float* __restrict__ gamma,
                                 const float* __restrict__ beta)
{
    const int row = blockIdx.x;
    const float* x = in + (size_t)row * Dd;
    float* y       = out + (size_t)row * Dd;
    const int tid = threadIdx.x;

    float v[4];
    float s = 0.0f, s2 = 0.0f;
    #pragma unroll
    for (int i = 0; i < 4; i++) {
        v[i] = x[tid + i * 256];
        s  += v[i];
        s2 += v[i] * v[i];
    }
    __shared__ float r1[256], r2[256];
    r1[tid] = s; r2[tid] = s2; __syncthreads();
    for (int off = 128; off > 0; off >>= 1) {
        if (tid < off) { r1[tid] += r1[tid + off]; r2[tid] += r2[tid + off]; }
        __syncthreads();
    }
    float mean = r1[0] * (1.0f / Dd);
    float var  = r2[0] * (1.0f / Dd) - mean * mean;
    float inv  = rsqrtf(var + EPSL);
    #pragma unroll
    for (int i = 0; i < 4; i++) {
        int c = tid + i * 256;
        y[c] = (v[i] - mean) * inv * gamma[c] + beta[c];
    }
}

// ---------------- host-side launch helpers ----------------
static inline void gemm_nt(const float* A, const float* B, float* C,
                           int Md, int Nd, int Kd,
                           long lda, long ldb, long ldc,
                           long sA, long sB, long sC, int batch,
                           float alpha,
                           const float* add, long ldadd, long sAdd,
                           const float* bias, int relu)
{
    dim3 grid(Nd / 64, Md / 64, batch);
    sgemm_kernel<true><<<grid, 256>>>(A, B, C, Md, Nd, Kd, lda, ldb, ldc,
                                      sA, sB, sC, alpha, add, ldadd, sAdd, bias, relu);
}

static inline void gemm_nn(const float* A, const float* B, float* C,
                           int Md, int Nd, int Kd,
                           long lda, long ldb, long ldc,
                           long sA, long sB, long sC, int batch,
                           float alpha)
{
    dim3 grid(Nd / 64, Md / 64, batch);
    sgemm_kernel<false><<<grid, 256>>>(A, B, C, Md, Nd, Kd, lda, ldb, ldc,
                                       sA, sB, sC, alpha, nullptr, 0, 0, nullptr, 0);
}

extern "C" void kernel_launch(void* const* d_in, const int* in_sizes, int n_in,
                              void* d_out, int out_size)
{
    const float* x     = (const float*)d_in[0];   // (S,B,D) -> rows s*B+b
    const float* mask  = (const float*)d_in[1];   // (S,S)
    const float* wq    = (const float*)d_in[2];   // (HK,D)
    const float* wk    = (const float*)d_in[3];
    const float* wv    = (const float*)d_in[4];
    const float* wc    = (const float*)d_in[5];   // (D,HK)
    const float* w1_w  = (const float*)d_in[6];   // (M,D)
    const float* w1_b  = (const float*)d_in[7];   // (M,)
    const float* w2_w  = (const float*)d_in[8];   // (D,M)
    const float* w2_b  = (const float*)d_in[9];   // (D,)
    const float* ln1_g = (const float*)d_in[10];
    const float* ln1_b = (const float*)d_in[11];
    const float* ln2_g = (const float*)d_in[12];
    const float* ln2_b = (const float*)d_in[13];
    float* out = (float*)d_out;

    float *q, *k, *v, *scores, *av, *attn, *u, *h1, *z;
    cudaGetSymbolAddress((void**)&q,      g_q);
    cudaGetSymbolAddress((void**)&k,      g_k);
    cudaGetSymbolAddress((void**)&v,      g_v);
    cudaGetSymbolAddress((void**)&scores, g_scores);
    cudaGetSymbolAddress((void**)&av,     g_av);
    cudaGetSymbolAddress((void**)&attn,   g_attn);
    cudaGetSymbolAddress((void**)&u,      g_u);
    cudaGetSymbolAddress((void**)&h1,     g_h1);
    cudaGetSymbolAddress((void**)&z,      g_z);

    // 1) QKV projections: (NTOK,D) @ (HK,D)^T -> (NTOK,HK)
    gemm_nt(x, wq, q, NTOK, Dd, Dd, Dd, Dd, Dd, 0, 0, 0, 1, 1.0f, nullptr, 0, 0, nullptr, 0);
    gemm_nt(x, wk, k, NTOK, Dd, Dd, Dd, Dd, Dd, 0, 0, 0, 1, 1.0f, nullptr, 0, 0, nullptr, 0);
    gemm_nt(x, wv, v, NTOK, Dd, Dd, Dd, Dd, Dd, 0, 0, 0, 1, 1.0f, nullptr, 0, 0, nullptr, 0);

    // 2) scores[bh,s,t] = (1/sqrt(K)) * q[s,bh,:] . k[t,bh,:]
    //    batch z=b*H+h: A/B offset z*K, row stride B*H*K=4096
    gemm_nt(q, k, scores,
            Ss, Ss, Kh,
            (long)Bb * Hh * Kh, (long)Bb * Hh * Kh, Ss,
            Kh, Kh, (long)Ss * Ss, BH,
            0.125f, nullptr, 0, 0, nullptr, 0);

    // 3) softmax with additive mask
    {
        dim3 grid(Ss, BH);
        softmax_mask_kernel<<<grid, 256>>>(scores, mask);
    }

    // 4) av[s,bh,k] = sum_t alpha[bh,s,t] * v[t,bh,k]   (NN batched)
    gemm_nn(scores, v, av,
            Ss, Kh, Ss,
            Ss, (long)Bb * Hh * Kh, (long)Bb * Hh * Kh,
            (long)Ss * Ss, Kh, Kh, BH,
            1.0f);

    // 5) attn = av @ wc^T + x ; u = LN1(attn)
    gemm_nt(av, wc, attn, NTOK, Dd, Dd, Dd, Dd, Dd, 0, 0, 0, 1, 1.0f, x, Dd, 0, nullptr, 0);
    layernorm_kernel<<<NTOK, 256>>>(attn, u, ln1_g, ln1_b);

    // 6) h1 = relu(u @ w1^T + b1)
    gemm_nt(u, w1_w, h1, NTOK, Mf, Dd, Dd, Dd, Mf, 0, 0, 0, 1, 1.0f, nullptr, 0, 0, w1_b, 1);

    // 7) z = h1 @ w2^T + b2 + u
    gemm_nt(h1, w2_w, z, NTOK, Dd, Mf, Mf, Mf, Dd, 0, 0, 0, 1, 1.0f, u, Dd, 0, w2_b, 0);

    // 8) out = LN2(z)
    layernorm_kernel<<<NTOK, 256>>>(z, out, ln2_g, ln2_b);
}

// round 3
// speedup vs baseline: 3.3514x; 3.3514x over previous
#include <cuda_runtime.h>
#include <cuda_bf16.h>
#include <cstdint>
#include <math.h>

#define Hh   16
#define Kh   64
#define Dd   1024
#define Mf   4096
#define Ss   2048
#define Bb   4
#define NTOK (Ss*Bb)      // 8192
#define BH   (Bb*Hh)      // 64
#define EPSL 1e-5f

// ---------------- scratch buffers (device globals: allocation-free) ----------------
__device__ __nv_bfloat16 g_x_h[(size_t)NTOK*Dd],  g_x_l[(size_t)NTOK*Dd];
__device__ __nv_bfloat16 g_wq_h[(size_t)Dd*Dd],   g_wq_l[(size_t)Dd*Dd];
__device__ __nv_bfloat16 g_wk_h[(size_t)Dd*Dd],   g_wk_l[(size_t)Dd*Dd];
__device__ __nv_bfloat16 g_wv_h[(size_t)Dd*Dd],   g_wv_l[(size_t)Dd*Dd];
__device__ __nv_bfloat16 g_wc_h[(size_t)Dd*Dd],   g_wc_l[(size_t)Dd*Dd];
__device__ __nv_bfloat16 g_w1_h[(size_t)Mf*Dd],   g_w1_l[(size_t)Mf*Dd];
__device__ __nv_bfloat16 g_w2_h[(size_t)Mf*Dd],   g_w2_l[(size_t)Mf*Dd];
__device__ __nv_bfloat16 g_q_h[(size_t)NTOK*Dd],  g_q_l[(size_t)NTOK*Dd];
__device__ __nv_bfloat16 g_k_h[(size_t)NTOK*Dd],  g_k_l[(size_t)NTOK*Dd];
__device__ float         g_v[(size_t)NTOK*Dd];
__device__ __nv_bfloat16 g_vt_h[(size_t)BH*Kh*Ss], g_vt_l[(size_t)BH*Kh*Ss];
__device__ float         g_sc[(size_t)BH*Ss*Ss];                 // 1 GiB
__device__ __nv_bfloat16 g_sch[(size_t)BH*Ss*Ss], g_scl[(size_t)BH*Ss*Ss];
__device__ __nv_bfloat16 g_av_h[(size_t)NTOK*Dd], g_av_l[(size_t)NTOK*Dd];
__device__ float         g_attn[(size_t)NTOK*Dd];
__device__ float         g_u[(size_t)NTOK*Dd];
__device__ __nv_bfloat16 g_u_h[(size_t)NTOK*Dd],  g_u_l[(size_t)NTOK*Dd];
__device__ __nv_bfloat16 g_h1_h[(size_t)NTOK*Mf], g_h1_l[(size_t)NTOK*Mf];
__device__ float         g_z[(size_t)NTOK*Dd];

// ---------------- helpers ----------------
__device__ __forceinline__ uint32_t smem_u32(const void* p){
    uint32_t a;
    asm("{ .reg .u64 t; cvta.to.shared.u64 t, %1; cvt.u32.u64 %0, t; }" : "=r"(a) : "l"(p));
    return a;
}
__device__ __forceinline__ void split2(float x, __nv_bfloat16& h, __nv_bfloat16& l){
    h = __float2bfloat16(x);
    l = __float2bfloat16(x - __bfloat162float(h));
}
__device__ __forceinline__ void cpasync16(uint32_t saddr, const void* gaddr){
    asm volatile("cp.async.cg.shared.global [%0], [%1], 16;" :: "r"(saddr), "l"(gaddr) : "memory");
}
__device__ __forceinline__ void ldmx4(uint32_t* r, uint32_t addr){
    asm volatile("ldmatrix.sync.aligned.m8n8.x4.shared.b16 {%0,%1,%2,%3}, [%4];"
                 : "=r"(r[0]), "=r"(r[1]), "=r"(r[2]), "=r"(r[3]) : "r"(addr));
}
__device__ __forceinline__ void mma16816(float* c, const uint32_t* a, const uint32_t* b){
    asm volatile("mma.sync.aligned.m16n8k16.row.col.f32.bf16.bf16.f32 "
                 "{%0,%1,%2,%3}, {%4,%5,%6,%7}, {%8,%9}, {%0,%1,%2,%3};"
                 : "+f"(c[0]), "+f"(c[1]), "+f"(c[2]), "+f"(c[3])
                 : "r"(a[0]), "r"(a[1]), "r"(a[2]), "r"(a[3]), "r"(b[0]), "r"(b[1]));
}

// ---------------- mma.sync bf16x3 NT GEMM ----------------
// C[128 x BN per CTA] = alpha * A @ B^T (+bias[n]) (+add[m,n]) (+relu)
// A: [M,K] bf16 hi/lo (K-contig), B: [N,K] bf16 hi/lo (K-contig).
// Output fp32 (Cf) or bf16 hi/lo pair (Ch/Cl) if Ch != nullptr.
// Requires Kd % 32 == 0, Kd >= 64.
template<int BN>
__global__ void __launch_bounds__(256) mma_gemm(
    const __nv_bfloat16* __restrict__ Ah, const __nv_bfloat16* __restrict__ Al,
    const __nv_bfloat16* __restrict__ Bh, const __nv_bfloat16* __restrict__ Bl,
    float* __restrict__ Cf, __nv_bfloat16* __restrict__ Ch, __nv_bfloat16* __restrict__ Cl,
    int Kd, long lda, long ldb, long ldc,
    long sA, long sB, long sC,
    float alpha, const float* __restrict__ add, long ldadd,
    const float* __restrict__ bias, int doRelu)
{
    constexpr int BK   = 32;                 // halves per k-stage
    constexpr int LDS  = BK + 8;             // 40 halves = 80 bytes/row
    constexpr int WN   = BN / 2;             // warp n-extent
    constexpr int NT   = WN / 8;             // n8 tiles per warp (8 or 4)
    constexpr int A_BYTES = 128 * LDS * 2;   // 10240
    constexpr int B_BYTES = BN  * LDS * 2;
    constexpr int STAGE   = 2 * A_BYTES + 2 * B_BYTES;

    extern __shared__ char smc[];
    const uint32_t sbase = smem_u32(smc);

    const int tid  = threadIdx.x;
    const int lane = tid & 31;
    const int wid  = tid >> 5;
    const int warpM = (wid & 3) * 32;
    const int warpN = (wid >> 2) * WN;

    const long aOff = (long)blockIdx.z * sA;
    const long bOff = (long)blockIdx.z * sB;
    const long cOff = (long)blockIdx.z * sC;
    const int  m0   = blockIdx.y * 128;
    const int  n0   = blockIdx.x * BN;
    const int  KT   = Kd / BK;

    // per-thread load indices
    const int la_row = tid >> 2, la_ch = tid & 3;   // A: 128 rows x 4 chunks over 2 iters
    // stage loader
    auto load_stage = [&](int kt, int buf){
        const int k0 = kt * BK;
        const uint32_t s0 = sbase + buf * STAGE;
        #pragma unroll
        for (int it = 0; it < 2; it++){
            int row = la_row + it * 64;
            long g = aOff + (long)(m0 + row) * lda + k0 + la_ch * 8;
            uint32_t so = (uint32_t)(row * (LDS * 2) + la_ch * 16);
            cpasync16(s0 + so,           Ah + g);
            cpasync16(s0 + A_BYTES + so, Al + g);
        }
        #pragma unroll
        for (int it = 0; it < BN / 64; it++){
            int row = la_row + it * 64;
            long g = bOff + (long)(n0 + row) * ldb + k0 + la_ch * 8;
            uint32_t so = (uint32_t)(row * (LDS * 2) + la_ch * 16);
            cpasync16(s0 + 2*A_BYTES + so,           Bh + g);
            cpasync16(s0 + 2*A_BYTES + B_BYTES + so, Bl + g);
        }
    };

    load_stage(0, 0);
    asm volatile("cp.async.commit_group;" ::: "memory");
    load_stage(1, 1);
    asm volatile("cp.async.commit_group;" ::: "memory");

    float acc[2][NT][4];
    #pragma unroll
    for (int i = 0; i < 2; i++)
        #pragma unroll
        for (int j = 0; j < NT; j++)
            #pragma unroll
            for (int e = 0; e < 4; e++) acc[i][j][e] = 0.0f;

    // per-lane ldmatrix offsets (in halves, within a buffer)
    const int aRow = (lane & 15), aColHalf = (lane >> 4) * 8;
    const int bRow = (lane >> 4) * 8 + (lane & 7), bColHalf = ((lane >> 3) & 1) * 8;

    for (int kt = 0; kt < KT; kt++){
        asm volatile("cp.async.wait_group 1;" ::: "memory");
        __syncthreads();
        const int buf = kt & 1;
        const uint32_t sA0 = sbase + buf * STAGE;
        const uint32_t sB0 = sA0 + 2 * A_BYTES;

        #pragma unroll
        for (int ks = 0; ks < 2; ks++){
            const int k16 = ks * 16;
            uint32_t ah[2][4], al[2][4];
            #pragma unroll
            for (int mt = 0; mt < 2; mt++){
                uint32_t addr = sA0 + (uint32_t)(((warpM + mt*16 + aRow) * LDS + k16 + aColHalf) * 2);
                ldmx4(ah[mt], addr);
                ldmx4(al[mt], addr + A_BYTES);
            }
            uint32_t bh[NT][2], bl[NT][2];
            #pragma unroll
            for (int g = 0; g < NT/2; g++){
                uint32_t addr = sB0 + (uint32_t)(((warpN + g*16 + bRow) * LDS + k16 + bColHalf) * 2);
                uint32_t r[4];
                ldmx4(r, addr);
                bh[2*g][0] = r[0]; bh[2*g][1] = r[1];
                bh[2*g+1][0] = r[2]; bh[2*g+1][1] = r[3];
                ldmx4(r, addr + B_BYTES);
                bl[2*g][0] = r[0]; bl[2*g][1] = r[1];
                bl[2*g+1][0] = r[2]; bl[2*g+1][1] = r[3];
            }
            #pragma unroll
            for (int mt = 0; mt < 2; mt++)
                #pragma unroll
                for (int j = 0; j < NT; j++){
                    mma16816(acc[mt][j], ah[mt], bh[j]);   // hi*hi
                    mma16816(acc[mt][j], ah[mt], bl[j]);   // hi*lo
                    mma16816(acc[mt][j], al[mt], bh[j]);   // lo*hi
                }
        }
        __syncthreads();
        if (kt + 2 < KT) load_stage(kt + 2, buf);
        asm volatile("cp.async.commit_group;" ::: "memory");
    }

    // ---- epilogue: acc -> global with alpha/bias/add/relu, fp32 or bf16-pair ----
    #pragma unroll
    for (int mt = 0; mt < 2; mt++){
        #pragma unroll
        for (int j = 0; j < NT; j++){
            const int col = n0 + warpN + j*8 + (lane & 3) * 2;
            const float b0 = bias ? bias[col]   : 0.0f;
            const float b1 = bias ? bias[col+1] : 0.0f;
            #pragma unroll
            for (int half = 0; half < 2; half++){
                const long row = m0 + warpM + mt*16 + (lane >> 2) + half*8;
                float v0 = acc[mt][j][half*2+0] * alpha + b0;
                float v1 = acc[mt][j][half*2+1] * alpha + b1;
                if (add){
                    v0 += add[row * ldadd + col];
                    v1 += add[row * ldadd + col + 1];
                }
                if (doRelu){ v0 = fmaxf(v0, 0.0f); v1 = fmaxf(v1, 0.0f); }
                const long ci = cOff + row * ldc + col;
                if (Ch){
                    __nv_bfloat16 h0,l0,h1,l1;
                    split2(v0,h0,l0); split2(v1,h1,l1);
                    *(uint32_t*)(Ch + ci) = (uint32_t)__bfloat16_as_ushort(h0) |
                                            ((uint32_t)__bfloat16_as_ushort(h1) << 16);
                    *(uint32_t*)(Cl + ci) = (uint32_t)__bfloat16_as_ushort(l0) |
                                            ((uint32_t)__bfloat16_as_ushort(l1) << 16);
                } else {
                    *(float2*)(Cf + ci) = make_float2(v0, v1);
                }
            }
        }
    }
}

// ---------------- fp32 -> bf16 hi/lo split (vectorized x4) ----------------
__global__ void cvt_split_kernel(const float4* __restrict__ in,
                                 uint2* __restrict__ hi, uint2* __restrict__ lo, long n4)
{
    long i = (long)blockIdx.x * 256 + threadIdx.x;
    if (i >= n4) return;
    float4 v = in[i];
    __nv_bfloat16 h0,h1,h2,h3,l0,l1,l2,l3;
    split2(v.x,h0,l0); split2(v.y,h1,l1); split2(v.z,h2,l2); split2(v.w,h3,l3);
    uint2 H, L;
    H.x = (uint32_t)__bfloat16_as_ushort(h0) | ((uint32_t)__bfloat16_as_ushort(h1) << 16);
    H.y = (uint32_t)__bfloat16_as_ushort(h2) | ((uint32_t)__bfloat16_as_ushort(h3) << 16);
    L.x = (uint32_t)__bfloat16_as_ushort(l0) | ((uint32_t)__bfloat16_as_ushort(l1) << 16);
    L.y = (uint32_t)__bfloat16_as_ushort(l2) | ((uint32_t)__bfloat16_as_ushort(l3) << 16);
    hi[i] = H; lo[i] = L;
}

// ---------------- V transpose + split ----------------
__global__ void transpose_split_v(const float* __restrict__ v,
                                  __nv_bfloat16* __restrict__ vth,
                                  __nv_bfloat16* __restrict__ vtl)
{
    __shared__ float t[64][65];
    const int z  = blockIdx.y;
    const int t0 = blockIdx.x * 64;
    const int b  = z >> 4, h = z & 15;
    const float* src = v + (size_t)b*1024 + (size_t)h*64;
    for (int it = 0; it < 16; it++){
        int idx = it*256 + threadIdx.x;
        int ti = idx >> 6, kk = idx & 63;
        t[ti][kk] = src[(size_t)(t0 + ti)*4096 + kk];
    }
    __syncthreads();
    size_t obase = (size_t)z * Kh * Ss + t0;
    for (int it = 0; it < 16; it++){
        int idx = it*256 + threadIdx.x;
        int kk = idx >> 6, ti = idx & 63;
        float x = t[ti][kk];
        __nv_bfloat16 h2, l2; split2(x, h2, l2);
        vth[obase + (size_t)kk*Ss + ti] = h2;
        vtl[obase + (size_t)kk*Ss + ti] = l2;
    }
}

// ---------------- softmax (additive mask) -> bf16 hi/lo ----------------
__global__ void softmax_split_kernel(const float* __restrict__ scores,
                                     const float* __restrict__ mask,
                                     __nv_bfloat16* __restrict__ oh,
                                     __nv_bfloat16* __restrict__ ol)
{
    const int s  = blockIdx.x;
    const int bh = blockIdx.y;
    const size_t rbase = ((size_t)bh * Ss + s) * Ss;
    const float* row  = scores + rbase;
    const float* mrow = mask + (size_t)s * Ss;
    const int tid = threadIdx.x;

    float vals[8];
    float mx = -INFINITY;
    #pragma unroll
    for (int i = 0; i < 8; i++){
        int t = tid + i*256;
        vals[i] = row[t] + mrow[t];
        mx = fmaxf(mx, vals[i]);
    }
    __shared__ float red[256];
    red[tid] = mx; __syncthreads();
    for (int off = 128; off > 0; off >>= 1){
        if (tid < off) red[tid] = fmaxf(red[tid], red[tid+off]);
        __syncthreads();
    }
    mx = red[0];
    __syncthreads();
    float sum = 0.0f;
    #pragma unroll
    for (int i = 0; i < 8; i++){ vals[i] = __expf(vals[i] - mx); sum += vals[i]; }
    red[tid] = sum; __syncthreads();
    for (int off = 128; off > 0; off >>= 1){
        if (tid < off) red[tid] += red[tid+off];
        __syncthreads();
    }
    float inv = 1.0f / red[0];
    #pragma unroll
    for (int i = 0; i < 8; i++){
        float p = vals[i] * inv;
        __nv_bfloat16 h, l; split2(p, h, l);
        size_t idx = rbase + tid + i*256;
        oh[idx] = h; ol[idx] = l;
    }
}

// ---------------- layernorm over D=1024; optional bf16 split output ----------------
__global__ void layernorm_kernel(const float* __restrict__ in,
                                 float* __restrict__ out,
                                 __nv_bfloat16* __restrict__ oh,
                                 __nv_bfloat16* __restrict__ ol,
                                 const float* __restrict__ gamma,
                                 const float* __restrict__ beta)
{
    const int row = blockIdx.x;
    const float* x = in + (size_t)row * Dd;
    const int tid = threadIdx.x;

    float v[4];
    float s = 0.0f, s2 = 0.0f;
    #pragma unroll
    for (int i = 0; i < 4; i++){
        v[i] = x[tid + i*256];
        s  += v[i];
        s2 += v[i]*v[i];
    }
    __shared__ float r1[256], r2[256];
    r1[tid] = s; r2[tid] = s2; __syncthreads();
    for (int off = 128; off > 0; off >>= 1){
        if (tid < off){ r1[tid] += r1[tid+off]; r2[tid] += r2[tid+off]; }
        __syncthreads();
    }
    float mean = r1[0] * (1.0f/Dd);
    float var  = r2[0] * (1.0f/Dd) - mean*mean;
    float inv  = rsqrtf(var + EPSL);
    #pragma unroll
    for (int i = 0; i < 4; i++){
        int c = tid + i*256;
        float y = (v[i] - mean) * inv * gamma[c] + beta[c];
        out[(size_t)row*Dd + c] = y;
        if (oh){
            __nv_bfloat16 h, l; split2(y, h, l);
            oh[(size_t)row*Dd + c] = h;
            ol[(size_t)row*Dd + c] = l;
        }
    }
}

// ---------------- host side ----------------
static const int SMEM128 = 2 * (2*10240 + 2*128*40*2);  // 81920
static const int SMEM64  = 2 * (2*10240 + 2*64*40*2);   // 61440

static inline void cvt(const float* in, __nv_bfloat16* h, __nv_bfloat16* l, long n){
    long n4 = n / 4;
    cvt_split_kernel<<<(unsigned)(n4 / 256), 256>>>((const float4*)in, (uint2*)h, (uint2*)l, n4);
}

struct GemmArgs {
    const __nv_bfloat16 *Ah, *Al, *Bh, *Bl;
    float* Cf; __nv_bfloat16 *Ch, *Cl;
    int M, N, Kd; long lda, ldb, ldc, sA, sB, sC; int batch;
    float alpha; const float* add; long ldadd; const float* bias; int relu;
};

template<int BN>
static inline void run_gemm(const GemmArgs& a){
    dim3 grid(a.N / BN, a.M / 128, a.batch);
    int smem = (BN == 128) ? SMEM128 : SMEM64;
    mma_gemm<BN><<<grid, 256, smem>>>(a.Ah, a.Al, a.Bh, a.Bl, a.Cf, a.Ch, a.Cl,
                                      a.Kd, a.lda, a.ldb, a.ldc, a.sA, a.sB, a.sC,
                                      a.alpha, a.add, a.ldadd, a.bias, a.relu);
}

extern "C" void kernel_launch(void* const* d_in, const int* in_sizes, int n_in,
                              void* d_out, int out_size)
{
    const float* x     = (const float*)d_in[0];
    const float* mask  = (const float*)d_in[1];
    const float* wq    = (const float*)d_in[2];
    const float* wk    = (const float*)d_in[3];
    const float* wv    = (const float*)d_in[4];
    const float* wc    = (const float*)d_in[5];
    const float* w1_w  = (const float*)d_in[6];
    const float* w1_b  = (const float*)d_in[7];
    const float* w2_w  = (const float*)d_in[8];
    const float* w2_b  = (const float*)d_in[9];
    const float* ln1_g = (const float*)d_in[10];
    const float* ln1_b = (const float*)d_in[11];
    const float* ln2_g = (const float*)d_in[12];
    const float* ln2_b = (const float*)d_in[13];
    float* out = (float*)d_out;

    cudaFuncSetAttribute((const void*)mma_gemm<128>, cudaFuncAttributeMaxDynamicSharedMemorySize, SMEM128);
    cudaFuncSetAttribute((const void*)mma_gemm<64>,  cudaFuncAttributeMaxDynamicSharedMemorySize, SMEM64);

    __nv_bfloat16 *xh,*xl,*wqh,*wql,*wkh,*wkl,*wvh,*wvl,*wch,*wcl,*w1h,*w1l,*w2h,*w2l;
    __nv_bfloat16 *qh,*ql,*kh,*kl,*vth,*vtl,*sch,*scl,*avh,*avl,*uh,*ul,*h1h,*h1l;
    float *v,*sc,*attn,*u,*z;
    cudaGetSymbolAddress((void**)&xh,  g_x_h);  cudaGetSymbolAddress((void**)&xl,  g_x_l);
    cudaGetSymbolAddress((void**)&wqh, g_wq_h); cudaGetSymbolAddress((void**)&wql, g_wq_l);
    cudaGetSymbolAddress((void**)&wkh, g_wk_h); cudaGetSymbolAddress((void**)&wkl, g_wk_l);
    cudaGetSymbolAddress((void**)&wvh, g_wv_h); cudaGetSymbolAddress((void**)&wvl, g_wv_l);
    cudaGetSymbolAddress((void**)&wch, g_wc_h); cudaGetSymbolAddress((void**)&wcl, g_wc_l);
    cudaGetSymbolAddress((void**)&w1h, g_w1_h); cudaGetSymbolAddress((void**)&w1l, g_w1_l);
    cudaGetSymbolAddress((void**)&w2h, g_w2_h); cudaGetSymbolAddress((void**)&w2l, g_w2_l);
    cudaGetSymbolAddress((void**)&qh,  g_q_h);  cudaGetSymbolAddress((void**)&ql,  g_q_l);
    cudaGetSymbolAddress((void**)&kh,  g_k_h);  cudaGetSymbolAddress((void**)&kl,  g_k_l);
    cudaGetSymbolAddress((void**)&v,   g_v);
    cudaGetSymbolAddress((void**)&vth, g_vt_h); cudaGetSymbolAddress((void**)&vtl, g_vt_l);
    cudaGetSymbolAddress((void**)&sc,  g_sc);
    cudaGetSymbolAddress((void**)&sch, g_sch);  cudaGetSymbolAddress((void**)&scl, g_scl);
    cudaGetSymbolAddress((void**)&avh, g_av_h); cudaGetSymbolAddress((void**)&avl, g_av_l);
    cudaGetSymbolAddress((void**)&attn,g_attn);
    cudaGetSymbolAddress((void**)&u,   g_u);
    cudaGetSymbolAddress((void**)&uh,  g_u_h);  cudaGetSymbolAddress((void**)&ul,  g_u_l);
    cudaGetSymbolAddress((void**)&h1h, g_h1_h); cudaGetSymbolAddress((void**)&h1l, g_h1_l);
    cudaGetSymbolAddress((void**)&z,   g_z);

    // input conversions
    cvt(x,   xh,  xl,  (long)NTOK*Dd);
    cvt(wq,  wqh, wql, (long)Dd*Dd);
    cvt(wk,  wkh, wkl, (long)Dd*Dd);
    cvt(wv,  wvh, wvl, (long)Dd*Dd);
    cvt(wc,  wch, wcl, (long)Dd*Dd);
    cvt(w1_w,w1h, w1l, (long)Mf*Dd);
    cvt(w2_w,w2h, w2l, (long)Mf*Dd);

    GemmArgs a;
    // Q = x @ wq^T  (bf16-pair output)
    a = {xh,xl,wqh,wql, nullptr,qh,ql, NTOK,Dd,Dd, Dd,Dd,Dd, 0,0,0,1, 1.0f, nullptr,0, nullptr,0};
    run_gemm<128>(a);
    // K
    a = {xh,xl,wkh,wkl, nullptr,kh,kl, NTOK,Dd,Dd, Dd,Dd,Dd, 0,0,0,1, 1.0f, nullptr,0, nullptr,0};
    run_gemm<128>(a);
    // V (fp32, then transpose+split)
    a = {xh,xl,wvh,wvl, v,nullptr,nullptr, NTOK,Dd,Dd, Dd,Dd,Dd, 0,0,0,1, 1.0f, nullptr,0, nullptr,0};
    run_gemm<128>(a);
    {
        dim3 g(Ss/64, BH);
        transpose_split_v<<<g, 256>>>(v, vth, vtl);
    }
    // scores[z][s][t] = 0.125 * Q_z @ K_z^T  (fp32)
    a = {qh,ql,kh,kl, sc,nullptr,nullptr, Ss,Ss,Kh,
         (long)Bb*Hh*Kh,(long)Bb*Hh*Kh,Ss, Kh,Kh,(long)Ss*Ss, BH,
         0.125f, nullptr,0, nullptr,0};
    run_gemm<128>(a);
    // softmax + mask -> bf16 pair
    {
        dim3 g(Ss, BH);
        softmax_split_kernel<<<g, 256>>>(sc, mask, sch, scl);
    }
    // av[z][s][kk] = alpha_z @ vt_z^T  (bf16-pair output, N=64)
    a = {sch,scl,vth,vtl, nullptr,avh,avl, Ss,Kh,Ss,
         Ss,Ss,(long)Bb*Hh*Kh, (long)Ss*Ss,(long)Kh*Ss,Kh, BH,
         1.0f, nullptr,0, nullptr,0};
    run_gemm<64>(a);
    // attn = av @ wc^T + x  (fp32)
    a = {avh,avl,wch,wcl, attn,nullptr,nullptr, NTOK,Dd,Dd, Dd,Dd,Dd, 0,0,0,1,
         1.0f, x,Dd, nullptr,0};
    run_gemm<128>(a);
    // u = LN1(attn)  (fp32 + pair)
    layernorm_kernel<<<NTOK, 256>>>(attn, u, uh, ul, ln1_g, ln1_b);
    // h1 = relu(u @ w1^T + b1)  (bf16-pair output)
    a = {uh,ul,w1h,w1l, nullptr,h1h,h1l, NTOK,Mf,Dd, Dd,Dd,Mf, 0,0,0,1,
         1.0f, nullptr,0, w1_b,1};
    run_gemm<128>(a);
    // z = h1 @ w2^T + b2 + u  (fp32)
    a = {h1h,h1l,w2h,w2l, z,nullptr,nullptr, NTOK,Dd,Mf, Mf,Mf,Dd, 0,0,0,1,
         1.0f, u,Dd, w2_b,0};
    run_gemm<128>(a);
    // out = LN2(z)
    layernorm_kernel<<<NTOK, 256>>>(z, out, nullptr, nullptr, ln2_g, ln2_b);
}

// round 4
// speedup vs baseline: 4.0220x; 1.2001x over previous
#include <cuda_runtime.h>
#include <cuda_bf16.h>
#include <cstdint>
#include <math.h>

#define Hh   16
#define Kh   64
#define Dd   1024
#define Mf   4096
#define Ss   2048
#define Bb   4
#define NTOK (Ss*Bb)      // 8192
#define BH   (Bb*Hh)      // 64
#define EPSL 1e-5f

// ---------------- scratch buffers (device globals: allocation-free) ----------------
__device__ __nv_bfloat16 g_x_h[(size_t)NTOK*Dd],  g_x_l[(size_t)NTOK*Dd];
__device__ __nv_bfloat16 g_wq_h[(size_t)Dd*Dd],   g_wq_l[(size_t)Dd*Dd];
__device__ __nv_bfloat16 g_wk_h[(size_t)Dd*Dd],   g_wk_l[(size_t)Dd*Dd];
__device__ __nv_bfloat16 g_wv_h[(size_t)Dd*Dd],   g_wv_l[(size_t)Dd*Dd];
__device__ __nv_bfloat16 g_wc_h[(size_t)Dd*Dd],   g_wc_l[(size_t)Dd*Dd];
__device__ __nv_bfloat16 g_w1_h[(size_t)Mf*Dd],   g_w1_l[(size_t)Mf*Dd];
__device__ __nv_bfloat16 g_w2_h[(size_t)Mf*Dd],   g_w2_l[(size_t)Mf*Dd];
__device__ __nv_bfloat16 g_q_h[(size_t)NTOK*Dd],  g_q_l[(size_t)NTOK*Dd];
__device__ __nv_bfloat16 g_k_h[(size_t)NTOK*Dd],  g_k_l[(size_t)NTOK*Dd];
__device__ float         g_v[(size_t)NTOK*Dd];
__device__ __nv_bfloat16 g_vt_h[(size_t)BH*Kh*Ss], g_vt_l[(size_t)BH*Kh*Ss];
__device__ __nv_bfloat16 g_av_h[(size_t)NTOK*Dd], g_av_l[(size_t)NTOK*Dd];
__device__ float         g_attn[(size_t)NTOK*Dd];
__device__ float         g_u[(size_t)NTOK*Dd];
__device__ __nv_bfloat16 g_u_h[(size_t)NTOK*Dd],  g_u_l[(size_t)NTOK*Dd];
__device__ __nv_bfloat16 g_h1_h[(size_t)NTOK*Mf], g_h1_l[(size_t)NTOK*Mf];
__device__ float         g_z[(size_t)NTOK*Dd];

// ---------------- helpers ----------------
__device__ __forceinline__ uint32_t smem_u32(const void* p){
    uint32_t a;
    asm("{ .reg .u64 t; cvta.to.shared.u64 t, %1; cvt.u32.u64 %0, t; }" : "=r"(a) : "l"(p));
    return a;
}
__device__ __forceinline__ void split2(float x, __nv_bfloat16& h, __nv_bfloat16& l){
    h = __float2bfloat16(x);
    l = __float2bfloat16(x - __bfloat162float(h));
}
__device__ __forceinline__ void cpasync16(uint32_t saddr, const void* gaddr){
    asm volatile("cp.async.cg.shared.global [%0], [%1], 16;" :: "r"(saddr), "l"(gaddr) : "memory");
}
__device__ __forceinline__ void ldmx4(uint32_t* r, uint32_t addr){
    asm volatile("ldmatrix.sync.aligned.m8n8.x4.shared.b16 {%0,%1,%2,%3}, [%4];"
                 : "=r"(r[0]), "=r"(r[1]), "=r"(r[2]), "=r"(r[3]) : "r"(addr));
}
__device__ __forceinline__ void mma16816(float* c, const uint32_t* a, const uint32_t* b){
    asm volatile("mma.sync.aligned.m16n8k16.row.col.f32.bf16.bf16.f32 "
                 "{%0,%1,%2,%3}, {%4,%5,%6,%7}, {%8,%9}, {%0,%1,%2,%3};"
                 : "+f"(c[0]), "+f"(c[1]), "+f"(c[2]), "+f"(c[3])
                 : "r"(a[0]), "r"(a[1]), "r"(a[2]), "r"(a[3]), "r"(b[0]), "r"(b[1]));
}
__device__ __forceinline__ uint32_t pack_bf2(__nv_bfloat16 a, __nv_bfloat16 b){
    return (uint32_t)__bfloat16_as_ushort(a) | ((uint32_t)__bfloat16_as_ushort(b) << 16);
}

// ---------------- mma.sync bf16x3 NT GEMM (unchanged from R3) ----------------
template<int BN>
__global__ void __launch_bounds__(256) mma_gemm(
    const __nv_bfloat16* __restrict__ Ah, const __nv_bfloat16* __restrict__ Al,
    const __nv_bfloat16* __restrict__ Bh, const __nv_bfloat16* __restrict__ Bl,
    float* __restrict__ Cf, __nv_bfloat16* __restrict__ Ch, __nv_bfloat16* __restrict__ Cl,
    int Kd, long lda, long ldb, long ldc,
    long sA, long sB, long sC,
    float alpha, const float* __restrict__ add, long ldadd,
    const float* __restrict__ bias, int doRelu)
{
    constexpr int BK   = 32;
    constexpr int LDS  = BK + 8;
    constexpr int WN   = BN / 2;
    constexpr int NT   = WN / 8;
    constexpr int A_BYTES = 128 * LDS * 2;
    constexpr int B_BYTES = BN  * LDS * 2;
    constexpr int STAGE   = 2 * A_BYTES + 2 * B_BYTES;

    extern __shared__ char smc[];
    const uint32_t sbase = smem_u32(smc);

    const int tid  = threadIdx.x;
    const int lane = tid & 31;
    const int wid  = tid >> 5;
    const int warpM = (wid & 3) * 32;
    const int warpN = (wid >> 2) * WN;

    const long aOff = (long)blockIdx.z * sA;
    const long bOff = (long)blockIdx.z * sB;
    const long cOff = (long)blockIdx.z * sC;
    const int  m0   = blockIdx.y * 128;
    const int  n0   = blockIdx.x * BN;
    const int  KT   = Kd / BK;

    const int la_row = tid >> 2, la_ch = tid & 3;
    auto load_stage = [&](int kt, int buf){
        const int k0 = kt * BK;
        const uint32_t s0 = sbase + buf * STAGE;
        #pragma unroll
        for (int it = 0; it < 2; it++){
            int row = la_row + it * 64;
            long g = aOff + (long)(m0 + row) * lda + k0 + la_ch * 8;
            uint32_t so = (uint32_t)(row * (LDS * 2) + la_ch * 16);
            cpasync16(s0 + so,           Ah + g);
            cpasync16(s0 + A_BYTES + so, Al + g);
        }
        #pragma unroll
        for (int it = 0; it < BN / 64; it++){
            int row = la_row + it * 64;
            long g = bOff + (long)(n0 + row) * ldb + k0 + la_ch * 8;
            uint32_t so = (uint32_t)(row * (LDS * 2) + la_ch * 16);
            cpasync16(s0 + 2*A_BYTES + so,           Bh + g);
            cpasync16(s0 + 2*A_BYTES + B_BYTES + so, Bl + g);
        }
    };

    load_stage(0, 0);
    asm volatile("cp.async.commit_group;" ::: "memory");
    load_stage(1, 1);
    asm volatile("cp.async.commit_group;" ::: "memory");

    float acc[2][NT][4];
    #pragma unroll
    for (int i = 0; i < 2; i++)
        #pragma unroll
        for (int j = 0; j < NT; j++)
            #pragma unroll
            for (int e = 0; e < 4; e++) acc[i][j][e] = 0.0f;

    const int aRow = (lane & 15), aColHalf = (lane >> 4) * 8;
    const int bRow = (lane >> 4) * 8 + (lane & 7), bColHalf = ((lane >> 3) & 1) * 8;

    for (int kt = 0; kt < KT; kt++){
        asm volatile("cp.async.wait_group 1;" ::: "memory");
        __syncthreads();
        const int buf = kt & 1;
        const uint32_t sA0 = sbase + buf * STAGE;
        const uint32_t sB0 = sA0 + 2 * A_BYTES;

        #pragma unroll
        for (int ks = 0; ks < 2; ks++){
            const int k16 = ks * 16;
            uint32_t ah[2][4], al[2][4];
            #pragma unroll
            for (int mt = 0; mt < 2; mt++){
                uint32_t addr = sA0 + (uint32_t)(((warpM + mt*16 + aRow) * LDS + k16 + aColHalf) * 2);
                ldmx4(ah[mt], addr);
                ldmx4(al[mt], addr + A_BYTES);
            }
            uint32_t bh[NT][2], bl[NT][2];
            #pragma unroll
            for (int g = 0; g < NT/2; g++){
                uint32_t addr = sB0 + (uint32_t)(((warpN + g*16 + bRow) * LDS + k16 + bColHalf) * 2);
                uint32_t r[4];
                ldmx4(r, addr);
                bh[2*g][0] = r[0]; bh[2*g][1] = r[1];
                bh[2*g+1][0] = r[2]; bh[2*g+1][1] = r[3];
                ldmx4(r, addr + B_BYTES);
                bl[2*g][0] = r[0]; bl[2*g][1] = r[1];
                bl[2*g+1][0] = r[2]; bl[2*g+1][1] = r[3];
            }
            #pragma unroll
            for (int mt = 0; mt < 2; mt++)
                #pragma unroll
                for (int j = 0; j < NT; j++){
                    mma16816(acc[mt][j], ah[mt], bh[j]);
                    mma16816(acc[mt][j], ah[mt], bl[j]);
                    mma16816(acc[mt][j], al[mt], bh[j]);
                }
        }
        __syncthreads();
        if (kt + 2 < KT) load_stage(kt + 2, buf);
        asm volatile("cp.async.commit_group;" ::: "memory");
    }

    #pragma unroll
    for (int mt = 0; mt < 2; mt++){
        #pragma unroll
        for (int j = 0; j < NT; j++){
            const int col = n0 + warpN + j*8 + (lane & 3) * 2;
            const float b0 = bias ? bias[col]   : 0.0f;
            const float b1 = bias ? bias[col+1] : 0.0f;
            #pragma unroll
            for (int half = 0; half < 2; half++){
                const long row = m0 + warpM + mt*16 + (lane >> 2) + half*8;
                float v0 = acc[mt][j][half*2+0] * alpha + b0;
                float v1 = acc[mt][j][half*2+1] * alpha + b1;
                if (add){
                    v0 += add[row * ldadd + col];
                    v1 += add[row * ldadd + col + 1];
                }
                if (doRelu){ v0 = fmaxf(v0, 0.0f); v1 = fmaxf(v1, 0.0f); }
                const long ci = cOff + row * ldc + col;
                if (Ch){
                    __nv_bfloat16 h0,l0,h1,l1;
                    split2(v0,h0,l0); split2(v1,h1,l1);
                    *(uint32_t*)(Ch + ci) = pack_bf2(h0, h1);
                    *(uint32_t*)(Cl + ci) = pack_bf2(l0, l1);
                } else {
                    *(float2*)(Cf + ci) = make_float2(v0, v1);
                }
            }
        }
    }
}

// ---------------- fused flash attention ----------------
// grid (Ss/128, BH); 256 threads = 8 warps, each warp owns 16 q-rows.
// Q/K: token rows (s*B+b) stride 4096 halves, head offset z*64. Vt: [z][kk][t].
#define FL_LQ 72
#define FL_LV 136
#define FL_QCOMP (128*FL_LQ*2)
#define FL_KCOMP (128*FL_LQ*2)
#define FL_VCOMP (64*FL_LV*2)
#define FL_STAGE (2*FL_KCOMP + 2*FL_VCOMP)
#define FL_SMQ   0
#define FL_SMST  (2*FL_QCOMP)
#define FL_SMEM  (FL_SMST + 2*FL_STAGE)     // 180224

__global__ void __launch_bounds__(256,1) flash_kernel(
    const __nv_bfloat16* __restrict__ Qh, const __nv_bfloat16* __restrict__ Ql,
    const __nv_bfloat16* __restrict__ Kh2, const __nv_bfloat16* __restrict__ Kl2,
    const __nv_bfloat16* __restrict__ Vth, const __nv_bfloat16* __restrict__ Vtl,
    const float* __restrict__ mask,
    __nv_bfloat16* __restrict__ AVh, __nv_bfloat16* __restrict__ AVl)
{
    extern __shared__ char smc[];
    const uint32_t sbase = smem_u32(smc);
    const int tid = threadIdx.x, lane = tid & 31, wid = tid >> 5;
    const int q0 = blockIdx.x * 128;
    const int z  = blockIdx.y;
    const long hOff = (long)z * 64;

    auto load_q = [&](){
        #pragma unroll
        for (int it = 0; it < 4; it++){
            int idx = it*256 + tid;
            int row = idx >> 3, ch = idx & 7;
            long g = (long)(q0 + row) * 4096 + hOff + ch*8;
            uint32_t so = sbase + FL_SMQ + (uint32_t)(row*FL_LQ*2 + ch*16);
            cpasync16(so,            Qh + g);
            cpasync16(so + FL_QCOMP, Ql + g);
        }
    };
    auto load_stage = [&](int kt, int buf){
        const int t0 = kt * 128;
        const uint32_t s0 = sbase + FL_SMST + buf*FL_STAGE;
        #pragma unroll
        for (int it = 0; it < 4; it++){
            int idx = it*256 + tid;
            int row = idx >> 3, ch = idx & 7;
            long g = (long)(t0 + row) * 4096 + hOff + ch*8;
            uint32_t so = s0 + (uint32_t)(row*FL_LQ*2 + ch*16);
            cpasync16(so,            Kh2 + g);
            cpasync16(so + FL_KCOMP, Kl2 + g);
        }
        const uint32_t v0 = s0 + 2*FL_KCOMP;
        #pragma unroll
        for (int it = 0; it < 4; it++){
            int idx = it*256 + tid;
            int row = idx >> 4, ch = idx & 15;
            long g = (long)z*64*2048 + (long)row*2048 + t0 + ch*8;
            uint32_t so = v0 + (uint32_t)(row*FL_LV*2 + ch*16);
            cpasync16(so,            Vth + g);
            cpasync16(so + FL_VCOMP, Vtl + g);
        }
    };

    load_q();
    load_stage(0, 0);
    asm volatile("cp.async.commit_group;" ::: "memory");
    load_stage(1, 1);
    asm volatile("cp.async.commit_group;" ::: "memory");
    asm volatile("cp.async.wait_group 1;" ::: "memory");
    __syncthreads();

    const int aRow = lane & 15, aCol = (lane >> 4) * 8;
    const int bRow = (lane >> 4) * 8 + (lane & 7), bCol = ((lane >> 3) & 1) * 8;

    uint32_t qfh[4][4], qfl[4][4];
    #pragma unroll
    for (int kc = 0; kc < 4; kc++){
        uint32_t addr = sbase + FL_SMQ + (uint32_t)(((wid*16 + aRow)*FL_LQ + kc*16 + aCol) * 2);
        ldmx4(qfh[kc], addr);
        ldmx4(qfl[kc], addr + FL_QCOMP);
    }

    float O[8][4];
    #pragma unroll
    for (int j = 0; j < 8; j++){ O[j][0]=0; O[j][1]=0; O[j][2]=0; O[j][3]=0; }
    float m0 = -INFINITY, m1 = -INFINITY, l0 = 0.0f, l1 = 0.0f;
    const int rloc = wid*16 + (lane >> 2);

    for (int kt = 0; kt < 16; kt++){
        asm volatile("cp.async.wait_group 1;" ::: "memory");
        __syncthreads();
        const uint32_t sK = sbase + FL_SMST + (kt & 1)*FL_STAGE;
        const uint32_t sV = sK + 2*FL_KCOMP;

        float S[16][4];
        #pragma unroll
        for (int j = 0; j < 16; j++){ S[j][0]=0; S[j][1]=0; S[j][2]=0; S[j][3]=0; }

        #pragma unroll
        for (int kc = 0; kc < 4; kc++){
            #pragma unroll
            for (int g = 0; g < 8; g++){
                uint32_t addr = sK + (uint32_t)(((g*16 + bRow)*FL_LQ + kc*16 + bCol) * 2);
                uint32_t bh2[4], bl2[4];
                ldmx4(bh2, addr);
                ldmx4(bl2, addr + FL_KCOMP);
                mma16816(S[2*g],   qfh[kc], bh2+0);
                mma16816(S[2*g],   qfh[kc], bl2+0);
                mma16816(S[2*g],   qfl[kc], bh2+0);
                mma16816(S[2*g+1], qfh[kc], bh2+2);
                mma16816(S[2*g+1], qfh[kc], bl2+2);
                mma16816(S[2*g+1], qfl[kc], bh2+2);
            }
        }

        // scale + mask + running max
        const int t0 = kt * 128;
        const long mr0 = (long)(q0 + rloc) * 2048 + t0;
        const long mr1 = mr0 + 8 * 2048;
        float mx0 = -INFINITY, mx1 = -INFINITY;
        #pragma unroll
        for (int j = 0; j < 16; j++){
            int c = j*8 + (lane & 3)*2;
            float2 k0v = *(const float2*)(mask + mr0 + c);
            float2 k1v = *(const float2*)(mask + mr1 + c);
            S[j][0] = S[j][0]*0.125f + k0v.x;
            S[j][1] = S[j][1]*0.125f + k0v.y;
            S[j][2] = S[j][2]*0.125f + k1v.x;
            S[j][3] = S[j][3]*0.125f + k1v.y;
            mx0 = fmaxf(mx0, fmaxf(S[j][0], S[j][1]));
            mx1 = fmaxf(mx1, fmaxf(S[j][2], S[j][3]));
        }
        mx0 = fmaxf(mx0, __shfl_xor_sync(0xFFFFFFFFu, mx0, 1));
        mx0 = fmaxf(mx0, __shfl_xor_sync(0xFFFFFFFFu, mx0, 2));
        mx1 = fmaxf(mx1, __shfl_xor_sync(0xFFFFFFFFu, mx1, 1));
        mx1 = fmaxf(mx1, __shfl_xor_sync(0xFFFFFFFFu, mx1, 2));
        float nm0 = fmaxf(m0, mx0), nm1 = fmaxf(m1, mx1);
        float f0 = (m0 > -INFINITY) ? __expf(m0 - nm0) : 0.0f;
        float f1 = (m1 > -INFINITY) ? __expf(m1 - nm1) : 0.0f;
        m0 = nm0; m1 = nm1;

        float s0 = 0.0f, s1 = 0.0f;
        #pragma unroll
        for (int j = 0; j < 16; j++){
            S[j][0] = __expf(S[j][0] - m0);
            S[j][1] = __expf(S[j][1] - m0);
            S[j][2] = __expf(S[j][2] - m1);
            S[j][3] = __expf(S[j][3] - m1);
            s0 += S[j][0] + S[j][1];
            s1 += S[j][2] + S[j][3];
        }
        s0 += __shfl_xor_sync(0xFFFFFFFFu, s0, 1);
        s0 += __shfl_xor_sync(0xFFFFFFFFu, s0, 2);
        s1 += __shfl_xor_sync(0xFFFFFFFFu, s1, 1);
        s1 += __shfl_xor_sync(0xFFFFFFFFu, s1, 2);
        l0 = l0*f0 + s0;
        l1 = l1*f1 + s1;
        #pragma unroll
        for (int j = 0; j < 8; j++){
            O[j][0]*=f0; O[j][1]*=f0; O[j][2]*=f1; O[j][3]*=f1;
        }

        // O += P @ Vt  (P hi/lo, V hi; plus P hi * V lo)
        #pragma unroll
        for (int kc = 0; kc < 8; kc++){
            uint32_t ph[4], pl[4];
            {
                __nv_bfloat16 h0,l0_,h1,l1_;
                split2(S[2*kc][0],h0,l0_);   split2(S[2*kc][1],h1,l1_);
                ph[0]=pack_bf2(h0,h1); pl[0]=pack_bf2(l0_,l1_);
                split2(S[2*kc][2],h0,l0_);   split2(S[2*kc][3],h1,l1_);
                ph[1]=pack_bf2(h0,h1); pl[1]=pack_bf2(l0_,l1_);
                split2(S[2*kc+1][0],h0,l0_); split2(S[2*kc+1][1],h1,l1_);
                ph[2]=pack_bf2(h0,h1); pl[2]=pack_bf2(l0_,l1_);
                split2(S[2*kc+1][2],h0,l0_); split2(S[2*kc+1][3],h1,l1_);
                ph[3]=pack_bf2(h0,h1); pl[3]=pack_bf2(l0_,l1_);
            }
            #pragma unroll
            for (int g = 0; g < 4; g++){
                uint32_t addr = sV + (uint32_t)(((g*16 + bRow)*FL_LV + kc*16 + bCol) * 2);
                uint32_t vh2[4], vl2[4];
                ldmx4(vh2, addr);
                ldmx4(vl2, addr + FL_VCOMP);
                mma16816(O[2*g],   ph, vh2+0);
                mma16816(O[2*g],   pl, vh2+0);
                mma16816(O[2*g],   ph, vl2+0);
                mma16816(O[2*g+1], ph, vh2+2);
                mma16816(O[2*g+1], pl, vh2+2);
                mma16816(O[2*g+1], ph, vl2+2);
            }
        }

        __syncthreads();
        if (kt + 2 < 16) load_stage(kt + 2, kt & 1);
        asm volatile("cp.async.commit_group;" ::: "memory");
    }

    // finalize: O /= l, write av (bf16 pair) at token rows (s*B+b)
    const float inv0 = 1.0f / l0, inv1 = 1.0f / l1;
    #pragma unroll
    for (int j = 0; j < 8; j++){
        const int col = j*8 + (lane & 3)*2;
        const long a0 = (long)(q0 + rloc) * 4096 + hOff + col;
        const long a1 = a0 + 8L * 4096;
        __nv_bfloat16 h0,lo0,h1,lo1;
        split2(O[j][0]*inv0, h0, lo0);
        split2(O[j][1]*inv0, h1, lo1);
        *(uint32_t*)(AVh + a0) = pack_bf2(h0, h1);
        *(uint32_t*)(AVl + a0) = pack_bf2(lo0, lo1);
        split2(O[j][2]*inv1, h0, lo0);
        split2(O[j][3]*inv1, h1, lo1);
        *(uint32_t*)(AVh + a1) = pack_bf2(h0, h1);
        *(uint32_t*)(AVl + a1) = pack_bf2(lo0, lo1);
    }
}

// ---------------- fp32 -> bf16 hi/lo split ----------------
__global__ void cvt_split_kernel(const float4* __restrict__ in,
                                 uint2* __restrict__ hi, uint2* __restrict__ lo, long n4)
{
    long i = (long)blockIdx.x * 256 + threadIdx.x;
    if (i >= n4) return;
    float4 v = in[i];
    __nv_bfloat16 h0,h1,h2,h3,l0,l1,l2,l3;
    split2(v.x,h0,l0); split2(v.y,h1,l1); split2(v.z,h2,l2); split2(v.w,h3,l3);
    uint2 H, L;
    H.x = pack_bf2(h0,h1); H.y = pack_bf2(h2,h3);
    L.x = pack_bf2(l0,l1); L.y = pack_bf2(l2,l3);
    hi[i] = H; lo[i] = L;
}

// ---------------- V transpose + split ----------------
__global__ void transpose_split_v(const float* __restrict__ v,
                                  __nv_bfloat16* __restrict__ vth,
                                  __nv_bfloat16* __restrict__ vtl)
{
    __shared__ float t[64][65];
    const int z  = blockIdx.y;
    const int t0 = blockIdx.x * 64;
    const int b  = z >> 4, h = z & 15;
    const float* src = v + (size_t)b*1024 + (size_t)h*64;
    for (int it = 0; it < 16; it++){
        int idx = it*256 + threadIdx.x;
        int ti = idx >> 6, kk = idx & 63;
        t[ti][kk] = src[(size_t)(t0 + ti)*4096 + kk];
    }
    __syncthreads();
    size_t obase = (size_t)z * Kh * Ss + t0;
    for (int it = 0; it < 16; it++){
        int idx = it*256 + threadIdx.x;
        int kk = idx >> 6, ti = idx & 63;
        float x = t[ti][kk];
        __nv_bfloat16 h2, l2; split2(x, h2, l2);
        vth[obase + (size_t)kk*Ss + ti] = h2;
        vtl[obase + (size_t)kk*Ss + ti] = l2;
    }
}

// ---------------- layernorm over D=1024; optional bf16 split output ----------------
__global__ void layernorm_kernel(const float* __restrict__ in,
                                 float* __restrict__ out,
                                 __nv_bfloat16* __restrict__ oh,
                                 __nv_bfloat16* __restrict__ ol,
                                 const float* __restrict__ gamma,
                                 const float* __restrict__ beta)
{
    const int row = blockIdx.x;
    const float* x = in + (size_t)row * Dd;
    const int tid = threadIdx.x;

    float v[4];
    float s = 0.0f, s2 = 0.0f;
    #pragma unroll
    for (int i = 0; i < 4; i++){
        v[i] = x[tid + i*256];
        s  += v[i];
        s2 += v[i]*v[i];
    }
    __shared__ float r1[256], r2[256];
    r1[tid] = s; r2[tid] = s2; __syncthreads();
    for (int off = 128; off > 0; off >>= 1){
        if (tid < off){ r1[tid] += r1[tid+off]; r2[tid] += r2[tid+off]; }
        __syncthreads();
    }
    float mean = r1[0] * (1.0f/Dd);
    float var  = r2[0] * (1.0f/Dd) - mean*mean;
    float inv  = rsqrtf(var + EPSL);
    #pragma unroll
    for (int i = 0; i < 4; i++){
        int c = tid + i*256;
        float y = (v[i] - mean) * inv * gamma[c] + beta[c];
        out[(size_t)row*Dd + c] = y;
        if (oh){
            __nv_bfloat16 h, l; split2(y, h, l);
            oh[(size_t)row*Dd + c] = h;
            ol[(size_t)row*Dd + c] = l;
        }
    }
}

// ---------------- host side ----------------
static const int SMEM128 = 2 * (2*10240 + 2*128*40*2);  // 81920
static const int SMEM64  = 2 * (2*10240 + 2*64*40*2);   // 61440

static inline void cvt(const float* in, __nv_bfloat16* h, __nv_bfloat16* l, long n){
    long n4 = n / 4;
    cvt_split_kernel<<<(unsigned)(n4 / 256), 256>>>((const float4*)in, (uint2*)h, (uint2*)l, n4);
}

struct GemmArgs {
    const __nv_bfloat16 *Ah, *Al, *Bh, *Bl;
    float* Cf; __nv_bfloat16 *Ch, *Cl;
    int M, N, Kd; long lda, ldb, ldc, sA, sB, sC; int batch;
    float alpha; const float* add; long ldadd; const float* bias; int relu;
};

template<int BN>
static inline void run_gemm(const GemmArgs& a){
    dim3 grid(a.N / BN, a.M / 128, a.batch);
    int smem = (BN == 128) ? SMEM128 : SMEM64;
    mma_gemm<BN><<<grid, 256, smem>>>(a.Ah, a.Al, a.Bh, a.Bl, a.Cf, a.Ch, a.Cl,
                                      a.Kd, a.lda, a.ldb, a.ldc, a.sA, a.sB, a.sC,
                                      a.alpha, a.add, a.ldadd, a.bias, a.relu);
}

extern "C" void kernel_launch(void* const* d_in, const int* in_sizes, int n_in,
                              void* d_out, int out_size)
{
    const float* x     = (const float*)d_in[0];
    const float* mask  = (const float*)d_in[1];
    const float* wq    = (const float*)d_in[2];
    const float* wk    = (const float*)d_in[3];
    const float* wv    = (const float*)d_in[4];
    const float* wc    = (const float*)d_in[5];
    const float* w1_w  = (const float*)d_in[6];
    const float* w1_b  = (const float*)d_in[7];
    const float* w2_w  = (const float*)d_in[8];
    const float* w2_b  = (const float*)d_in[9];
    const float* ln1_g = (const float*)d_in[10];
    const float* ln1_b = (const float*)d_in[11];
    const float* ln2_g = (const float*)d_in[12];
    const float* ln2_b = (const float*)d_in[13];
    float* out = (float*)d_out;

    cudaFuncSetAttribute((const void*)mma_gemm<128>, cudaFuncAttributeMaxDynamicSharedMemorySize, SMEM128);
    cudaFuncSetAttribute((const void*)mma_gemm<64>,  cudaFuncAttributeMaxDynamicSharedMemorySize, SMEM64);
    cudaFuncSetAttribute((const void*)flash_kernel,  cudaFuncAttributeMaxDynamicSharedMemorySize, FL_SMEM);

    __nv_bfloat16 *xh,*xl,*wqh,*wql,*wkh,*wkl,*wvh,*wvl,*wch,*wcl,*w1h,*w1l,*w2h,*w2l;
    __nv_bfloat16 *qh,*ql,*kh,*kl,*vth,*vtl,*avh,*avl,*uh,*ul,*h1h,*h1l;
    float *v,*attn,*u,*z;
    cudaGetSymbolAddress((void**)&xh,  g_x_h);  cudaGetSymbolAddress((void**)&xl,  g_x_l);
    cudaGetSymbolAddress((void**)&wqh, g_wq_h); cudaGetSymbolAddress((void**)&wql, g_wq_l);
    cudaGetSymbolAddress((void**)&wkh, g_wk_h); cudaGetSymbolAddress((void**)&wkl, g_wk_l);
    cudaGetSymbolAddress((void**)&wvh, g_wv_h); cudaGetSymbolAddress((void**)&wvl, g_wv_l);
    cudaGetSymbolAddress((void**)&wch, g_wc_h); cudaGetSymbolAddress((void**)&wcl, g_wc_l);
    cudaGetSymbolAddress((void**)&w1h, g_w1_h); cudaGetSymbolAddress((void**)&w1l, g_w1_l);
    cudaGetSymbolAddress((void**)&w2h, g_w2_h); cudaGetSymbolAddress((void**)&w2l, g_w2_l);
    cudaGetSymbolAddress((void**)&qh,  g_q_h);  cudaGetSymbolAddress((void**)&ql,  g_q_l);
    cudaGetSymbolAddress((void**)&kh,  g_k_h);  cudaGetSymbolAddress((void**)&kl,  g_k_l);
    cudaGetSymbolAddress((void**)&v,   g_v);
    cudaGetSymbolAddress((void**)&vth, g_vt_h); cudaGetSymbolAddress((void**)&vtl, g_vt_l);
    cudaGetSymbolAddress((void**)&avh, g_av_h); cudaGetSymbolAddress((void**)&avl, g_av_l);
    cudaGetSymbolAddress((void**)&attn,g_attn);
    cudaGetSymbolAddress((void**)&u,   g_u);
    cudaGetSymbolAddress((void**)&uh,  g_u_h);  cudaGetSymbolAddress((void**)&ul,  g_u_l);
    cudaGetSymbolAddress((void**)&h1h, g_h1_h); cudaGetSymbolAddress((void**)&h1l, g_h1_l);
    cudaGetSymbolAddress((void**)&z,   g_z);

    // input conversions
    cvt(x,   xh,  xl,  (long)NTOK*Dd);
    cvt(wq,  wqh, wql, (long)Dd*Dd);
    cvt(wk,  wkh, wkl, (long)Dd*Dd);
    cvt(wv,  wvh, wvl, (long)Dd*Dd);
    cvt(wc,  wch, wcl, (long)Dd*Dd);
    cvt(w1_w,w1h, w1l, (long)Mf*Dd);
    cvt(w2_w,w2h, w2l, (long)Mf*Dd);

    GemmArgs a;
    // Q = x @ wq^T  (bf16-pair)
    a = {xh,xl,wqh,wql, nullptr,qh,ql, NTOK,Dd,Dd, Dd,Dd,Dd, 0,0,0,1, 1.0f, nullptr,0, nullptr,0};
    run_gemm<128>(a);
    // K
    a = {xh,xl,wkh,wkl, nullptr,kh,kl, NTOK,Dd,Dd, Dd,Dd,Dd, 0,0,0,1, 1.0f, nullptr,0, nullptr,0};
    run_gemm<128>(a);
    // V (fp32, then transpose+split)
    a = {xh,xl,wvh,wvl, v,nullptr,nullptr, NTOK,Dd,Dd, Dd,Dd,Dd, 0,0,0,1, 1.0f, nullptr,0, nullptr,0};
    run_gemm<128>(a);
    {
        dim3 g(Ss/64, BH);
        transpose_split_v<<<g, 256>>>(v, vth, vtl);
    }
    // fused attention: av = softmax(Q K^T / 8 + mask) @ V  (bf16-pair output)
    {
        dim3 g(Ss/128, BH);
        flash_kernel<<<g, 256, FL_SMEM>>>(qh, ql, kh, kl, vth, vtl, mask, avh, avl);
    }
    // attn = av @ wc^T + x  (fp32)
    a = {avh,avl,wch,wcl, attn,nullptr,nullptr, NTOK,Dd,Dd, Dd,Dd,Dd, 0,0,0,1,
         1.0f, x,Dd, nullptr,0};
    run_gemm<128>(a);
    // u = LN1(attn)
    layernorm_kernel<<<NTOK, 256>>>(attn, u, uh, ul, ln1_g, ln1_b);
    // h1 = relu(u @ w1^T + b1)
    a = {uh,ul,w1h,w1l, nullptr,h1h,h1l, NTOK,Mf,Dd, Dd,Dd,Mf, 0,0,0,1,
         1.0f, nullptr,0, w1_b,1};
    run_gemm<128>(a);
    // z = h1 @ w2^T + b2 + u
    a = {h1h,h1l,w2h,w2l, z,nullptr,nullptr, NTOK,Dd,Mf, Mf,Mf,Dd, 0,0,0,1,
         1.0f, u,Dd, w2_b,0};
    run_gemm<128>(a);
    // out = LN2(z)
    layernorm_kernel<<<NTOK, 256>>>(z, out, nullptr, nullptr, ln2_g, ln2_b);
}

// round 5
// speedup vs baseline: 6.2717x; 1.5593x over previous
#include <cuda_runtime.h>
#include <cuda_fp16.h>
#include <cstdint>
#include <math.h>

#define Hh   16
#define Kh   64
#define Dd   1024
#define Mf   4096
#define Ss   2048
#define Bb   4
#define NTOK (Ss*Bb)      // 8192
#define BH   (Bb*Hh)      // 64
#define EPSL 1e-5f

// ---------------- scratch buffers (device globals: allocation-free) ----------------
__device__ __half g_x_h[(size_t)NTOK*Dd],  g_x_l[(size_t)NTOK*Dd];
__device__ __half g_wq[(size_t)Dd*Dd];
__device__ __half g_wk[(size_t)Dd*Dd];
__device__ __half g_wv[(size_t)Dd*Dd];
__device__ __half g_wc[(size_t)Dd*Dd];
__device__ __half g_w1[(size_t)Mf*Dd];
__device__ __half g_w2[(size_t)Mf*Dd];
__device__ __half g_q_h[(size_t)NTOK*Dd],  g_q_l[(size_t)NTOK*Dd];
__device__ __half g_k[(size_t)NTOK*Dd];
__device__ float  g_v[(size_t)NTOK*Dd];
__device__ __half g_vt[(size_t)BH*Kh*Ss];
__device__ __half g_av_h[(size_t)NTOK*Dd], g_av_l[(size_t)NTOK*Dd];
__device__ float  g_attn[(size_t)NTOK*Dd];
__device__ float  g_u[(size_t)NTOK*Dd];
__device__ __half g_u_h[(size_t)NTOK*Dd],  g_u_l[(size_t)NTOK*Dd];
__device__ __half g_h1_h[(size_t)NTOK*Mf], g_h1_l[(size_t)NTOK*Mf];
__device__ float  g_z[(size_t)NTOK*Dd];

// ---------------- helpers ----------------
__device__ __forceinline__ uint32_t smem_u32(const void* p){
    uint32_t a;
    asm("{ .reg .u64 t; cvta.to.shared.u64 t, %1; cvt.u32.u64 %0, t; }" : "=r"(a) : "l"(p));
    return a;
}
__device__ __forceinline__ void split2h(float x, __half& h, __half& l){
    h = __float2half_rn(x);
    l = __float2half_rn(x - __half2float(h));
}
__device__ __forceinline__ uint32_t pack2h(__half a, __half b){
    return (uint32_t)__half_as_ushort(a) | ((uint32_t)__half_as_ushort(b) << 16);
}
__device__ __forceinline__ void cpasync16(uint32_t saddr, const void* gaddr){
    asm volatile("cp.async.cg.shared.global [%0], [%1], 16;" :: "r"(saddr), "l"(gaddr) : "memory");
}
__device__ __forceinline__ void ldmx4(uint32_t* r, uint32_t addr){
    asm volatile("ldmatrix.sync.aligned.m8n8.x4.shared.b16 {%0,%1,%2,%3}, [%4];"
                 : "=r"(r[0]), "=r"(r[1]), "=r"(r[2]), "=r"(r[3]) : "r"(addr));
}
__device__ __forceinline__ void mma16816(float* c, const uint32_t* a, const uint32_t* b){
    asm volatile("mma.sync.aligned.m16n8k16.row.col.f32.f16.f16.f32 "
                 "{%0,%1,%2,%3}, {%4,%5,%6,%7}, {%8,%9}, {%0,%1,%2,%3};"
                 : "+f"(c[0]), "+f"(c[1]), "+f"(c[2]), "+f"(c[3])
                 : "r"(a[0]), "r"(a[1]), "r"(a[2]), "r"(a[3]), "r"(b[0]), "r"(b[1]));
}

// ---------------- mma.sync fp16 2-pass NT GEMM ----------------
// C[128 x BN] = alpha * (Ah+Al) @ B^T (+bias[n]) (+add[m,n]) (+relu)
// A: split fp16 hi/lo (exact), B: single fp16 (rounded). K-contiguous rows.
// Output: fp32 (Cf), fp16 split pair (Ch+Cl), or fp16 single (Ch only).
template<int BN>
__global__ void __launch_bounds__(256) mma_gemm(
    const __half* __restrict__ Ah, const __half* __restrict__ Al,
    const __half* __restrict__ B,
    float* __restrict__ Cf, __half* __restrict__ Ch, __half* __restrict__ Cl,
    int Kd, long lda, long ldb, long ldc,
    float alpha, const float* __restrict__ add, long ldadd,
    const float* __restrict__ bias, int doRelu)
{
    constexpr int BK   = 32;
    constexpr int LDS  = BK + 8;
    constexpr int WN   = BN / 2;
    constexpr int NT   = WN / 8;
    constexpr int A_BYTES = 128 * LDS * 2;
    constexpr int B_BYTES = BN  * LDS * 2;
    constexpr int STAGE   = 2 * A_BYTES + B_BYTES;

    extern __shared__ char smc[];
    const uint32_t sbase = smem_u32(smc);

    const int tid  = threadIdx.x;
    const int lane = tid & 31;
    const int wid  = tid >> 5;
    const int warpM = (wid & 3) * 32;
    const int warpN = (wid >> 2) * WN;

    const int  m0   = blockIdx.y * 128;
    const int  n0   = blockIdx.x * BN;
    const int  KT   = Kd / BK;

    const int la_row = tid >> 2, la_ch = tid & 3;
    auto load_stage = [&](int kt, int buf){
        const int k0 = kt * BK;
        const uint32_t s0 = sbase + buf * STAGE;
        #pragma unroll
        for (int it = 0; it < 2; it++){
            int row = la_row + it * 64;
            long g = (long)(m0 + row) * lda + k0 + la_ch * 8;
            uint32_t so = (uint32_t)(row * (LDS * 2) + la_ch * 16);
            cpasync16(s0 + so,           Ah + g);
            cpasync16(s0 + A_BYTES + so, Al + g);
        }
        #pragma unroll
        for (int it = 0; it < BN / 64; it++){
            int row = la_row + it * 64;
            long g = (long)(n0 + row) * ldb + k0 + la_ch * 8;
            uint32_t so = (uint32_t)(row * (LDS * 2) + la_ch * 16);
            cpasync16(s0 + 2*A_BYTES + so, B + g);
        }
    };

    load_stage(0, 0);
    asm volatile("cp.async.commit_group;" ::: "memory");
    load_stage(1, 1);
    asm volatile("cp.async.commit_group;" ::: "memory");

    float acc[2][NT][4];
    #pragma unroll
    for (int i = 0; i < 2; i++)
        #pragma unroll
        for (int j = 0; j < NT; j++)
            #pragma unroll
            for (int e = 0; e < 4; e++) acc[i][j][e] = 0.0f;

    const int aRow = (lane & 15), aColHalf = (lane >> 4) * 8;
    const int bRow = (lane >> 4) * 8 + (lane & 7), bColHalf = ((lane >> 3) & 1) * 8;

    for (int kt = 0; kt < KT; kt++){
        asm volatile("cp.async.wait_group 1;" ::: "memory");
        __syncthreads();
        const int buf = kt & 1;
        const uint32_t sA0 = sbase + buf * STAGE;
        const uint32_t sB0 = sA0 + 2 * A_BYTES;

        #pragma unroll
        for (int ks = 0; ks < 2; ks++){
            const int k16 = ks * 16;
            uint32_t ah[2][4], al[2][4];
            #pragma unroll
            for (int mt = 0; mt < 2; mt++){
                uint32_t addr = sA0 + (uint32_t)(((warpM + mt*16 + aRow) * LDS + k16 + aColHalf) * 2);
                ldmx4(ah[mt], addr);
                ldmx4(al[mt], addr + A_BYTES);
            }
            uint32_t bf[NT][2];
            #pragma unroll
            for (int g = 0; g < NT/2; g++){
                uint32_t addr = sB0 + (uint32_t)(((warpN + g*16 + bRow) * LDS + k16 + bColHalf) * 2);
                uint32_t r[4];
                ldmx4(r, addr);
                bf[2*g][0] = r[0]; bf[2*g][1] = r[1];
                bf[2*g+1][0] = r[2]; bf[2*g+1][1] = r[3];
            }
            #pragma unroll
            for (int mt = 0; mt < 2; mt++)
                #pragma unroll
                for (int j = 0; j < NT; j++){
                    mma16816(acc[mt][j], ah[mt], bf[j]);
                    mma16816(acc[mt][j], al[mt], bf[j]);
                }
        }
        __syncthreads();
        if (kt + 2 < KT) load_stage(kt + 2, buf);
        asm volatile("cp.async.commit_group;" ::: "memory");
    }

    #pragma unroll
    for (int mt = 0; mt < 2; mt++){
        #pragma unroll
        for (int j = 0; j < NT; j++){
            const int col = n0 + warpN + j*8 + (lane & 3) * 2;
            const float b0 = bias ? bias[col]   : 0.0f;
            const float b1 = bias ? bias[col+1] : 0.0f;
            #pragma unroll
            for (int half = 0; half < 2; half++){
                const long row = m0 + warpM + mt*16 + (lane >> 2) + half*8;
                float v0 = acc[mt][j][half*2+0] * alpha + b0;
                float v1 = acc[mt][j][half*2+1] * alpha + b1;
                if (add){
                    v0 += add[row * ldadd + col];
                    v1 += add[row * ldadd + col + 1];
                }
                if (doRelu){ v0 = fmaxf(v0, 0.0f); v1 = fmaxf(v1, 0.0f); }
                const long ci = row * ldc + col;
                if (Ch){
                    __half h0,l0,h1,l1;
                    split2h(v0,h0,l0); split2h(v1,h1,l1);
                    *(uint32_t*)(Ch + ci) = pack2h(h0, h1);
                    if (Cl) *(uint32_t*)(Cl + ci) = pack2h(l0, l1);
                } else {
                    *(float2*)(Cf + ci) = make_float2(v0, v1);
                }
            }
        }
    }
}

// ---------------- fused flash attention (fp16 2-pass) ----------------
// grid (Ss/128, BH); 256 threads = 8 warps, each warp owns 16 q-rows.
// Q/K viewed as [Ss, 4096] (cols = b*1024 + h*64 + k), head offset z*64, z = b*16+h.
#define FL_LQ 72
#define FL_LV 136
#define FL_QCOMP (128*FL_LQ*2)               // 18432
#define FL_KBYTES (128*FL_LQ*2)              // 18432 (single)
#define FL_VBYTES (64*FL_LV*2)               // 17408 (single)
#define FL_STAGE (FL_KBYTES + FL_VBYTES)     // 35840
#define FL_SMQ   0
#define FL_SMST  (2*FL_QCOMP)                // 36864
#define FL_SMEM  (FL_SMST + 2*FL_STAGE)      // 108544

__global__ void __launch_bounds__(256,1) flash_kernel(
    const __half* __restrict__ Qh, const __half* __restrict__ Ql,
    const __half* __restrict__ Kk,
    const __half* __restrict__ Vt,
    const float* __restrict__ mask,
    __half* __restrict__ AVh, __half* __restrict__ AVl)
{
    extern __shared__ char smc[];
    const uint32_t sbase = smem_u32(smc);
    const int tid = threadIdx.x, lane = tid & 31, wid = tid >> 5;
    const int q0 = blockIdx.x * 128;
    const int z  = blockIdx.y;
    const long hOff = (long)z * 64;

    auto load_q = [&](){
        #pragma unroll
        for (int it = 0; it < 4; it++){
            int idx = it*256 + tid;
            int row = idx >> 3, ch = idx & 7;
            long g = (long)(q0 + row) * 4096 + hOff + ch*8;
            uint32_t so = sbase + FL_SMQ + (uint32_t)(row*FL_LQ*2 + ch*16);
            cpasync16(so,            Qh + g);
            cpasync16(so + FL_QCOMP, Ql + g);
        }
    };
    auto load_stage = [&](int kt, int buf){
        const int t0 = kt * 128;
        const uint32_t s0 = sbase + FL_SMST + buf*FL_STAGE;
        #pragma unroll
        for (int it = 0; it < 4; it++){
            int idx = it*256 + tid;
            int row = idx >> 3, ch = idx & 7;
            long g = (long)(t0 + row) * 4096 + hOff + ch*8;
            uint32_t so = s0 + (uint32_t)(row*FL_LQ*2 + ch*16);
            cpasync16(so, Kk + g);
        }
        const uint32_t v0 = s0 + FL_KBYTES;
        #pragma unroll
        for (int it = 0; it < 4; it++){
            int idx = it*256 + tid;
            int row = idx >> 4, ch = idx & 15;
            long g = (long)z*64*2048 + (long)row*2048 + t0 + ch*8;
            uint32_t so = v0 + (uint32_t)(row*FL_LV*2 + ch*16);
            cpasync16(so, Vt + g);
        }
    };

    load_q();
    load_stage(0, 0);
    asm volatile("cp.async.commit_group;" ::: "memory");
    load_stage(1, 1);
    asm volatile("cp.async.commit_group;" ::: "memory");
    asm volatile("cp.async.wait_group 1;" ::: "memory");
    __syncthreads();

    const int aRow = lane & 15, aCol = (lane >> 4) * 8;
    const int bRow = (lane >> 4) * 8 + (lane & 7), bCol = ((lane >> 3) & 1) * 8;

    uint32_t qfh[4][4], qfl[4][4];
    #pragma unroll
    for (int kc = 0; kc < 4; kc++){
        uint32_t addr = sbase + FL_SMQ + (uint32_t)(((wid*16 + aRow)*FL_LQ + kc*16 + aCol) * 2);
        ldmx4(qfh[kc], addr);
        ldmx4(qfl[kc], addr + FL_QCOMP);
    }

    float O[8][4];
    #pragma unroll
    for (int j = 0; j < 8; j++){ O[j][0]=0; O[j][1]=0; O[j][2]=0; O[j][3]=0; }
    float m0 = -INFINITY, m1 = -INFINITY, l0 = 0.0f, l1 = 0.0f;
    const int rloc = wid*16 + (lane >> 2);

    for (int kt = 0; kt < 16; kt++){
        asm volatile("cp.async.wait_group 1;" ::: "memory");
        __syncthreads();
        const uint32_t sK = sbase + FL_SMST + (kt & 1)*FL_STAGE;
        const uint32_t sV = sK + FL_KBYTES;

        float S[16][4];
        #pragma unroll
        for (int j = 0; j < 16; j++){ S[j][0]=0; S[j][1]=0; S[j][2]=0; S[j][3]=0; }

        #pragma unroll
        for (int kc = 0; kc < 4; kc++){
            #pragma unroll
            for (int g = 0; g < 8; g++){
                uint32_t addr = sK + (uint32_t)(((g*16 + bRow)*FL_LQ + kc*16 + bCol) * 2);
                uint32_t bk[4];
                ldmx4(bk, addr);
                mma16816(S[2*g],   qfh[kc], bk+0);
                mma16816(S[2*g],   qfl[kc], bk+0);
                mma16816(S[2*g+1], qfh[kc], bk+2);
                mma16816(S[2*g+1], qfl[kc], bk+2);
            }
        }

        // scale + mask + running max
        const int t0 = kt * 128;
        const long mr0 = (long)(q0 + rloc) * 2048 + t0;
        const long mr1 = mr0 + 8 * 2048;
        float mx0 = -INFINITY, mx1 = -INFINITY;
        #pragma unroll
        for (int j = 0; j < 16; j++){
            int c = j*8 + (lane & 3)*2;
            float2 k0v = *(const float2*)(mask + mr0 + c);
            float2 k1v = *(const float2*)(mask + mr1 + c);
            S[j][0] = S[j][0]*0.125f + k0v.x;
            S[j][1] = S[j][1]*0.125f + k0v.y;
            S[j][2] = S[j][2]*0.125f + k1v.x;
            S[j][3] = S[j][3]*0.125f + k1v.y;
            mx0 = fmaxf(mx0, fmaxf(S[j][0], S[j][1]));
            mx1 = fmaxf(mx1, fmaxf(S[j][2], S[j][3]));
        }
        mx0 = fmaxf(mx0, __shfl_xor_sync(0xFFFFFFFFu, mx0, 1));
        mx0 = fmaxf(mx0, __shfl_xor_sync(0xFFFFFFFFu, mx0, 2));
        mx1 = fmaxf(mx1, __shfl_xor_sync(0xFFFFFFFFu, mx1, 1));
        mx1 = fmaxf(mx1, __shfl_xor_sync(0xFFFFFFFFu, mx1, 2));
        float nm0 = fmaxf(m0, mx0), nm1 = fmaxf(m1, mx1);
        float f0 = (m0 > -INFINITY) ? __expf(m0 - nm0) : 0.0f;
        float f1 = (m1 > -INFINITY) ? __expf(m1 - nm1) : 0.0f;
        m0 = nm0; m1 = nm1;

        float s0 = 0.0f, s1 = 0.0f;
        #pragma unroll
        for (int j = 0; j < 16; j++){
            S[j][0] = __expf(S[j][0] - m0);
            S[j][1] = __expf(S[j][1] - m0);
            S[j][2] = __expf(S[j][2] - m1);
            S[j][3] = __expf(S[j][3] - m1);
            s0 += S[j][0] + S[j][1];
            s1 += S[j][2] + S[j][3];
        }
        s0 += __shfl_xor_sync(0xFFFFFFFFu, s0, 1);
        s0 += __shfl_xor_sync(0xFFFFFFFFu, s0, 2);
        s1 += __shfl_xor_sync(0xFFFFFFFFu, s1, 1);
        s1 += __shfl_xor_sync(0xFFFFFFFFu, s1, 2);
        l0 = l0*f0 + s0;
        l1 = l1*f1 + s1;
        #pragma unroll
        for (int j = 0; j < 8; j++){
            O[j][0]*=f0; O[j][1]*=f0; O[j][2]*=f1; O[j][3]*=f1;
        }

        // O += (Ph + Pl) @ V   (P split exact, V single)
        #pragma unroll
        for (int kc = 0; kc < 8; kc++){
            uint32_t ph[4], pl[4];
            {
                __half h0,lo0,h1,lo1;
                split2h(S[2*kc][0],h0,lo0);   split2h(S[2*kc][1],h1,lo1);
                ph[0]=pack2h(h0,h1); pl[0]=pack2h(lo0,lo1);
                split2h(S[2*kc][2],h0,lo0);   split2h(S[2*kc][3],h1,lo1);
                ph[1]=pack2h(h0,h1); pl[1]=pack2h(lo0,lo1);
                split2h(S[2*kc+1][0],h0,lo0); split2h(S[2*kc+1][1],h1,lo1);
                ph[2]=pack2h(h0,h1); pl[2]=pack2h(lo0,lo1);
                split2h(S[2*kc+1][2],h0,lo0); split2h(S[2*kc+1][3],h1,lo1);
                ph[3]=pack2h(h0,h1); pl[3]=pack2h(lo0,lo1);
            }
            #pragma unroll
            for (int g = 0; g < 4; g++){
                uint32_t addr = sV + (uint32_t)(((g*16 + bRow)*FL_LV + kc*16 + bCol) * 2);
                uint32_t vf[4];
                ldmx4(vf, addr);
                mma16816(O[2*g],   ph, vf+0);
                mma16816(O[2*g],   pl, vf+0);
                mma16816(O[2*g+1], ph, vf+2);
                mma16816(O[2*g+1], pl, vf+2);
            }
        }

        __syncthreads();
        if (kt + 2 < 16) load_stage(kt + 2, kt & 1);
        asm volatile("cp.async.commit_group;" ::: "memory");
    }

    // finalize: O /= l, write av (fp16 pair), av viewed as [Ss, 4096]
    const float inv0 = 1.0f / l0, inv1 = 1.0f / l1;
    #pragma unroll
    for (int j = 0; j < 8; j++){
        const int col = j*8 + (lane & 3)*2;
        const long a0 = (long)(q0 + rloc) * 4096 + hOff + col;
        const long a1 = a0 + 8L * 4096;
        __half h0,lo0,h1,lo1;
        split2h(O[j][0]*inv0, h0, lo0);
        split2h(O[j][1]*inv0, h1, lo1);
        *(uint32_t*)(AVh + a0) = pack2h(h0, h1);
        *(uint32_t*)(AVl + a0) = pack2h(lo0, lo1);
        split2h(O[j][2]*inv1, h0, lo0);
        split2h(O[j][3]*inv1, h1, lo1);
        *(uint32_t*)(AVh + a1) = pack2h(h0, h1);
        *(uint32_t*)(AVl + a1) = pack2h(lo0, lo1);
    }
}

// ---------------- fp32 -> fp16 hi/lo split ----------------
__global__ void cvt_split_kernel(const float4* __restrict__ in,
                                 uint2* __restrict__ hi, uint2* __restrict__ lo, long n4)
{
    long i = (long)blockIdx.x * 256 + threadIdx.x;
    if (i >= n4) return;
    float4 v = in[i];
    __half h0,h1,h2,h3,l0,l1,l2,l3;
    split2h(v.x,h0,l0); split2h(v.y,h1,l1); split2h(v.z,h2,l2); split2h(v.w,h3,l3);
    uint2 H, L;
    H.x = pack2h(h0,h1); H.y = pack2h(h2,h3);
    L.x = pack2h(l0,l1); L.y = pack2h(l2,l3);
    hi[i] = H; lo[i] = L;
}

// ---------------- fp32 -> fp16 single ----------------
__global__ void cvt_half_kernel(const float4* __restrict__ in,
                                uint2* __restrict__ out, long n4)
{
    long i = (long)blockIdx.x * 256 + threadIdx.x;
    if (i >= n4) return;
    float4 v = in[i];
    uint2 H;
    H.x = pack2h(__float2half_rn(v.x), __float2half_rn(v.y));
    H.y = pack2h(__float2half_rn(v.z), __float2half_rn(v.w));
    out[i] = H;
}

// ---------------- V transpose -> fp16 single: v[s,b,h,kk] -> vt[z][kk][t] ----------------
__global__ void transpose_v(const float* __restrict__ v, __half* __restrict__ vt)
{
    __shared__ float t[64][65];
    const int z  = blockIdx.y;
    const int t0 = blockIdx.x * 64;
    const int b  = z >> 4, h = z & 15;
    const float* src = v + (size_t)b*1024 + (size_t)h*64;
    for (int it = 0; it < 16; it++){
        int idx = it*256 + threadIdx.x;
        int ti = idx >> 6, kk = idx & 63;
        t[ti][kk] = src[(size_t)(t0 + ti)*4096 + kk];
    }
    __syncthreads();
    size_t obase = (size_t)z * Kh * Ss + t0;
    for (int it = 0; it < 16; it++){
        int idx = it*256 + threadIdx.x;
        int kk = idx >> 6, ti = idx & 63;
        vt[obase + (size_t)kk*Ss + ti] = __float2half_rn(t[ti][kk]);
    }
}

// ---------------- layernorm over D=1024; optional fp16 split output ----------------
__global__ void layernorm_kernel(const float* __restrict__ in,
                                 float* __restrict__ out,
                                 __half* __restrict__ oh,
                                 __half* __restrict__ ol,
                                 const float* __restrict__ gamma,
                                 const float* __restrict__ beta)
{
    const int row = blockIdx.x;
    const float* x = in + (size_t)row * Dd;
    const int tid = threadIdx.x;

    float v[4];
    float s = 0.0f, s2 = 0.0f;
    #pragma unroll
    for (int i = 0; i < 4; i++){
        v[i] = x[tid + i*256];
        s  += v[i];
        s2 += v[i]*v[i];
    }
    __shared__ float r1[256], r2[256];
    r1[tid] = s; r2[tid] = s2; __syncthreads();
    for (int off = 128; off > 0; off >>= 1){
        if (tid < off){ r1[tid] += r1[tid+off]; r2[tid] += r2[tid+off]; }
        __syncthreads();
    }
    float mean = r1[0] * (1.0f/Dd);
    float var  = r2[0] * (1.0f/Dd) - mean*mean;
    float inv  = rsqrtf(var + EPSL);
    #pragma unroll
    for (int i = 0; i < 4; i++){
        int c = tid + i*256;
        float y = (v[i] - mean) * inv * gamma[c] + beta[c];
        out[(size_t)row*Dd + c] = y;
        if (oh){
            __half h, l; split2h(y, h, l);
            oh[(size_t)row*Dd + c] = h;
            ol[(size_t)row*Dd + c] = l;
        }
    }
}

// ---------------- host side ----------------
static const int SMEM128 = 2 * (2*10240 + 10240);   // 61440
static const int SMEM64  = 2 * (2*10240 + 5120);    // 51200

static inline void cvt_split(const float* in, __half* h, __half* l, long n){
    long n4 = n / 4;
    cvt_split_kernel<<<(unsigned)(n4 / 256), 256>>>((const float4*)in, (uint2*)h, (uint2*)l, n4);
}
static inline void cvt_half(const float* in, __half* o, long n){
    long n4 = n / 4;
    cvt_half_kernel<<<(unsigned)(n4 / 256), 256>>>((const float4*)in, (uint2*)o, n4);
}

struct GemmArgs {
    const __half *Ah, *Al, *B;
    float* Cf; __half *Ch, *Cl;
    int M, N, Kd; long lda, ldb, ldc;
    float alpha; const float* add; long ldadd; const float* bias; int relu;
};

template<int BN>
static inline void run_gemm(const GemmArgs& a){
    dim3 grid(a.N / BN, a.M / 128, 1);
    int smem = (BN == 128) ? SMEM128 : SMEM64;
    mma_gemm<BN><<<grid, 256, smem>>>(a.Ah, a.Al, a.B, a.Cf, a.Ch, a.Cl,
                                      a.Kd, a.lda, a.ldb, a.ldc,
                                      a.alpha, a.add, a.ldadd, a.bias, a.relu);
}

extern "C" void kernel_launch(void* const* d_in, const int* in_sizes, int n_in,
                              void* d_out, int out_size)
{
    const float* x     = (const float*)d_in[0];
    const float* mask  = (const float*)d_in[1];
    const float* wq    = (const float*)d_in[2];
    const float* wk    = (const float*)d_in[3];
    const float* wv    = (const float*)d_in[4];
    const float* wc    = (const float*)d_in[5];
    const float* w1_w  = (const float*)d_in[6];
    const float* w1_b  = (const float*)d_in[7];
    const float* w2_w  = (const float*)d_in[8];
    const float* w2_b  = (const float*)d_in[9];
    const float* ln1_g = (const float*)d_in[10];
    const float* ln1_b = (const float*)d_in[11];
    const float* ln2_g = (const float*)d_in[12];
    const float* ln2_b = (const float*)d_in[13];
    float* out = (float*)d_out;

    cudaFuncSetAttribute((const void*)mma_gemm<128>, cudaFuncAttributeMaxDynamicSharedMemorySize, SMEM128);
    cudaFuncSetAttribute((const void*)flash_kernel,  cudaFuncAttributeMaxDynamicSharedMemorySize, FL_SMEM);

    __half *xh,*xl,*pwq,*pwk,*pwv,*pwc,*pw1,*pw2;
    __half *qh,*ql,*kk,*vt,*avh,*avl,*uh,*ul,*h1h,*h1l;
    float *v,*attn,*u,*z;
    cudaGetSymbolAddress((void**)&xh,  g_x_h);  cudaGetSymbolAddress((void**)&xl,  g_x_l);
    cudaGetSymbolAddress((void**)&pwq, g_wq);
    cudaGetSymbolAddress((void**)&pwk, g_wk);
    cudaGetSymbolAddress((void**)&pwv, g_wv);
    cudaGetSymbolAddress((void**)&pwc, g_wc);
    cudaGetSymbolAddress((void**)&pw1, g_w1);
    cudaGetSymbolAddress((void**)&pw2, g_w2);
    cudaGetSymbolAddress((void**)&qh,  g_q_h);  cudaGetSymbolAddress((void**)&ql,  g_q_l);
    cudaGetSymbolAddress((void**)&kk,  g_k);
    cudaGetSymbolAddress((void**)&v,   g_v);
    cudaGetSymbolAddress((void**)&vt,  g_vt);
    cudaGetSymbolAddress((void**)&avh, g_av_h); cudaGetSymbolAddress((void**)&avl, g_av_l);
    cudaGetSymbolAddress((void**)&attn,g_attn);
    cudaGetSymbolAddress((void**)&u,   g_u);
    cudaGetSymbolAddress((void**)&uh,  g_u_h);  cudaGetSymbolAddress((void**)&ul,  g_u_l);
    cudaGetSymbolAddress((void**)&h1h, g_h1_h); cudaGetSymbolAddress((void**)&h1l, g_h1_l);
    cudaGetSymbolAddress((void**)&z,   g_z);

    // input conversions: x split (exact), weights single (rounded)
    cvt_split(x, xh, xl, (long)NTOK*Dd);
    cvt_half(wq,  pwq, (long)Dd*Dd);
    cvt_half(wk,  pwk, (long)Dd*Dd);
    cvt_half(wv,  pwv, (long)Dd*Dd);
    cvt_half(wc,  pwc, (long)Dd*Dd);
    cvt_half(w1_w,pw1, (long)Mf*Dd);
    cvt_half(w2_w,pw2, (long)Mf*Dd);

    GemmArgs a;
    // Q = x @ wq^T  (split pair out: A-side of flash)
    a = {xh,xl,pwq, nullptr,qh,ql, NTOK,Dd,Dd, Dd,Dd,Dd, 1.0f, nullptr,0, nullptr,0};
    run_gemm<128>(a);
    // K  (single fp16 out: B-side of flash)
    a = {xh,xl,pwk, nullptr,kk,nullptr, NTOK,Dd,Dd, Dd,Dd,Dd, 1.0f, nullptr,0, nullptr,0};
    run_gemm<128>(a);
    // V (fp32, then transpose to single fp16)
    a = {xh,xl,pwv, v,nullptr,nullptr, NTOK,Dd,Dd, Dd,Dd,Dd, 1.0f, nullptr,0, nullptr,0};
    run_gemm<128>(a);
    {
        dim3 g(Ss/64, BH);
        transpose_v<<<g, 256>>>(v, vt);
    }
    // fused attention: av = softmax(Q K^T / 8 + mask) @ V  (split pair out)
    {
        dim3 g(Ss/128, BH);
        flash_kernel<<<g, 256, FL_SMEM>>>(qh, ql, kk, vt, mask, avh, avl);
    }
    // attn = av @ wc^T + x  (fp32)
    a = {avh,avl,pwc, attn,nullptr,nullptr, NTOK,Dd,Dd, Dd,Dd,Dd, 1.0f, x,Dd, nullptr,0};
    run_gemm<128>(a);
    // u = LN1(attn)  (fp32 + split pair)
    layernorm_kernel<<<NTOK, 256>>>(attn, u, uh, ul, ln1_g, ln1_b);
    // h1 = relu(u @ w1^T + b1)  (split pair out)
    a = {uh,ul,pw1, nullptr,h1h,h1l, NTOK,Mf,Dd, Dd,Dd,Mf, 1.0f, nullptr,0, w1_b,1};
    run_gemm<128>(a);
    // z = h1 @ w2^T + b2 + u  (fp32)
    a = {h1h,h1l,pw2, z,nullptr,nullptr, NTOK,Dd,Mf, Mf,Mf,Dd, 1.0f, u,Dd, w2_b,0};
    run_gemm<128>(a);
    // out = LN2(z)
    layernorm_kernel<<<NTOK, 256>>>(z, out, nullptr, nullptr, ln2_g, ln2_b);
}

// round 6
// speedup vs baseline: 9.5678x; 1.5256x over previous
#include <cuda_runtime.h>
#include <cuda_fp16.h>
#include <cstdint>
#include <math.h>

#define Hh   16
#define Kh   64
#define Dd   1024
#define Mf   4096
#define Ss   2048
#define Bb   4
#define NTOK (Ss*Bb)      // 8192
#define BH   (Bb*Hh)      // 64
#define EPSL 1e-5f

// ---------------- scratch buffers (device globals: allocation-free) ----------------
__device__ __half g_x[(size_t)NTOK*Dd];
__device__ __half g_wq[(size_t)Dd*Dd];
__device__ __half g_wk[(size_t)Dd*Dd];
__device__ __half g_wv[(size_t)Dd*Dd];
__device__ __half g_wc[(size_t)Dd*Dd];
__device__ __half g_w1[(size_t)Mf*Dd];
__device__ __half g_w2[(size_t)Mf*Dd];
__device__ __half g_q[(size_t)NTOK*Dd];
__device__ __half g_k[(size_t)NTOK*Dd];
__device__ __half g_vh[(size_t)NTOK*Dd];
__device__ __half g_vt[(size_t)BH*Kh*Ss];
__device__ __half g_av[(size_t)NTOK*Dd];
__device__ float  g_attn[(size_t)NTOK*Dd];
__device__ float  g_u[(size_t)NTOK*Dd];
__device__ __half g_uh[(size_t)NTOK*Dd];
__device__ __half g_h1[(size_t)NTOK*Mf];
__device__ float  g_z[(size_t)NTOK*Dd];

// ---------------- helpers ----------------
__device__ __forceinline__ uint32_t smem_u32(const void* p){
    uint32_t a;
    asm("{ .reg .u64 t; cvta.to.shared.u64 t, %1; cvt.u32.u64 %0, t; }" : "=r"(a) : "l"(p));
    return a;
}
__device__ __forceinline__ uint32_t pack2h(__half a, __half b){
    return (uint32_t)__half_as_ushort(a) | ((uint32_t)__half_as_ushort(b) << 16);
}
__device__ __forceinline__ void cpasync16(uint32_t saddr, const void* gaddr){
    asm volatile("cp.async.cg.shared.global [%0], [%1], 16;" :: "r"(saddr), "l"(gaddr) : "memory");
}
__device__ __forceinline__ void ldmx4(uint32_t* r, uint32_t addr){
    asm volatile("ldmatrix.sync.aligned.m8n8.x4.shared.b16 {%0,%1,%2,%3}, [%4];"
                 : "=r"(r[0]), "=r"(r[1]), "=r"(r[2]), "=r"(r[3]) : "r"(addr));
}
__device__ __forceinline__ void mma16816(float* c, const uint32_t* a, const uint32_t* b){
    asm volatile("mma.sync.aligned.m16n8k16.row.col.f32.f16.f16.f32 "
                 "{%0,%1,%2,%3}, {%4,%5,%6,%7}, {%8,%9}, {%0,%1,%2,%3};"
                 : "+f"(c[0]), "+f"(c[1]), "+f"(c[2]), "+f"(c[3])
                 : "r"(a[0]), "r"(a[1]), "r"(a[2]), "r"(a[3]), "r"(b[0]), "r"(b[1]));
}

// ---------------- mma.sync fp16 single-pass NT GEMM ----------------
// C[128 x BN] = alpha * A @ B^T (+bias[n]) (+add[m,n]) (+relu)
// A,B fp16, K-contiguous rows. Output fp32 (Cf) or fp16 (Ch).
template<int BN>
__global__ void __launch_bounds__(256) mma_gemm(
    const __half* __restrict__ A, const __half* __restrict__ B,
    float* __restrict__ Cf, __half* __restrict__ Ch,
    int Kd, long lda, long ldb, long ldc,
    float alpha, const float* __restrict__ add, long ldadd,
    const float* __restrict__ bias, int doRelu)
{
    constexpr int BK   = 32;
    constexpr int LDS  = BK + 8;
    constexpr int WN   = BN / 2;
    constexpr int NT   = WN / 8;
    constexpr int A_BYTES = 128 * LDS * 2;
    constexpr int B_BYTES = BN  * LDS * 2;
    constexpr int STAGE   = A_BYTES + B_BYTES;

    extern __shared__ char smc[];
    const uint32_t sbase = smem_u32(smc);

    const int tid  = threadIdx.x;
    const int lane = tid & 31;
    const int wid  = tid >> 5;
    const int warpM = (wid & 3) * 32;
    const int warpN = (wid >> 2) * WN;

    const int  m0   = blockIdx.y * 128;
    const int  n0   = blockIdx.x * BN;
    const int  KT   = Kd / BK;

    const int la_row = tid >> 2, la_ch = tid & 3;
    auto load_stage = [&](int kt, int buf){
        const int k0 = kt * BK;
        const uint32_t s0 = sbase + buf * STAGE;
        #pragma unroll
        for (int it = 0; it < 2; it++){
            int row = la_row + it * 64;
            long g = (long)(m0 + row) * lda + k0 + la_ch * 8;
            uint32_t so = (uint32_t)(row * (LDS * 2) + la_ch * 16);
            cpasync16(s0 + so, A + g);
        }
        #pragma unroll
        for (int it = 0; it < BN / 64; it++){
            int row = la_row + it * 64;
            long g = (long)(n0 + row) * ldb + k0 + la_ch * 8;
            uint32_t so = (uint32_t)(row * (LDS * 2) + la_ch * 16);
            cpasync16(s0 + A_BYTES + so, B + g);
        }
    };

    load_stage(0, 0);
    asm volatile("cp.async.commit_group;" ::: "memory");
    load_stage(1, 1);
    asm volatile("cp.async.commit_group;" ::: "memory");

    float acc[2][NT][4];
    #pragma unroll
    for (int i = 0; i < 2; i++)
        #pragma unroll
        for (int j = 0; j < NT; j++)
            #pragma unroll
            for (int e = 0; e < 4; e++) acc[i][j][e] = 0.0f;

    const int aRow = (lane & 15), aColHalf = (lane >> 4) * 8;
    const int bRow = (lane >> 4) * 8 + (lane & 7), bColHalf = ((lane >> 3) & 1) * 8;

    for (int kt = 0; kt < KT; kt++){
        asm volatile("cp.async.wait_group 1;" ::: "memory");
        __syncthreads();
        const int buf = kt & 1;
        const uint32_t sA0 = sbase + buf * STAGE;
        const uint32_t sB0 = sA0 + A_BYTES;

        #pragma unroll
        for (int ks = 0; ks < 2; ks++){
            const int k16 = ks * 16;
            uint32_t af[2][4];
            #pragma unroll
            for (int mt = 0; mt < 2; mt++){
                uint32_t addr = sA0 + (uint32_t)(((warpM + mt*16 + aRow) * LDS + k16 + aColHalf) * 2);
                ldmx4(af[mt], addr);
            }
            uint32_t bf[NT][2];
            #pragma unroll
            for (int g = 0; g < NT/2; g++){
                uint32_t addr = sB0 + (uint32_t)(((warpN + g*16 + bRow) * LDS + k16 + bColHalf) * 2);
                uint32_t r[4];
                ldmx4(r, addr);
                bf[2*g][0] = r[0]; bf[2*g][1] = r[1];
                bf[2*g+1][0] = r[2]; bf[2*g+1][1] = r[3];
            }
            #pragma unroll
            for (int mt = 0; mt < 2; mt++)
                #pragma unroll
                for (int j = 0; j < NT; j++)
                    mma16816(acc[mt][j], af[mt], bf[j]);
        }
        __syncthreads();
        if (kt + 2 < KT) load_stage(kt + 2, buf);
        asm volatile("cp.async.commit_group;" ::: "memory");
    }

    #pragma unroll
    for (int mt = 0; mt < 2; mt++){
        #pragma unroll
        for (int j = 0; j < NT; j++){
            const int col = n0 + warpN + j*8 + (lane & 3) * 2;
            const float b0 = bias ? bias[col]   : 0.0f;
            const float b1 = bias ? bias[col+1] : 0.0f;
            #pragma unroll
            for (int half = 0; half < 2; half++){
                const long row = m0 + warpM + mt*16 + (lane >> 2) + half*8;
                float v0 = acc[mt][j][half*2+0] * alpha + b0;
                float v1 = acc[mt][j][half*2+1] * alpha + b1;
                if (add){
                    v0 += add[row * ldadd + col];
                    v1 += add[row * ldadd + col + 1];
                }
                if (doRelu){ v0 = fmaxf(v0, 0.0f); v1 = fmaxf(v1, 0.0f); }
                const long ci = row * ldc + col;
                if (Ch){
                    *(uint32_t*)(Ch + ci) = pack2h(__float2half_rn(v0), __float2half_rn(v1));
                } else {
                    *(float2*)(Cf + ci) = make_float2(v0, v1);
                }
            }
        }
    }
}

// ---------------- fused flash attention (fp16 single-pass) ----------------
// grid (Ss/128, BH); 256 threads = 8 warps, each warp owns 16 q-rows.
// Q/K viewed as [Ss, 4096] (cols = b*1024 + h*64 + k), head offset z*64, z = b*16+h.
#define FL_LQ 72
#define FL_LV 136
#define FL_QBYTES (128*FL_LQ*2)              // 18432
#define FL_KBYTES (128*FL_LQ*2)              // 18432
#define FL_VBYTES (64*FL_LV*2)               // 17408
#define FL_STAGE (FL_KBYTES + FL_VBYTES)     // 35840
#define FL_SMQ   0
#define FL_SMST  FL_QBYTES                   // 18432
#define FL_SMEM  (FL_SMST + 2*FL_STAGE)      // 90112

__global__ void __launch_bounds__(256,1) flash_kernel(
    const __half* __restrict__ Qq,
    const __half* __restrict__ Kk,
    const __half* __restrict__ Vt,
    const float* __restrict__ mask,
    __half* __restrict__ AV)
{
    extern __shared__ char smc[];
    const uint32_t sbase = smem_u32(smc);
    const int tid = threadIdx.x, lane = tid & 31, wid = tid >> 5;
    const int q0 = blockIdx.x * 128;
    const int z  = blockIdx.y;
    const long hOff = (long)z * 64;

    auto load_q = [&](){
        #pragma unroll
        for (int it = 0; it < 4; it++){
            int idx = it*256 + tid;
            int row = idx >> 3, ch = idx & 7;
            long g = (long)(q0 + row) * 4096 + hOff + ch*8;
            uint32_t so = sbase + FL_SMQ + (uint32_t)(row*FL_LQ*2 + ch*16);
            cpasync16(so, Qq + g);
        }
    };
    auto load_stage = [&](int kt, int buf){
        const int t0 = kt * 128;
        const uint32_t s0 = sbase + FL_SMST + buf*FL_STAGE;
        #pragma unroll
        for (int it = 0; it < 4; it++){
            int idx = it*256 + tid;
            int row = idx >> 3, ch = idx & 7;
            long g = (long)(t0 + row) * 4096 + hOff + ch*8;
            uint32_t so = s0 + (uint32_t)(row*FL_LQ*2 + ch*16);
            cpasync16(so, Kk + g);
        }
        const uint32_t v0 = s0 + FL_KBYTES;
        #pragma unroll
        for (int it = 0; it < 4; it++){
            int idx = it*256 + tid;
            int row = idx >> 4, ch = idx & 15;
            long g = (long)z*64*2048 + (long)row*2048 + t0 + ch*8;
            uint32_t so = v0 + (uint32_t)(row*FL_LV*2 + ch*16);
            cpasync16(so, Vt + g);
        }
    };

    load_q();
    load_stage(0, 0);
    asm volatile("cp.async.commit_group;" ::: "memory");
    load_stage(1, 1);
    asm volatile("cp.async.commit_group;" ::: "memory");
    asm volatile("cp.async.wait_group 1;" ::: "memory");
    __syncthreads();

    const int aRow = lane & 15, aCol = (lane >> 4) * 8;
    const int bRow = (lane >> 4) * 8 + (lane & 7), bCol = ((lane >> 3) & 1) * 8;

    uint32_t qf[4][4];
    #pragma unroll
    for (int kc = 0; kc < 4; kc++){
        uint32_t addr = sbase + FL_SMQ + (uint32_t)(((wid*16 + aRow)*FL_LQ + kc*16 + aCol) * 2);
        ldmx4(qf[kc], addr);
    }

    float O[8][4];
    #pragma unroll
    for (int j = 0; j < 8; j++){ O[j][0]=0; O[j][1]=0; O[j][2]=0; O[j][3]=0; }
    float m0 = -INFINITY, m1 = -INFINITY, l0 = 0.0f, l1 = 0.0f;
    const int rloc = wid*16 + (lane >> 2);

    for (int kt = 0; kt < 16; kt++){
        asm volatile("cp.async.wait_group 1;" ::: "memory");
        __syncthreads();
        const uint32_t sK = sbase + FL_SMST + (kt & 1)*FL_STAGE;
        const uint32_t sV = sK + FL_KBYTES;

        float S[16][4];
        #pragma unroll
        for (int j = 0; j < 16; j++){ S[j][0]=0; S[j][1]=0; S[j][2]=0; S[j][3]=0; }

        #pragma unroll
        for (int kc = 0; kc < 4; kc++){
            #pragma unroll
            for (int g = 0; g < 8; g++){
                uint32_t addr = sK + (uint32_t)(((g*16 + bRow)*FL_LQ + kc*16 + bCol) * 2);
                uint32_t bk[4];
                ldmx4(bk, addr);
                mma16816(S[2*g],   qf[kc], bk+0);
                mma16816(S[2*g+1], qf[kc], bk+2);
            }
        }

        // scale + mask + running max
        const int t0 = kt * 128;
        const long mr0 = (long)(q0 + rloc) * 2048 + t0;
        const long mr1 = mr0 + 8 * 2048;
        float mx0 = -INFINITY, mx1 = -INFINITY;
        #pragma unroll
        for (int j = 0; j < 16; j++){
            int c = j*8 + (lane & 3)*2;
            float2 k0v = *(const float2*)(mask + mr0 + c);
            float2 k1v = *(const float2*)(mask + mr1 + c);
            S[j][0] = S[j][0]*0.125f + k0v.x;
            S[j][1] = S[j][1]*0.125f + k0v.y;
            S[j][2] = S[j][2]*0.125f + k1v.x;
            S[j][3] = S[j][3]*0.125f + k1v.y;
            mx0 = fmaxf(mx0, fmaxf(S[j][0], S[j][1]));
            mx1 = fmaxf(mx1, fmaxf(S[j][2], S[j][3]));
        }
        mx0 = fmaxf(mx0, __shfl_xor_sync(0xFFFFFFFFu, mx0, 1));
        mx0 = fmaxf(mx0, __shfl_xor_sync(0xFFFFFFFFu, mx0, 2));
        mx1 = fmaxf(mx1, __shfl_xor_sync(0xFFFFFFFFu, mx1, 1));
        mx1 = fmaxf(mx1, __shfl_xor_sync(0xFFFFFFFFu, mx1, 2));
        float nm0 = fmaxf(m0, mx0), nm1 = fmaxf(m1, mx1);
        float f0 = (m0 > -INFINITY) ? __expf(m0 - nm0) : 0.0f;
        float f1 = (m1 > -INFINITY) ? __expf(m1 - nm1) : 0.0f;
        m0 = nm0; m1 = nm1;

        float s0 = 0.0f, s1 = 0.0f;
        #pragma unroll
        for (int j = 0; j < 16; j++){
            S[j][0] = __expf(S[j][0] - m0);
            S[j][1] = __expf(S[j][1] - m0);
            S[j][2] = __expf(S[j][2] - m1);
            S[j][3] = __expf(S[j][3] - m1);
            s0 += S[j][0] + S[j][1];
            s1 += S[j][2] + S[j][3];
        }
        s0 += __shfl_xor_sync(0xFFFFFFFFu, s0, 1);
        s0 += __shfl_xor_sync(0xFFFFFFFFu, s0, 2);
        s1 += __shfl_xor_sync(0xFFFFFFFFu, s1, 1);
        s1 += __shfl_xor_sync(0xFFFFFFFFu, s1, 2);
        l0 = l0*f0 + s0;
        l1 = l1*f1 + s1;
        #pragma unroll
        for (int j = 0; j < 8; j++){
            O[j][0]*=f0; O[j][1]*=f0; O[j][2]*=f1; O[j][3]*=f1;
        }

        // O += P @ V   (P rounded to fp16)
        #pragma unroll
        for (int kc = 0; kc < 8; kc++){
            uint32_t ph[4];
            ph[0] = pack2h(__float2half_rn(S[2*kc][0]),   __float2half_rn(S[2*kc][1]));
            ph[1] = pack2h(__float2half_rn(S[2*kc][2]),   __float2half_rn(S[2*kc][3]));
            ph[2] = pack2h(__float2half_rn(S[2*kc+1][0]), __float2half_rn(S[2*kc+1][1]));
            ph[3] = pack2h(__float2half_rn(S[2*kc+1][2]), __float2half_rn(S[2*kc+1][3]));
            #pragma unroll
            for (int g = 0; g < 4; g++){
                uint32_t addr = sV + (uint32_t)(((g*16 + bRow)*FL_LV + kc*16 + bCol) * 2);
                uint32_t vf[4];
                ldmx4(vf, addr);
                mma16816(O[2*g],   ph, vf+0);
                mma16816(O[2*g+1], ph, vf+2);
            }
        }

        __syncthreads();
        if (kt + 2 < 16) load_stage(kt + 2, kt & 1);
        asm volatile("cp.async.commit_group;" ::: "memory");
    }

    // finalize: O /= l, write av (fp16), av viewed as [Ss, 4096]
    const float inv0 = 1.0f / l0, inv1 = 1.0f / l1;
    #pragma unroll
    for (int j = 0; j < 8; j++){
        const int col = j*8 + (lane & 3)*2;
        const long a0 = (long)(q0 + rloc) * 4096 + hOff + col;
        const long a1 = a0 + 8L * 4096;
        *(uint32_t*)(AV + a0) = pack2h(__float2half_rn(O[j][0]*inv0), __float2half_rn(O[j][1]*inv0));
        *(uint32_t*)(AV + a1) = pack2h(__float2half_rn(O[j][2]*inv1), __float2half_rn(O[j][3]*inv1));
    }
}

// ---------------- fp32 -> fp16 ----------------
__global__ void cvt_half_kernel(const float4* __restrict__ in,
                                uint2* __restrict__ out, long n4)
{
    long i = (long)blockIdx.x * 256 + threadIdx.x;
    if (i >= n4) return;
    float4 v = in[i];
    uint2 H;
    H.x = pack2h(__float2half_rn(v.x), __float2half_rn(v.y));
    H.y = pack2h(__float2half_rn(v.z), __float2half_rn(v.w));
    out[i] = H;
}

// ---------------- V transpose (fp16): v[s,b,h,kk] -> vt[z][kk][t] ----------------
__global__ void transpose_v(const __half* __restrict__ v, __half* __restrict__ vt)
{
    __shared__ __half t[64][72];
    const int z  = blockIdx.y;
    const int t0 = blockIdx.x * 64;
    const int b  = z >> 4, h = z & 15;
    const __half* src = v + (size_t)b*1024 + (size_t)h*64;
    for (int it = 0; it < 16; it++){
        int idx = it*256 + threadIdx.x;
        int ti = idx >> 6, kk = idx & 63;
        t[ti][kk] = src[(size_t)(t0 + ti)*4096 + kk];
    }
    __syncthreads();
    size_t obase = (size_t)z * Kh * Ss + t0;
    for (int it = 0; it < 16; it++){
        int idx = it*256 + threadIdx.x;
        int kk = idx >> 6, ti = idx & 63;
        vt[obase + (size_t)kk*Ss + ti] = t[ti][kk];
    }
}

// ---------------- layernorm over D=1024; optional fp16 output ----------------
__global__ void layernorm_kernel(const float* __restrict__ in,
                                 float* __restrict__ out,
                                 __half* __restrict__ oh,
                                 const float* __restrict__ gamma,
                                 const float* __restrict__ beta)
{
    const int row = blockIdx.x;
    const float* x = in + (size_t)row * Dd;
    const int tid = threadIdx.x;

    float v[4];
    float s = 0.0f, s2 = 0.0f;
    #pragma unroll
    for (int i = 0; i < 4; i++){
        v[i] = x[tid + i*256];
        s  += v[i];
        s2 += v[i]*v[i];
    }
    __shared__ float r1[256], r2[256];
    r1[tid] = s; r2[tid] = s2; __syncthreads();
    for (int off = 128; off > 0; off >>= 1){
        if (tid < off){ r1[tid] += r1[tid+off]; r2[tid] += r2[tid+off]; }
        __syncthreads();
    }
    float mean = r1[0] * (1.0f/Dd);
    float var  = r2[0] * (1.0f/Dd) - mean*mean;
    float inv  = rsqrtf(var + EPSL);
    #pragma unroll
    for (int i = 0; i < 4; i++){
        int c = tid + i*256;
        float y = (v[i] - mean) * inv * gamma[c] + beta[c];
        out[(size_t)row*Dd + c] = y;
        if (oh) oh[(size_t)row*Dd + c] = __float2half_rn(y);
    }
}

// ---------------- host side ----------------
static const int SMEM128 = 2 * (10240 + 10240);   // 40960
static const int SMEM64  = 2 * (10240 + 5120);    // 30720

static inline void cvt_half(const float* in, __half* o, long n){
    long n4 = n / 4;
    cvt_half_kernel<<<(unsigned)(n4 / 256), 256>>>((const float4*)in, (uint2*)o, n4);
}

struct GemmArgs {
    const __half *A, *B;
    float* Cf; __half *Ch;
    int M, N, Kd; long lda, ldb, ldc;
    float alpha; const float* add; long ldadd; const float* bias; int relu;
};

template<int BN>
static inline void run_gemm(const GemmArgs& a){
    dim3 grid(a.N / BN, a.M / 128, 1);
    int smem = (BN == 128) ? SMEM128 : SMEM64;
    mma_gemm<BN><<<grid, 256, smem>>>(a.A, a.B, a.Cf, a.Ch,
                                      a.Kd, a.lda, a.ldb, a.ldc,
                                      a.alpha, a.add, a.ldadd, a.bias, a.relu);
}

extern "C" void kernel_launch(void* const* d_in, const int* in_sizes, int n_in,
                              void* d_out, int out_size)
{
    const float* x     = (const float*)d_in[0];
    const float* mask  = (const float*)d_in[1];
    const float* wq    = (const float*)d_in[2];
    const float* wk    = (const float*)d_in[3];
    const float* wv    = (const float*)d_in[4];
    const float* wc    = (const float*)d_in[5];
    const float* w1_w  = (const float*)d_in[6];
    const float* w1_b  = (const float*)d_in[7];
    const float* w2_w  = (const float*)d_in[8];
    const float* w2_b  = (const float*)d_in[9];
    const float* ln1_g = (const float*)d_in[10];
    const float* ln1_b = (const float*)d_in[11];
    const float* ln2_g = (const float*)d_in[12];
    const float* ln2_b = (const float*)d_in[13];
    float* out = (float*)d_out;

    cudaFuncSetAttribute((const void*)mma_gemm<128>, cudaFuncAttributeMaxDynamicSharedMemorySize, SMEM128);
    cudaFuncSetAttribute((const void*)flash_kernel,  cudaFuncAttributeMaxDynamicSharedMemorySize, FL_SMEM);

    __half *xh,*pwq,*pwk,*pwv,*pwc,*pw1,*pw2;
    __half *q,*kk,*vh,*vt,*av,*uh,*h1;
    float *attn,*u,*z;
    cudaGetSymbolAddress((void**)&xh,  g_x);
    cudaGetSymbolAddress((void**)&pwq, g_wq);
    cudaGetSymbolAddress((void**)&pwk, g_wk);
    cudaGetSymbolAddress((void**)&pwv, g_wv);
    cudaGetSymbolAddress((void**)&pwc, g_wc);
    cudaGetSymbolAddress((void**)&pw1, g_w1);
    cudaGetSymbolAddress((void**)&pw2, g_w2);
    cudaGetSymbolAddress((void**)&q,   g_q);
    cudaGetSymbolAddress((void**)&kk,  g_k);
    cudaGetSymbolAddress((void**)&vh,  g_vh);
    cudaGetSymbolAddress((void**)&vt,  g_vt);
    cudaGetSymbolAddress((void**)&av,  g_av);
    cudaGetSymbolAddress((void**)&attn,g_attn);
    cudaGetSymbolAddress((void**)&u,   g_u);
    cudaGetSymbolAddress((void**)&uh,  g_uh);
    cudaGetSymbolAddress((void**)&h1,  g_h1);
    cudaGetSymbolAddress((void**)&z,   g_z);

    // input conversions
    cvt_half(x,   xh,  (long)NTOK*Dd);
    cvt_half(wq,  pwq, (long)Dd*Dd);
    cvt_half(wk,  pwk, (long)Dd*Dd);
    cvt_half(wv,  pwv, (long)Dd*Dd);
    cvt_half(wc,  pwc, (long)Dd*Dd);
    cvt_half(w1_w,pw1, (long)Mf*Dd);
    cvt_half(w2_w,pw2, (long)Mf*Dd);

    GemmArgs a;
    // Q = x @ wq^T
    a = {xh,pwq, nullptr,q, NTOK,Dd,Dd, Dd,Dd,Dd, 1.0f, nullptr,0, nullptr,0};
    run_gemm<128>(a);
    // K
    a = {xh,pwk, nullptr,kk, NTOK,Dd,Dd, Dd,Dd,Dd, 1.0f, nullptr,0, nullptr,0};
    run_gemm<128>(a);
    // V (fp16, then transpose)
    a = {xh,pwv, nullptr,vh, NTOK,Dd,Dd, Dd,Dd,Dd, 1.0f, nullptr,0, nullptr,0};
    run_gemm<128>(a);
    {
        dim3 g(Ss/64, BH);
        transpose_v<<<g, 256>>>(vh, vt);
    }
    // fused attention: av = softmax(Q K^T / 8 + mask) @ V
    {
        dim3 g(Ss/128, BH);
        flash_kernel<<<g, 256, FL_SMEM>>>(q, kk, vt, mask, av);
    }
    // attn = av @ wc^T + x  (fp32)
    a = {av,pwc, attn,nullptr, NTOK,Dd,Dd, Dd,Dd,Dd, 1.0f, x,Dd, nullptr,0};
    run_gemm<128>(a);
    // u = LN1(attn)  (fp32 + fp16)
    layernorm_kernel<<<NTOK, 256>>>(attn, u, uh, ln1_g, ln1_b);
    // h1 = relu(u @ w1^T + b1)
    a = {uh,pw1, nullptr,h1, NTOK,Mf,Dd, Dd,Dd,Mf, 1.0f, nullptr,0, w1_b,1};
    run_gemm<128>(a);
    // z = h1 @ w2^T + b2 + u  (fp32)
    a = {h1,pw2, z,nullptr, NTOK,Dd,Mf, Mf,Mf,Dd, 1.0f, u,Dd, w2_b,0};
    run_gemm<128>(a);
    // out = LN2(z)
    layernorm_kernel<<<NTOK, 256>>>(z, out, nullptr, ln2_g, ln2_b);
}

// round 7
// speedup vs baseline: 10.0350x; 1.0488x over previous
#include <cuda_runtime.h>
#include <cuda_fp16.h>
#include <cstdint>
#include <math.h>

#define Hh   16
#define Kh   64
#define Dd   1024
#define Mf   4096
#define Ss   2048
#define Bb   4
#define NTOK (Ss*Bb)      // 8192
#define BH   (Bb*Hh)      // 64
#define EPSL 1e-5f

// ---------------- scratch buffers (device globals: allocation-free) ----------------
__device__ __half g_x[(size_t)NTOK*Dd];
__device__ __half g_wq[(size_t)Dd*Dd];
__device__ __half g_wk[(size_t)Dd*Dd];
__device__ __half g_wv[(size_t)Dd*Dd];
__device__ __half g_wc[(size_t)Dd*Dd];
__device__ __half g_w1[(size_t)Mf*Dd];
__device__ __half g_w2[(size_t)Mf*Dd];
__device__ __half g_maskh[(size_t)Ss*Ss];
__device__ __half g_q[(size_t)NTOK*Dd];
__device__ __half g_k[(size_t)NTOK*Dd];
__device__ __half g_vh[(size_t)NTOK*Dd];
__device__ __half g_vt[(size_t)BH*Kh*Ss];
__device__ __half g_av[(size_t)NTOK*Dd];
__device__ float  g_attn[(size_t)NTOK*Dd];
__device__ float  g_u[(size_t)NTOK*Dd];
__device__ __half g_uh[(size_t)NTOK*Dd];
__device__ __half g_h1[(size_t)NTOK*Mf];
__device__ float  g_z[(size_t)NTOK*Dd];

// ---------------- helpers ----------------
__device__ __forceinline__ uint32_t smem_u32(const void* p){
    uint32_t a;
    asm("{ .reg .u64 t; cvta.to.shared.u64 t, %1; cvt.u32.u64 %0, t; }" : "=r"(a) : "l"(p));
    return a;
}
__device__ __forceinline__ uint32_t pack2h(__half a, __half b){
    return (uint32_t)__half_as_ushort(a) | ((uint32_t)__half_as_ushort(b) << 16);
}
__device__ __forceinline__ void cpasync16(uint32_t saddr, const void* gaddr){
    asm volatile("cp.async.cg.shared.global [%0], [%1], 16;" :: "r"(saddr), "l"(gaddr) : "memory");
}
__device__ __forceinline__ void ldmx4(uint32_t* r, uint32_t addr){
    asm volatile("ldmatrix.sync.aligned.m8n8.x4.shared.b16 {%0,%1,%2,%3}, [%4];"
                 : "=r"(r[0]), "=r"(r[1]), "=r"(r[2]), "=r"(r[3]) : "r"(addr));
}
__device__ __forceinline__ void mma16816(float* c, const uint32_t* a, const uint32_t* b){
    asm volatile("mma.sync.aligned.m16n8k16.row.col.f32.f16.f16.f32 "
                 "{%0,%1,%2,%3}, {%4,%5,%6,%7}, {%8,%9}, {%0,%1,%2,%3};"
                 : "+f"(c[0]), "+f"(c[1]), "+f"(c[2]), "+f"(c[3])
                 : "r"(a[0]), "r"(a[1]), "r"(a[2]), "r"(a[3]), "r"(b[0]), "r"(b[1]));
}

// ---------------- mma.sync fp16 NT GEMM, 3-stage pipeline ----------------
// C[128 x 128 per CTA] = alpha * A @ B^T (+bias[n]) (+add[m,n]) (+relu)
// A,B fp16, K-contiguous rows. Output fp32 (Cf) or fp16 (Ch).
__global__ void __launch_bounds__(256) mma_gemm(
    const __half* __restrict__ A, const __half* __restrict__ B,
    float* __restrict__ Cf, __half* __restrict__ Ch,
    int Kd, long lda, long ldb, long ldc,
    float alpha, const float* __restrict__ add, long ldadd,
    const float* __restrict__ bias, int doRelu)
{
    constexpr int BN   = 128;
    constexpr int BK   = 32;
    constexpr int LDS  = BK + 8;
    constexpr int WN   = BN / 2;
    constexpr int NT   = WN / 8;
    constexpr int A_BYTES = 128 * LDS * 2;   // 10240
    constexpr int B_BYTES = BN  * LDS * 2;   // 10240
    constexpr int STAGE   = A_BYTES + B_BYTES;

    extern __shared__ char smc[];
    const uint32_t sbase = smem_u32(smc);

    const int tid  = threadIdx.x;
    const int lane = tid & 31;
    const int wid  = tid >> 5;
    const int warpM = (wid & 3) * 32;
    const int warpN = (wid >> 2) * WN;

    const int  m0   = blockIdx.y * 128;
    const int  n0   = blockIdx.x * BN;
    const int  KT   = Kd / BK;

    const int la_row = tid >> 2, la_ch = tid & 3;
    auto load_stage = [&](int kt, int buf){
        const int k0 = kt * BK;
        const uint32_t s0 = sbase + buf * STAGE;
        #pragma unroll
        for (int it = 0; it < 2; it++){
            int row = la_row + it * 64;
            long g = (long)(m0 + row) * lda + k0 + la_ch * 8;
            uint32_t so = (uint32_t)(row * (LDS * 2) + la_ch * 16);
            cpasync16(s0 + so, A + g);
        }
        #pragma unroll
        for (int it = 0; it < 2; it++){
            int row = la_row + it * 64;
            long g = (long)(n0 + row) * ldb + k0 + la_ch * 8;
            uint32_t so = (uint32_t)(row * (LDS * 2) + la_ch * 16);
            cpasync16(s0 + A_BYTES + so, B + g);
        }
    };

    load_stage(0, 0);
    asm volatile("cp.async.commit_group;" ::: "memory");
    load_stage(1, 1);
    asm volatile("cp.async.commit_group;" ::: "memory");

    float acc[2][NT][4];
    #pragma unroll
    for (int i = 0; i < 2; i++)
        #pragma unroll
        for (int j = 0; j < NT; j++)
            #pragma unroll
            for (int e = 0; e < 4; e++) acc[i][j][e] = 0.0f;

    const int aRow = (lane & 15), aColHalf = (lane >> 4) * 8;
    const int bRow = (lane >> 4) * 8 + (lane & 7), bColHalf = ((lane >> 3) & 1) * 8;

    int buf = 0;
    for (int kt = 0; kt < KT; kt++){
        asm volatile("cp.async.wait_group 1;" ::: "memory");
        __syncthreads();
        const uint32_t sA0 = sbase + buf * STAGE;
        const uint32_t sB0 = sA0 + A_BYTES;

        #pragma unroll
        for (int ks = 0; ks < 2; ks++){
            const int k16 = ks * 16;
            uint32_t af[2][4];
            #pragma unroll
            for (int mt = 0; mt < 2; mt++){
                uint32_t addr = sA0 + (uint32_t)(((warpM + mt*16 + aRow) * LDS + k16 + aColHalf) * 2);
                ldmx4(af[mt], addr);
            }
            uint32_t bf[NT][2];
            #pragma unroll
            for (int g = 0; g < NT/2; g++){
                uint32_t addr = sB0 + (uint32_t)(((warpN + g*16 + bRow) * LDS + k16 + bColHalf) * 2);
                uint32_t r[4];
                ldmx4(r, addr);
                bf[2*g][0] = r[0]; bf[2*g][1] = r[1];
                bf[2*g+1][0] = r[2]; bf[2*g+1][1] = r[3];
            }
            #pragma unroll
            for (int mt = 0; mt < 2; mt++)
                #pragma unroll
                for (int j = 0; j < NT; j++)
                    mma16816(acc[mt][j], af[mt], bf[j]);
        }
        // issue next stage load (3-buffer: WAR distance 2, protected by top sync)
        if (kt + 2 < KT){
            int nbuf = buf + 2; if (nbuf >= 3) nbuf -= 3;
            load_stage(kt + 2, nbuf);
        }
        asm volatile("cp.async.commit_group;" ::: "memory");
        if (++buf == 3) buf = 0;
    }

    #pragma unroll
    for (int mt = 0; mt < 2; mt++){
        #pragma unroll
        for (int j = 0; j < NT; j++){
            const int col = n0 + warpN + j*8 + (lane & 3) * 2;
            const float b0 = bias ? bias[col]   : 0.0f;
            const float b1 = bias ? bias[col+1] : 0.0f;
            #pragma unroll
            for (int half = 0; half < 2; half++){
                const long row = m0 + warpM + mt*16 + (lane >> 2) + half*8;
                float v0 = acc[mt][j][half*2+0] * alpha + b0;
                float v1 = acc[mt][j][half*2+1] * alpha + b1;
                if (add){
                    v0 += add[row * ldadd + col];
                    v1 += add[row * ldadd + col + 1];
                }
                if (doRelu){ v0 = fmaxf(v0, 0.0f); v1 = fmaxf(v1, 0.0f); }
                const long ci = row * ldc + col;
                if (Ch){
                    *(uint32_t*)(Ch + ci) = pack2h(__float2half_rn(v0), __float2half_rn(v1));
                } else {
                    *(float2*)(Cf + ci) = make_float2(v0, v1);
                }
            }
        }
    }
}

// ---------------- fused flash attention (fp16, 3-stage) ----------------
// grid (Ss/128, BH); 256 threads = 8 warps, each warp owns 16 q-rows.
#define FL_LQ 72
#define FL_LV 136
#define FL_QBYTES (128*FL_LQ*2)              // 18432
#define FL_KBYTES (128*FL_LQ*2)              // 18432
#define FL_VBYTES (64*FL_LV*2)               // 17408
#define FL_STAGE (FL_KBYTES + FL_VBYTES)     // 35840
#define FL_SMQ   0
#define FL_SMST  FL_QBYTES                   // 18432
#define FL_SMEM  (FL_SMST + 3*FL_STAGE)      // 125952

__global__ void __launch_bounds__(256,1) flash_kernel(
    const __half* __restrict__ Qq,
    const __half* __restrict__ Kk,
    const __half* __restrict__ Vt,
    const __half* __restrict__ maskh,
    __half* __restrict__ AV)
{
    extern __shared__ char smc[];
    const uint32_t sbase = smem_u32(smc);
    const int tid = threadIdx.x, lane = tid & 31, wid = tid >> 5;
    const int q0 = blockIdx.x * 128;
    const int z  = blockIdx.y;
    const long hOff = (long)z * 64;

    auto load_q = [&](){
        #pragma unroll
        for (int it = 0; it < 4; it++){
            int idx = it*256 + tid;
            int row = idx >> 3, ch = idx & 7;
            long g = (long)(q0 + row) * 4096 + hOff + ch*8;
            uint32_t so = sbase + FL_SMQ + (uint32_t)(row*FL_LQ*2 + ch*16);
            cpasync16(so, Qq + g);
        }
    };
    auto load_stage = [&](int kt, int buf){
        const int t0 = kt * 128;
        const uint32_t s0 = sbase + FL_SMST + buf*FL_STAGE;
        #pragma unroll
        for (int it = 0; it < 4; it++){
            int idx = it*256 + tid;
            int row = idx >> 3, ch = idx & 7;
            long g = (long)(t0 + row) * 4096 + hOff + ch*8;
            uint32_t so = s0 + (uint32_t)(row*FL_LQ*2 + ch*16);
            cpasync16(so, Kk + g);
        }
        const uint32_t v0 = s0 + FL_KBYTES;
        #pragma unroll
        for (int it = 0; it < 4; it++){
            int idx = it*256 + tid;
            int row = idx >> 4, ch = idx & 15;
            long g = (long)z*64*2048 + (long)row*2048 + t0 + ch*8;
            uint32_t so = v0 + (uint32_t)(row*FL_LV*2 + ch*16);
            cpasync16(so, Vt + g);
        }
    };

    load_q();
    load_stage(0, 0);
    asm volatile("cp.async.commit_group;" ::: "memory");
    load_stage(1, 1);
    asm volatile("cp.async.commit_group;" ::: "memory");
    asm volatile("cp.async.wait_group 1;" ::: "memory");
    __syncthreads();

    const int aRow = lane & 15, aCol = (lane >> 4) * 8;
    const int bRow = (lane >> 4) * 8 + (lane & 7), bCol = ((lane >> 3) & 1) * 8;

    uint32_t qf[4][4];
    #pragma unroll
    for (int kc = 0; kc < 4; kc++){
        uint32_t addr = sbase + FL_SMQ + (uint32_t)(((wid*16 + aRow)*FL_LQ + kc*16 + aCol) * 2);
        ldmx4(qf[kc], addr);
    }

    float O[8][4];
    #pragma unroll
    for (int j = 0; j < 8; j++){ O[j][0]=0; O[j][1]=0; O[j][2]=0; O[j][3]=0; }
    float m0 = -INFINITY, m1 = -INFINITY, l0 = 0.0f, l1 = 0.0f;
    const int rloc = wid*16 + (lane >> 2);

    int buf = 0;
    for (int kt = 0; kt < 16; kt++){
        asm volatile("cp.async.wait_group 1;" ::: "memory");
        __syncthreads();
        const uint32_t sK = sbase + FL_SMST + buf*FL_STAGE;
        const uint32_t sV = sK + FL_KBYTES;

        float S[16][4];
        #pragma unroll
        for (int j = 0; j < 16; j++){ S[j][0]=0; S[j][1]=0; S[j][2]=0; S[j][3]=0; }

        #pragma unroll
        for (int kc = 0; kc < 4; kc++){
            #pragma unroll
            for (int g = 0; g < 8; g++){
                uint32_t addr = sK + (uint32_t)(((g*16 + bRow)*FL_LQ + kc*16 + bCol) * 2);
                uint32_t bk[4];
                ldmx4(bk, addr);
                mma16816(S[2*g],   qf[kc], bk+0);
                mma16816(S[2*g+1], qf[kc], bk+2);
            }
        }

        // scale + mask(fp16) + running max
        const int t0 = kt * 128;
        const long mr0 = (long)(q0 + rloc) * 2048 + t0;
        const long mr1 = mr0 + 8 * 2048;
        float mx0 = -INFINITY, mx1 = -INFINITY;
        #pragma unroll
        for (int j = 0; j < 16; j++){
            int c = j*8 + (lane & 3)*2;
            float2 k0v = __half22float2(*(const __half2*)(maskh + mr0 + c));
            float2 k1v = __half22float2(*(const __half2*)(maskh + mr1 + c));
            S[j][0] = S[j][0]*0.125f + k0v.x;
            S[j][1] = S[j][1]*0.125f + k0v.y;
            S[j][2] = S[j][2]*0.125f + k1v.x;
            S[j][3] = S[j][3]*0.125f + k1v.y;
            mx0 = fmaxf(mx0, fmaxf(S[j][0], S[j][1]));
            mx1 = fmaxf(mx1, fmaxf(S[j][2], S[j][3]));
        }
        mx0 = fmaxf(mx0, __shfl_xor_sync(0xFFFFFFFFu, mx0, 1));
        mx0 = fmaxf(mx0, __shfl_xor_sync(0xFFFFFFFFu, mx0, 2));
        mx1 = fmaxf(mx1, __shfl_xor_sync(0xFFFFFFFFu, mx1, 1));
        mx1 = fmaxf(mx1, __shfl_xor_sync(0xFFFFFFFFu, mx1, 2));
        float nm0 = fmaxf(m0, mx0), nm1 = fmaxf(m1, mx1);
        float f0 = (m0 > -INFINITY) ? __expf(m0 - nm0) : 0.0f;
        float f1 = (m1 > -INFINITY) ? __expf(m1 - nm1) : 0.0f;
        m0 = nm0; m1 = nm1;

        float s0 = 0.0f, s1 = 0.0f;
        #pragma unroll
        for (int j = 0; j < 16; j++){
            S[j][0] = __expf(S[j][0] - m0);
            S[j][1] = __expf(S[j][1] - m0);
            S[j][2] = __expf(S[j][2] - m1);
            S[j][3] = __expf(S[j][3] - m1);
            s0 += S[j][0] + S[j][1];
            s1 += S[j][2] + S[j][3];
        }
        s0 += __shfl_xor_sync(0xFFFFFFFFu, s0, 1);
        s0 += __shfl_xor_sync(0xFFFFFFFFu, s0, 2);
        s1 += __shfl_xor_sync(0xFFFFFFFFu, s1, 1);
        s1 += __shfl_xor_sync(0xFFFFFFFFu, s1, 2);
        l0 = l0*f0 + s0;
        l1 = l1*f1 + s1;
        #pragma unroll
        for (int j = 0; j < 8; j++){
            O[j][0]*=f0; O[j][1]*=f0; O[j][2]*=f1; O[j][3]*=f1;
        }

        // O += P @ V   (P rounded to fp16)
        #pragma unroll
        for (int kc = 0; kc < 8; kc++){
            uint32_t ph[4];
            ph[0] = pack2h(__float2half_rn(S[2*kc][0]),   __float2half_rn(S[2*kc][1]));
            ph[1] = pack2h(__float2half_rn(S[2*kc][2]),   __float2half_rn(S[2*kc][3]));
            ph[2] = pack2h(__float2half_rn(S[2*kc+1][0]), __float2half_rn(S[2*kc+1][1]));
            ph[3] = pack2h(__float2half_rn(S[2*kc+1][2]), __float2half_rn(S[2*kc+1][3]));
            #pragma unroll
            for (int g = 0; g < 4; g++){
                uint32_t addr = sV + (uint32_t)(((g*16 + bRow)*FL_LV + kc*16 + bCol) * 2);
                uint32_t vf[4];
                ldmx4(vf, addr);
                mma16816(O[2*g],   ph, vf+0);
                mma16816(O[2*g+1], ph, vf+2);
            }
        }

        if (kt + 2 < 16){
            int nbuf = buf + 2; if (nbuf >= 3) nbuf -= 3;
            load_stage(kt + 2, nbuf);
        }
        asm volatile("cp.async.commit_group;" ::: "memory");
        if (++buf == 3) buf = 0;
    }

    // finalize: O /= l, write av (fp16), av viewed as [Ss, 4096]
    const float inv0 = 1.0f / l0, inv1 = 1.0f / l1;
    #pragma unroll
    for (int j = 0; j < 8; j++){
        const int col = j*8 + (lane & 3)*2;
        const long a0 = (long)(q0 + rloc) * 4096 + hOff + col;
        const long a1 = a0 + 8L * 4096;
        *(uint32_t*)(AV + a0) = pack2h(__float2half_rn(O[j][0]*inv0), __float2half_rn(O[j][1]*inv0));
        *(uint32_t*)(AV + a1) = pack2h(__float2half_rn(O[j][2]*inv1), __float2half_rn(O[j][3]*inv1));
    }
}

// ---------------- fused fp32 -> fp16 conversion (all segments, one launch) ----------------
struct CvtSegs {
    const float4* in[8];
    uint2*        out[8];
    long          start[9];   // cumulative n4 offsets
};
__global__ void cvt_multi(CvtSegs s)
{
    long i = (long)blockIdx.x * 256 + threadIdx.x;
    if (i >= s.start[8]) return;
    int seg = 0;
    #pragma unroll
    for (int k = 1; k < 8; k++) if (i >= s.start[k]) seg = k;
    long j = i - s.start[seg];
    float4 v = s.in[seg][j];
    uint2 H;
    H.x = pack2h(__float2half_rn(v.x), __float2half_rn(v.y));
    H.y = pack2h(__float2half_rn(v.z), __float2half_rn(v.w));
    s.out[seg][j] = H;
}

// ---------------- V transpose (fp16): v[s,b,h,kk] -> vt[z][kk][t] ----------------
__global__ void transpose_v(const __half* __restrict__ v, __half* __restrict__ vt)
{
    __shared__ __half t[64][72];
    const int z  = blockIdx.y;
    const int t0 = blockIdx.x * 64;
    const int b  = z >> 4, h = z & 15;
    const __half* src = v + (size_t)b*1024 + (size_t)h*64;
    for (int it = 0; it < 16; it++){
        int idx = it*256 + threadIdx.x;
        int ti = idx >> 6, kk = idx & 63;
        t[ti][kk] = src[(size_t)(t0 + ti)*4096 + kk];
    }
    __syncthreads();
    size_t obase = (size_t)z * Kh * Ss + t0;
    for (int it = 0; it < 16; it++){
        int idx = it*256 + threadIdx.x;
        int kk = idx >> 6, ti = idx & 63;
        vt[obase + (size_t)kk*Ss + ti] = t[ti][kk];
    }
}

// ---------------- layernorm over D=1024; optional fp16 output ----------------
__global__ void layernorm_kernel(const float* __restrict__ in,
                                 float* __restrict__ out,
                                 __half* __restrict__ oh,
                                 const float* __restrict__ gamma,
                                 const float* __restrict__ beta)
{
    const int row = blockIdx.x;
    const float* x = in + (size_t)row * Dd;
    const int tid = threadIdx.x;

    float v[4];
    float s = 0.0f, s2 = 0.0f;
    #pragma unroll
    for (int i = 0; i < 4; i++){
        v[i] = x[tid + i*256];
        s  += v[i];
        s2 += v[i]*v[i];
    }
    __shared__ float r1[256], r2[256];
    r1[tid] = s; r2[tid] = s2; __syncthreads();
    for (int off = 128; off > 0; off >>= 1){
        if (tid < off){ r1[tid] += r1[tid+off]; r2[tid] += r2[tid+off]; }
        __syncthreads();
    }
    float mean = r1[0] * (1.0f/Dd);
    float var  = r2[0] * (1.0f/Dd) - mean*mean;
    float inv  = rsqrtf(var + EPSL);
    #pragma unroll
    for (int i = 0; i < 4; i++){
        int c = tid + i*256;
        float y = (v[i] - mean) * inv * gamma[c] + beta[c];
        out[(size_t)row*Dd + c] = y;
        if (oh) oh[(size_t)row*Dd + c] = __float2half_rn(y);
    }
}

// ---------------- host side ----------------
static const int SMEM_GEMM = 3 * 20480;   // 61440

struct GemmArgs {
    const __half *A, *B;
    float* Cf; __half *Ch;
    int M, N, Kd; long lda, ldb, ldc;
    float alpha; const float* add; long ldadd; const float* bias; int relu;
};

static inline void run_gemm(const GemmArgs& a){
    dim3 grid(a.N / 128, a.M / 128, 1);
    mma_gemm<<<grid, 256, SMEM_GEMM>>>(a.A, a.B, a.Cf, a.Ch,
                                       a.Kd, a.lda, a.ldb, a.ldc,
                                       a.alpha, a.add, a.ldadd, a.bias, a.relu);
}

extern "C" void kernel_launch(void* const* d_in, const int* in_sizes, int n_in,
                              void* d_out, int out_size)
{
    const float* x     = (const float*)d_in[0];
    const float* mask  = (const float*)d_in[1];
    const float* wq    = (const float*)d_in[2];
    const float* wk    = (const float*)d_in[3];
    const float* wv    = (const float*)d_in[4];
    const float* wc    = (const float*)d_in[5];
    const float* w1_w  = (const float*)d_in[6];
    const float* w1_b  = (const float*)d_in[7];
    const float* w2_w  = (const float*)d_in[8];
    const float* w2_b  = (const float*)d_in[9];
    const float* ln1_g = (const float*)d_in[10];
    const float* ln1_b = (const float*)d_in[11];
    const float* ln2_g = (const float*)d_in[12];
    const float* ln2_b = (const float*)d_in[13];
    float* out = (float*)d_out;

    cudaFuncSetAttribute((const void*)mma_gemm,     cudaFuncAttributeMaxDynamicSharedMemorySize, SMEM_GEMM);
    cudaFuncSetAttribute((const void*)flash_kernel, cudaFuncAttributeMaxDynamicSharedMemorySize, FL_SMEM);

    __half *xh,*pwq,*pwk,*pwv,*pwc,*pw1,*pw2,*pmask;
    __half *q,*kk,*vh,*vt,*av,*uh,*h1;
    float *attn,*u,*z;
    cudaGetSymbolAddress((void**)&xh,   g_x);
    cudaGetSymbolAddress((void**)&pwq,  g_wq);
    cudaGetSymbolAddress((void**)&pwk,  g_wk);
    cudaGetSymbolAddress((void**)&pwv,  g_wv);
    cudaGetSymbolAddress((void**)&pwc,  g_wc);
    cudaGetSymbolAddress((void**)&pw1,  g_w1);
    cudaGetSymbolAddress((void**)&pw2,  g_w2);
    cudaGetSymbolAddress((void**)&pmask,g_maskh);
    cudaGetSymbolAddress((void**)&q,    g_q);
    cudaGetSymbolAddress((void**)&kk,   g_k);
    cudaGetSymbolAddress((void**)&vh,   g_vh);
    cudaGetSymbolAddress((void**)&vt,   g_vt);
    cudaGetSymbolAddress((void**)&av,   g_av);
    cudaGetSymbolAddress((void**)&attn, g_attn);
    cudaGetSymbolAddress((void**)&u,    g_u);
    cudaGetSymbolAddress((void**)&uh,   g_uh);
    cudaGetSymbolAddress((void**)&h1,   g_h1);
    cudaGetSymbolAddress((void**)&z,    g_z);

    // single fused conversion launch: x, 6 weights, mask
    {
        CvtSegs s;
        const float* srcs[8] = {x, wq, wk, wv, wc, w1_w, w2_w, mask};
        __half*      dsts[8] = {xh, pwq, pwk, pwv, pwc, pw1, pw2, pmask};
        long lens[8] = {(long)NTOK*Dd, (long)Dd*Dd, (long)Dd*Dd, (long)Dd*Dd,
                        (long)Dd*Dd, (long)Mf*Dd, (long)Mf*Dd, (long)Ss*Ss};
        long acc = 0;
        for (int i = 0; i < 8; i++){
            s.in[i]  = (const float4*)srcs[i];
            s.out[i] = (uint2*)dsts[i];
            s.start[i] = acc;
            acc += lens[i] / 4;
        }
        s.start[8] = acc;
        cvt_multi<<<(unsigned)((acc + 255) / 256), 256>>>(s);
    }

    GemmArgs a;
    // Q = x @ wq^T
    a = {xh,pwq, nullptr,q, NTOK,Dd,Dd, Dd,Dd,Dd, 1.0f, nullptr,0, nullptr,0};
    run_gemm(a);
    // K
    a = {xh,pwk, nullptr,kk, NTOK,Dd,Dd, Dd,Dd,Dd, 1.0f, nullptr,0, nullptr,0};
    run_gemm(a);
    // V (fp16, then transpose)
    a = {xh,pwv, nullptr,vh, NTOK,Dd,Dd, Dd,Dd,Dd, 1.0f, nullptr,0, nullptr,0};
    run_gemm(a);
    {
        dim3 g(Ss/64, BH);
        transpose_v<<<g, 256>>>(vh, vt);
    }
    // fused attention: av = softmax(Q K^T / 8 + mask) @ V
    {
        dim3 g(Ss/128, BH);
        flash_kernel<<<g, 256, FL_SMEM>>>(q, kk, vt, pmask, av);
    }
    // attn = av @ wc^T + x  (fp32)
    a = {av,pwc, attn,nullptr, NTOK,Dd,Dd, Dd,Dd,Dd, 1.0f, x,Dd, nullptr,0};
    run_gemm(a);
    // u = LN1(attn)  (fp32 + fp16)
    layernorm_kernel<<<NTOK, 256>>>(attn, u, uh, ln1_g, ln1_b);
    // h1 = relu(u @ w1^T + b1)
    a = {uh,pw1, nullptr,h1, NTOK,Mf,Dd, Dd,Dd,Mf, 1.0f, nullptr,0, w1_b,1};
    run_gemm(a);
    // z = h1 @ w2^T + b2 + u  (fp32)
    a = {h1,pw2, z,nullptr, NTOK,Dd,Mf, Mf,Mf,Dd, 1.0f, u,Dd, w2_b,0};
    run_gemm(a);
    // out = LN2(z)
    layernorm_kernel<<<NTOK, 256>>>(z, out, nullptr, ln2_g, ln2_b);
}

// round 8
// speedup vs baseline: 10.5975x; 1.0561x over previous
#include <cuda_runtime.h>
#include <cuda_fp16.h>
#include <cstdint>
#include <math.h>

#define Hh   16
#define Kh   64
#define Dd   1024
#define Mf   4096
#define Ss   2048
#define Bb   4
#define NTOK (Ss*Bb)      // 8192
#define BH   (Bb*Hh)      // 64
#define EPSL 1e-5f

// ---------------- scratch buffers (device globals: allocation-free) ----------------
__device__ __half g_x[(size_t)NTOK*Dd];
__device__ __half g_wq[(size_t)Dd*Dd];
__device__ __half g_wk[(size_t)Dd*Dd];
__device__ __half g_wv[(size_t)Dd*Dd];
__device__ __half g_wc[(size_t)Dd*Dd];
__device__ __half g_w1[(size_t)Mf*Dd];
__device__ __half g_w2[(size_t)Mf*Dd];
__device__ __half g_maskh[(size_t)Ss*Ss];
__device__ __half g_q[(size_t)NTOK*Dd];
__device__ __half g_k[(size_t)NTOK*Dd];
__device__ __half g_vh[(size_t)NTOK*Dd];
__device__ __half g_vt[(size_t)BH*Kh*Ss];
__device__ __half g_av[(size_t)NTOK*Dd];
__device__ float  g_attn[(size_t)NTOK*Dd];
__device__ float  g_u[(size_t)NTOK*Dd];
__device__ __half g_uh[(size_t)NTOK*Dd];
__device__ __half g_h1[(size_t)NTOK*Mf];
__device__ float  g_z[(size_t)NTOK*Dd];

// ---------------- helpers ----------------
__device__ __forceinline__ uint32_t smem_u32(const void* p){
    uint32_t a;
    asm("{ .reg .u64 t; cvta.to.shared.u64 t, %1; cvt.u32.u64 %0, t; }" : "=r"(a) : "l"(p));
    return a;
}
__device__ __forceinline__ uint32_t pack2h(__half a, __half b){
    return (uint32_t)__half_as_ushort(a) | ((uint32_t)__half_as_ushort(b) << 16);
}
__device__ __forceinline__ void cpasync16(uint32_t saddr, const void* gaddr){
    asm volatile("cp.async.cg.shared.global [%0], [%1], 16;" :: "r"(saddr), "l"(gaddr) : "memory");
}
__device__ __forceinline__ void ldmx4(uint32_t* r, uint32_t addr){
    asm volatile("ldmatrix.sync.aligned.m8n8.x4.shared.b16 {%0,%1,%2,%3}, [%4];"
                 : "=r"(r[0]), "=r"(r[1]), "=r"(r[2]), "=r"(r[3]) : "r"(addr));
}
__device__ __forceinline__ void mma16816(float* c, const uint32_t* a, const uint32_t* b){
    asm volatile("mma.sync.aligned.m16n8k16.row.col.f32.f16.f16.f32 "
                 "{%0,%1,%2,%3}, {%4,%5,%6,%7}, {%8,%9}, {%0,%1,%2,%3};"
                 : "+f"(c[0]), "+f"(c[1]), "+f"(c[2]), "+f"(c[3])
                 : "r"(a[0]), "r"(a[1]), "r"(a[2]), "r"(a[3]), "r"(b[0]), "r"(b[1]));
}

// ---------------- mma.sync fp16 NT GEMM, BK=64, 3-stage pipeline ----------------
// C[128 x 128 per CTA] = alpha * A @ B^T (+bias[n]) (+add[m,n]) (+relu)
// A,B fp16, K-contiguous rows (Kd % 64 == 0, Kd >= 192). Output fp32 (Cf) or fp16 (Ch).
__global__ void __launch_bounds__(256) mma_gemm(
    const __half* __restrict__ A, const __half* __restrict__ B,
    float* __restrict__ Cf, __half* __restrict__ Ch,
    int Kd, long lda, long ldb, long ldc,
    float alpha, const float* __restrict__ add, long ldadd,
    const float* __restrict__ bias, int doRelu)
{
    constexpr int BN   = 128;
    constexpr int BK   = 64;
    constexpr int LDS  = BK + 8;             // 72 halves = 144 B/row (conflict-free perm mod 128B)
    constexpr int WN   = BN / 2;
    constexpr int NT   = WN / 8;             // 8
    constexpr int A_BYTES = 128 * LDS * 2;   // 18432
    constexpr int B_BYTES = BN  * LDS * 2;   // 18432
    constexpr int STAGE   = A_BYTES + B_BYTES;  // 36864

    extern __shared__ char smc[];
    const uint32_t sbase = smem_u32(smc);

    const int tid  = threadIdx.x;
    const int lane = tid & 31;
    const int wid  = tid >> 5;
    const int warpM = (wid & 3) * 32;
    const int warpN = (wid >> 2) * WN;

    const int  m0   = blockIdx.y * 128;
    const int  n0   = blockIdx.x * BN;
    const int  KT   = Kd / BK;

    const int la_row = tid >> 3, la_ch = tid & 7;   // 32 rows x 8 chunks per pass
    auto load_stage = [&](int kt, int buf){
        const int k0 = kt * BK;
        const uint32_t s0 = sbase + buf * STAGE;
        #pragma unroll
        for (int it = 0; it < 4; it++){
            int row = la_row + it * 32;
            long g = (long)(m0 + row) * lda + k0 + la_ch * 8;
            uint32_t so = (uint32_t)(row * (LDS * 2) + la_ch * 16);
            cpasync16(s0 + so, A + g);
        }
        #pragma unroll
        for (int it = 0; it < 4; it++){
            int row = la_row + it * 32;
            long g = (long)(n0 + row) * ldb + k0 + la_ch * 8;
            uint32_t so = (uint32_t)(row * (LDS * 2) + la_ch * 16);
            cpasync16(s0 + A_BYTES + so, B + g);
        }
    };

    load_stage(0, 0);
    asm volatile("cp.async.commit_group;" ::: "memory");
    load_stage(1, 1);
    asm volatile("cp.async.commit_group;" ::: "memory");

    float acc[2][NT][4];
    #pragma unroll
    for (int i = 0; i < 2; i++)
        #pragma unroll
        for (int j = 0; j < NT; j++)
            #pragma unroll
            for (int e = 0; e < 4; e++) acc[i][j][e] = 0.0f;

    const int aRow = (lane & 15), aColHalf = (lane >> 4) * 8;
    const int bRow = (lane >> 4) * 8 + (lane & 7), bColHalf = ((lane >> 3) & 1) * 8;

    int buf = 0;
    for (int kt = 0; kt < KT; kt++){
        asm volatile("cp.async.wait_group 1;" ::: "memory");
        __syncthreads();
        const uint32_t sA0 = sbase + buf * STAGE;
        const uint32_t sB0 = sA0 + A_BYTES;

        #pragma unroll
        for (int ks = 0; ks < 4; ks++){
            const int k16 = ks * 16;
            uint32_t af[2][4];
            #pragma unroll
            for (int mt = 0; mt < 2; mt++){
                uint32_t addr = sA0 + (uint32_t)(((warpM + mt*16 + aRow) * LDS + k16 + aColHalf) * 2);
                ldmx4(af[mt], addr);
            }
            uint32_t bf[NT][2];
            #pragma unroll
            for (int g = 0; g < NT/2; g++){
                uint32_t addr = sB0 + (uint32_t)(((warpN + g*16 + bRow) * LDS + k16 + bColHalf) * 2);
                uint32_t r[4];
                ldmx4(r, addr);
                bf[2*g][0] = r[0]; bf[2*g][1] = r[1];
                bf[2*g+1][0] = r[2]; bf[2*g+1][1] = r[3];
            }
            #pragma unroll
            for (int mt = 0; mt < 2; mt++)
                #pragma unroll
                for (int j = 0; j < NT; j++)
                    mma16816(acc[mt][j], af[mt], bf[j]);
        }
        // issue next stage load (3-buffer: WAR distance 2, protected by top sync)
        if (kt + 2 < KT){
            int nbuf = buf + 2; if (nbuf >= 3) nbuf -= 3;
            load_stage(kt + 2, nbuf);
        }
        asm volatile("cp.async.commit_group;" ::: "memory");
        if (++buf == 3) buf = 0;
    }

    #pragma unroll
    for (int mt = 0; mt < 2; mt++){
        #pragma unroll
        for (int j = 0; j < NT; j++){
            const int col = n0 + warpN + j*8 + (lane & 3) * 2;
            const float b0 = bias ? bias[col]   : 0.0f;
            const float b1 = bias ? bias[col+1] : 0.0f;
            #pragma unroll
            for (int half = 0; half < 2; half++){
                const long row = m0 + warpM + mt*16 + (lane >> 2) + half*8;
                float v0 = acc[mt][j][half*2+0] * alpha + b0;
                float v1 = acc[mt][j][half*2+1] * alpha + b1;
                if (add){
                    v0 += add[row * ldadd + col];
                    v1 += add[row * ldadd + col + 1];
                }
                if (doRelu){ v0 = fmaxf(v0, 0.0f); v1 = fmaxf(v1, 0.0f); }
                const long ci = row * ldc + col;
                if (Ch){
                    *(uint32_t*)(Ch + ci) = pack2h(__float2half_rn(v0), __float2half_rn(v1));
                } else {
                    *(float2*)(Cf + ci) = make_float2(v0, v1);
                }
            }
        }
    }
}

// ---------------- fused flash attention (fp16, 3-stage) ----------------
// grid (Ss/128, BH); 256 threads = 8 warps, each warp owns 16 q-rows.
#define FL_LQ 72
#define FL_LV 136
#define FL_QBYTES (128*FL_LQ*2)              // 18432
#define FL_KBYTES (128*FL_LQ*2)              // 18432
#define FL_VBYTES (64*FL_LV*2)               // 17408
#define FL_STAGE (FL_KBYTES + FL_VBYTES)     // 35840
#define FL_SMQ   0
#define FL_SMST  FL_QBYTES                   // 18432
#define FL_SMEM  (FL_SMST + 3*FL_STAGE)      // 125952

__global__ void __launch_bounds__(256,1) flash_kernel(
    const __half* __restrict__ Qq,
    const __half* __restrict__ Kk,
    const __half* __restrict__ Vt,
    const __half* __restrict__ maskh,
    __half* __restrict__ AV)
{
    extern __shared__ char smc[];
    const uint32_t sbase = smem_u32(smc);
    const int tid = threadIdx.x, lane = tid & 31, wid = tid >> 5;
    const int q0 = blockIdx.x * 128;
    const int z  = blockIdx.y;
    const long hOff = (long)z * 64;

    auto load_q = [&](){
        #pragma unroll
        for (int it = 0; it < 4; it++){
            int idx = it*256 + tid;
            int row = idx >> 3, ch = idx & 7;
            long g = (long)(q0 + row) * 4096 + hOff + ch*8;
            uint32_t so = sbase + FL_SMQ + (uint32_t)(row*FL_LQ*2 + ch*16);
            cpasync16(so, Qq + g);
        }
    };
    auto load_stage = [&](int kt, int buf){
        const int t0 = kt * 128;
        const uint32_t s0 = sbase + FL_SMST + buf*FL_STAGE;
        #pragma unroll
        for (int it = 0; it < 4; it++){
            int idx = it*256 + tid;
            int row = idx >> 3, ch = idx & 7;
            long g = (long)(t0 + row) * 4096 + hOff + ch*8;
            uint32_t so = s0 + (uint32_t)(row*FL_LQ*2 + ch*16);
            cpasync16(so, Kk + g);
        }
        const uint32_t v0 = s0 + FL_KBYTES;
        #pragma unroll
        for (int it = 0; it < 4; it++){
            int idx = it*256 + tid;
            int row = idx >> 4, ch = idx & 15;
            long g = (long)z*64*2048 + (long)row*2048 + t0 + ch*8;
            uint32_t so = v0 + (uint32_t)(row*FL_LV*2 + ch*16);
            cpasync16(so, Vt + g);
        }
    };

    load_q();
    load_stage(0, 0);
    asm volatile("cp.async.commit_group;" ::: "memory");
    load_stage(1, 1);
    asm volatile("cp.async.commit_group;" ::: "memory");
    asm volatile("cp.async.wait_group 1;" ::: "memory");
    __syncthreads();

    const int aRow = lane & 15, aCol = (lane >> 4) * 8;
    const int bRow = (lane >> 4) * 8 + (lane & 7), bCol = ((lane >> 3) & 1) * 8;

    uint32_t qf[4][4];
    #pragma unroll
    for (int kc = 0; kc < 4; kc++){
        uint32_t addr = sbase + FL_SMQ + (uint32_t)(((wid*16 + aRow)*FL_LQ + kc*16 + aCol) * 2);
        ldmx4(qf[kc], addr);
    }

    float O[8][4];
    #pragma unroll
    for (int j = 0; j < 8; j++){ O[j][0]=0; O[j][1]=0; O[j][2]=0; O[j][3]=0; }
    float m0 = -INFINITY, m1 = -INFINITY, l0 = 0.0f, l1 = 0.0f;
    const int rloc = wid*16 + (lane >> 2);

    int buf = 0;
    for (int kt = 0; kt < 16; kt++){
        asm volatile("cp.async.wait_group 1;" ::: "memory");
        __syncthreads();
        const uint32_t sK = sbase + FL_SMST + buf*FL_STAGE;
        const uint32_t sV = sK + FL_KBYTES;

        float S[16][4];
        #pragma unroll
        for (int j = 0; j < 16; j++){ S[j][0]=0; S[j][1]=0; S[j][2]=0; S[j][3]=0; }

        #pragma unroll
        for (int kc = 0; kc < 4; kc++){
            #pragma unroll
            for (int g = 0; g < 8; g++){
                uint32_t addr = sK + (uint32_t)(((g*16 + bRow)*FL_LQ + kc*16 + bCol) * 2);
                uint32_t bk[4];
                ldmx4(bk, addr);
                mma16816(S[2*g],   qf[kc], bk+0);
                mma16816(S[2*g+1], qf[kc], bk+2);
            }
        }

        // scale + mask(fp16) + running max
        const int t0 = kt * 128;
        const long mr0 = (long)(q0 + rloc) * 2048 + t0;
        const long mr1 = mr0 + 8 * 2048;
        float mx0 = -INFINITY, mx1 = -INFINITY;
        #pragma unroll
        for (int j = 0; j < 16; j++){
            int c = j*8 + (lane & 3)*2;
            float2 k0v = __half22float2(*(const __half2*)(maskh + mr0 + c));
            float2 k1v = __half22float2(*(const __half2*)(maskh + mr1 + c));
            S[j][0] = S[j][0]*0.125f + k0v.x;
            S[j][1] = S[j][1]*0.125f + k0v.y;
            S[j][2] = S[j][2]*0.125f + k1v.x;
            S[j][3] = S[j][3]*0.125f + k1v.y;
            mx0 = fmaxf(mx0, fmaxf(S[j][0], S[j][1]));
            mx1 = fmaxf(mx1, fmaxf(S[j][2], S[j][3]));
        }
        mx0 = fmaxf(mx0, __shfl_xor_sync(0xFFFFFFFFu, mx0, 1));
        mx0 = fmaxf(mx0, __shfl_xor_sync(0xFFFFFFFFu, mx0, 2));
        mx1 = fmaxf(mx1, __shfl_xor_sync(0xFFFFFFFFu, mx1, 1));
        mx1 = fmaxf(mx1, __shfl_xor_sync(0xFFFFFFFFu, mx1, 2));
        float nm0 = fmaxf(m0, mx0), nm1 = fmaxf(m1, mx1);
        float f0 = (m0 > -INFINITY) ? __expf(m0 - nm0) : 0.0f;
        float f1 = (m1 > -INFINITY) ? __expf(m1 - nm1) : 0.0f;
        m0 = nm0; m1 = nm1;

        float s0 = 0.0f, s1 = 0.0f;
        #pragma unroll
        for (int j = 0; j < 16; j++){
            S[j][0] = __expf(S[j][0] - m0);
            S[j][1] = __expf(S[j][1] - m0);
            S[j][2] = __expf(S[j][2] - m1);
            S[j][3] = __expf(S[j][3] - m1);
            s0 += S[j][0] + S[j][1];
            s1 += S[j][2] + S[j][3];
        }
        s0 += __shfl_xor_sync(0xFFFFFFFFu, s0, 1);
        s0 += __shfl_xor_sync(0xFFFFFFFFu, s0, 2);
        s1 += __shfl_xor_sync(0xFFFFFFFFu, s1, 1);
        s1 += __shfl_xor_sync(0xFFFFFFFFu, s1, 2);
        l0 = l0*f0 + s0;
        l1 = l1*f1 + s1;
        #pragma unroll
        for (int j = 0; j < 8; j++){
            O[j][0]*=f0; O[j][1]*=f0; O[j][2]*=f1; O[j][3]*=f1;
        }

        // O += P @ V   (P rounded to fp16)
        #pragma unroll
        for (int kc = 0; kc < 8; kc++){
            uint32_t ph[4];
            ph[0] = pack2h(__float2half_rn(S[2*kc][0]),   __float2half_rn(S[2*kc][1]));
            ph[1] = pack2h(__float2half_rn(S[2*kc][2]),   __float2half_rn(S[2*kc][3]));
            ph[2] = pack2h(__float2half_rn(S[2*kc+1][0]), __float2half_rn(S[2*kc+1][1]));
            ph[3] = pack2h(__float2half_rn(S[2*kc+1][2]), __float2half_rn(S[2*kc+1][3]));
            #pragma unroll
            for (int g = 0; g < 4; g++){
                uint32_t addr = sV + (uint32_t)(((g*16 + bRow)*FL_LV + kc*16 + bCol) * 2);
                uint32_t vf[4];
                ldmx4(vf, addr);
                mma16816(O[2*g],   ph, vf+0);
                mma16816(O[2*g+1], ph, vf+2);
            }
        }

        if (kt + 2 < 16){
            int nbuf = buf + 2; if (nbuf >= 3) nbuf -= 3;
            load_stage(kt + 2, nbuf);
        }
        asm volatile("cp.async.commit_group;" ::: "memory");
        if (++buf == 3) buf = 0;
    }

    // finalize: O /= l, write av (fp16), av viewed as [Ss, 4096]
    const float inv0 = 1.0f / l0, inv1 = 1.0f / l1;
    #pragma unroll
    for (int j = 0; j < 8; j++){
        const int col = j*8 + (lane & 3)*2;
        const long a0 = (long)(q0 + rloc) * 4096 + hOff + col;
        const long a1 = a0 + 8L * 4096;
        *(uint32_t*)(AV + a0) = pack2h(__float2half_rn(O[j][0]*inv0), __float2half_rn(O[j][1]*inv0));
        *(uint32_t*)(AV + a1) = pack2h(__float2half_rn(O[j][2]*inv1), __float2half_rn(O[j][3]*inv1));
    }
}

// ---------------- fused fp32 -> fp16 conversion (all segments, one launch) ----------------
struct CvtSegs {
    const float4* in[8];
    uint2*        out[8];
    long          start[9];   // cumulative n4 offsets
};
__global__ void cvt_multi(CvtSegs s)
{
    long i = (long)blockIdx.x * 256 + threadIdx.x;
    if (i >= s.start[8]) return;
    int seg = 0;
    #pragma unroll
    for (int k = 1; k < 8; k++) if (i >= s.start[k]) seg = k;
    long j = i - s.start[seg];
    float4 v = s.in[seg][j];
    uint2 H;
    H.x = pack2h(__float2half_rn(v.x), __float2half_rn(v.y));
    H.y = pack2h(__float2half_rn(v.z), __float2half_rn(v.w));
    s.out[seg][j] = H;
}

// ---------------- V transpose (fp16): v[s,b,h,kk] -> vt[z][kk][t] ----------------
__global__ void transpose_v(const __half* __restrict__ v, __half* __restrict__ vt)
{
    __shared__ __half t[64][72];
    const int z  = blockIdx.y;
    const int t0 = blockIdx.x * 64;
    const int b  = z >> 4, h = z & 15;
    const __half* src = v + (size_t)b*1024 + (size_t)h*64;
    for (int it = 0; it < 16; it++){
        int idx = it*256 + threadIdx.x;
        int ti = idx >> 6, kk = idx & 63;
        t[ti][kk] = src[(size_t)(t0 + ti)*4096 + kk];
    }
    __syncthreads();
    size_t obase = (size_t)z * Kh * Ss + t0;
    for (int it = 0; it < 16; it++){
        int idx = it*256 + threadIdx.x;
        int kk = idx >> 6, ti = idx & 63;
        vt[obase + (size_t)kk*Ss + ti] = t[ti][kk];
    }
}

// ---------------- layernorm over D=1024; optional fp16 output ----------------
__global__ void layernorm_kernel(const float* __restrict__ in,
                                 float* __restrict__ out,
                                 __half* __restrict__ oh,
                                 const float* __restrict__ gamma,
                                 const float* __restrict__ beta)
{
    const int row = blockIdx.x;
    const float* x = in + (size_t)row * Dd;
    const int tid = threadIdx.x;

    float v[4];
    float s = 0.0f, s2 = 0.0f;
    #pragma unroll
    for (int i = 0; i < 4; i++){
        v[i] = x[tid + i*256];
        s  += v[i];
        s2 += v[i]*v[i];
    }
    __shared__ float r1[256], r2[256];
    r1[tid] = s; r2[tid] = s2; __syncthreads();
    for (int off = 128; off > 0; off >>= 1){
        if (tid < off){ r1[tid] += r1[tid+off]; r2[tid] += r2[tid+off]; }
        __syncthreads();
    }
    float mean = r1[0] * (1.0f/Dd);
    float var  = r2[0] * (1.0f/Dd) - mean*mean;
    float inv  = rsqrtf(var + EPSL);
    #pragma unroll
    for (int i = 0; i < 4; i++){
        int c = tid + i*256;
        float y = (v[i] - mean) * inv * gamma[c] + beta[c];
        out[(size_t)row*Dd + c] = y;
        if (oh) oh[(size_t)row*Dd + c] = __float2half_rn(y);
    }
}

// ---------------- host side ----------------
static const int SMEM_GEMM = 3 * 36864;   // 110592

struct GemmArgs {
    const __half *A, *B;
    float* Cf; __half *Ch;
    int M, N, Kd; long lda, ldb, ldc;
    float alpha; const float* add; long ldadd; const float* bias; int relu;
};

static inline void run_gemm(const GemmArgs& a){
    dim3 grid(a.N / 128, a.M / 128, 1);
    mma_gemm<<<grid, 256, SMEM_GEMM>>>(a.A, a.B, a.Cf, a.Ch,
                                       a.Kd, a.lda, a.ldb, a.ldc,
                                       a.alpha, a.add, a.ldadd, a.bias, a.relu);
}

extern "C" void kernel_launch(void* const* d_in, const int* in_sizes, int n_in,
                              void* d_out, int out_size)
{
    const float* x     = (const float*)d_in[0];
    const float* mask  = (const float*)d_in[1];
    const float* wq    = (const float*)d_in[2];
    const float* wk    = (const float*)d_in[3];
    const float* wv    = (const float*)d_in[4];
    const float* wc    = (const float*)d_in[5];
    const float* w1_w  = (const float*)d_in[6];
    const float* w1_b  = (const float*)d_in[7];
    const float* w2_w  = (const float*)d_in[8];
    const float* w2_b  = (const float*)d_in[9];
    const float* ln1_g = (const float*)d_in[10];
    const float* ln1_b = (const float*)d_in[11];
    const float* ln2_g = (const float*)d_in[12];
    const float* ln2_b = (const float*)d_in[13];
    float* out = (float*)d_out;

    cudaFuncSetAttribute((const void*)mma_gemm,     cudaFuncAttributeMaxDynamicSharedMemorySize, SMEM_GEMM);
    cudaFuncSetAttribute((const void*)flash_kernel, cudaFuncAttributeMaxDynamicSharedMemorySize, FL_SMEM);

    __half *xh,*pwq,*pwk,*pwv,*pwc,*pw1,*pw2,*pmask;
    __half *q,*kk,*vh,*vt,*av,*uh,*h1;
    float *attn,*u,*z;
    cudaGetSymbolAddress((void**)&xh,   g_x);
    cudaGetSymbolAddress((void**)&pwq,  g_wq);
    cudaGetSymbolAddress((void**)&pwk,  g_wk);
    cudaGetSymbolAddress((void**)&pwv,  g_wv);
    cudaGetSymbolAddress((void**)&pwc,  g_wc);
    cudaGetSymbolAddress((void**)&pw1,  g_w1);
    cudaGetSymbolAddress((void**)&pw2,  g_w2);
    cudaGetSymbolAddress((void**)&pmask,g_maskh);
    cudaGetSymbolAddress((void**)&q,    g_q);
    cudaGetSymbolAddress((void**)&kk,   g_k);
    cudaGetSymbolAddress((void**)&vh,   g_vh);
    cudaGetSymbolAddress((void**)&vt,   g_vt);
    cudaGetSymbolAddress((void**)&av,   g_av);
    cudaGetSymbolAddress((void**)&attn, g_attn);
    cudaGetSymbolAddress((void**)&u,    g_u);
    cudaGetSymbolAddress((void**)&uh,   g_uh);
    cudaGetSymbolAddress((void**)&h1,   g_h1);
    cudaGetSymbolAddress((void**)&z,    g_z);

    // single fused conversion launch: x, 6 weights, mask
    {
        CvtSegs s;
        const float* srcs[8] = {x, wq, wk, wv, wc, w1_w, w2_w, mask};
        __half*      dsts[8] = {xh, pwq, pwk, pwv, pwc, pw1, pw2, pmask};
        long lens[8] = {(long)NTOK*Dd, (long)Dd*Dd, (long)Dd*Dd, (long)Dd*Dd,
                        (long)Dd*Dd, (long)Mf*Dd, (long)Mf*Dd, (long)Ss*Ss};
        long acc = 0;
        for (int i = 0; i < 8; i++){
            s.in[i]  = (const float4*)srcs[i];
            s.out[i] = (uint2*)dsts[i];
            s.start[i] = acc;
            acc += lens[i] / 4;
        }
        s.start[8] = acc;
        cvt_multi<<<(unsigned)((acc + 255) / 256), 256>>>(s);
    }

    GemmArgs a;
    // Q = x @ wq^T
    a = {xh,pwq, nullptr,q, NTOK,Dd,Dd, Dd,Dd,Dd, 1.0f, nullptr,0, nullptr,0};
    run_gemm(a);
    // K
    a = {xh,pwk, nullptr,kk, NTOK,Dd,Dd, Dd,Dd,Dd, 1.0f, nullptr,0, nullptr,0};
    run_gemm(a);
    // V (fp16, then transpose)
    a = {xh,pwv, nullptr,vh, NTOK,Dd,Dd, Dd,Dd,Dd, 1.0f, nullptr,0, nullptr,0};
    run_gemm(a);
    {
        dim3 g(Ss/64, BH);
        transpose_v<<<g, 256>>>(vh, vt);
    }
    // fused attention: av = softmax(Q K^T / 8 + mask) @ V
    {
        dim3 g(Ss/128, BH);
        flash_kernel<<<g, 256, FL_SMEM>>>(q, kk, vt, pmask, av);
    }
    // attn = av @ wc^T + x  (fp32)
    a = {av,pwc, attn,nullptr, NTOK,Dd,Dd, Dd,Dd,Dd, 1.0f, x,Dd, nullptr,0};
    run_gemm(a);
    // u = LN1(attn)  (fp32 + fp16)
    layernorm_kernel<<<NTOK, 256>>>(attn, u, uh, ln1_g, ln1_b);
    // h1 = relu(u @ w1^T + b1)
    a = {uh,pw1, nullptr,h1, NTOK,Mf,Dd, Dd,Dd,Mf, 1.0f, nullptr,0, w1_b,1};
    run_gemm(a);
    // z = h1 @ w2^T + b2 + u  (fp32)
    a = {h1,pw2, z,nullptr, NTOK,Dd,Mf, Mf,Mf,Dd, 1.0f, u,Dd, w2_b,0};
    run_gemm(a);
    // out = LN2(z)
    layernorm_kernel<<<NTOK, 256>>>(z, out, nullptr, ln2_g, ln2_b);
}

// round 9
// speedup vs baseline: 10.6353x; 1.0036x over previous
#include <cuda_runtime.h>
#include <cuda_fp16.h>
#include <cstdint>
#include <math.h>

#define Hh   16
#define Kh   64
#define Dd   1024
#define Mf   4096
#define Ss   2048
#define Bb   4
#define NTOK (Ss*Bb)      // 8192
#define BH   (Bb*Hh)      // 64
#define EPSL 1e-5f

// ---------------- scratch buffers (device globals: allocation-free) ----------------
__device__ __half g_x[(size_t)NTOK*Dd];
__device__ __half g_wqkv[(size_t)3*Dd*Dd];        // rows: wq[0:1024), wk[1024:2048), wv[2048:3072)
__device__ __half g_wc[(size_t)Dd*Dd];
__device__ __half g_w1[(size_t)Mf*Dd];
__device__ __half g_w2[(size_t)Mf*Dd];
__device__ __half g_maskh[(size_t)Ss*Ss];
__device__ __half g_qkv[(size_t)NTOK*3*Dd];       // [8192 tokens, 3072]; viewed [2048, 12288]
__device__ __half g_vt[(size_t)BH*Kh*Ss];
__device__ __half g_av[(size_t)NTOK*Dd];
__device__ float  g_attn[(size_t)NTOK*Dd];
__device__ float  g_u[(size_t)NTOK*Dd];
__device__ __half g_uh[(size_t)NTOK*Dd];
__device__ __half g_h1[(size_t)NTOK*Mf];
__device__ float  g_z[(size_t)NTOK*Dd];

// ---------------- helpers ----------------
__device__ __forceinline__ uint32_t smem_u32(const void* p){
    uint32_t a;
    asm("{ .reg .u64 t; cvta.to.shared.u64 t, %1; cvt.u32.u64 %0, t; }" : "=r"(a) : "l"(p));
    return a;
}
__device__ __forceinline__ uint32_t pack2h(__half a, __half b){
    return (uint32_t)__half_as_ushort(a) | ((uint32_t)__half_as_ushort(b) << 16);
}
__device__ __forceinline__ void cpasync16(uint32_t saddr, const void* gaddr){
    asm volatile("cp.async.cg.shared.global [%0], [%1], 16;" :: "r"(saddr), "l"(gaddr) : "memory");
}
__device__ __forceinline__ void ldmx4(uint32_t* r, uint32_t addr){
    asm volatile("ldmatrix.sync.aligned.m8n8.x4.shared.b16 {%0,%1,%2,%3}, [%4];"
                 : "=r"(r[0]), "=r"(r[1]), "=r"(r[2]), "=r"(r[3]) : "r"(addr));
}
__device__ __forceinline__ void mma16816(float* c, const uint32_t* a, const uint32_t* b){
    asm volatile("mma.sync.aligned.m16n8k16.row.col.f32.f16.f16.f32 "
                 "{%0,%1,%2,%3}, {%4,%5,%6,%7}, {%8,%9}, {%0,%1,%2,%3};"
                 : "+f"(c[0]), "+f"(c[1]), "+f"(c[2]), "+f"(c[3])
                 : "r"(a[0]), "r"(a[1]), "r"(a[2]), "r"(a[3]), "r"(b[0]), "r"(b[1]));
}

// ---------------- mma.sync fp16 NT GEMM, BK=64, 3-stage pipeline ----------------
__global__ void __launch_bounds__(256) mma_gemm(
    const __half* __restrict__ A, const __half* __restrict__ B,
    float* __restrict__ Cf, __half* __restrict__ Ch,
    int Kd, long lda, long ldb, long ldc,
    float alpha, const float* __restrict__ add, long ldadd,
    const float* __restrict__ bias, int doRelu)
{
    constexpr int BN   = 128;
    constexpr int BK   = 64;
    constexpr int LDS  = BK + 8;             // 72 halves
    constexpr int WN   = BN / 2;
    constexpr int NT   = WN / 8;             // 8
    constexpr int A_BYTES = 128 * LDS * 2;   // 18432
    constexpr int B_BYTES = BN  * LDS * 2;   // 18432
    constexpr int STAGE   = A_BYTES + B_BYTES;  // 36864

    extern __shared__ char smc[];
    const uint32_t sbase = smem_u32(smc);

    const int tid  = threadIdx.x;
    const int lane = tid & 31;
    const int wid  = tid >> 5;
    const int warpM = (wid & 3) * 32;
    const int warpN = (wid >> 2) * WN;

    const int  m0   = blockIdx.y * 128;
    const int  n0   = blockIdx.x * BN;
    const int  KT   = Kd / BK;

    const int la_row = tid >> 3, la_ch = tid & 7;
    auto load_stage = [&](int kt, int buf){
        const int k0 = kt * BK;
        const uint32_t s0 = sbase + buf * STAGE;
        #pragma unroll
        for (int it = 0; it < 4; it++){
            int row = la_row + it * 32;
            long g = (long)(m0 + row) * lda + k0 + la_ch * 8;
            uint32_t so = (uint32_t)(row * (LDS * 2) + la_ch * 16);
            cpasync16(s0 + so, A + g);
        }
        #pragma unroll
        for (int it = 0; it < 4; it++){
            int row = la_row + it * 32;
            long g = (long)(n0 + row) * ldb + k0 + la_ch * 8;
            uint32_t so = (uint32_t)(row * (LDS * 2) + la_ch * 16);
            cpasync16(s0 + A_BYTES + so, B + g);
        }
    };

    load_stage(0, 0);
    asm volatile("cp.async.commit_group;" ::: "memory");
    load_stage(1, 1);
    asm volatile("cp.async.commit_group;" ::: "memory");

    float acc[2][NT][4];
    #pragma unroll
    for (int i = 0; i < 2; i++)
        #pragma unroll
        for (int j = 0; j < NT; j++)
            #pragma unroll
            for (int e = 0; e < 4; e++) acc[i][j][e] = 0.0f;

    const int aRow = (lane & 15), aColHalf = (lane >> 4) * 8;
    const int bRow = (lane >> 4) * 8 + (lane & 7), bColHalf = ((lane >> 3) & 1) * 8;

    int buf = 0;
    for (int kt = 0; kt < KT; kt++){
        asm volatile("cp.async.wait_group 1;" ::: "memory");
        __syncthreads();
        const uint32_t sA0 = sbase + buf * STAGE;
        const uint32_t sB0 = sA0 + A_BYTES;

        #pragma unroll
        for (int ks = 0; ks < 4; ks++){
            const int k16 = ks * 16;
            uint32_t af[2][4];
            #pragma unroll
            for (int mt = 0; mt < 2; mt++){
                uint32_t addr = sA0 + (uint32_t)(((warpM + mt*16 + aRow) * LDS + k16 + aColHalf) * 2);
                ldmx4(af[mt], addr);
            }
            uint32_t bf[NT][2];
            #pragma unroll
            for (int g = 0; g < NT/2; g++){
                uint32_t addr = sB0 + (uint32_t)(((warpN + g*16 + bRow) * LDS + k16 + bColHalf) * 2);
                uint32_t r[4];
                ldmx4(r, addr);
                bf[2*g][0] = r[0]; bf[2*g][1] = r[1];
                bf[2*g+1][0] = r[2]; bf[2*g+1][1] = r[3];
            }
            #pragma unroll
            for (int mt = 0; mt < 2; mt++)
                #pragma unroll
                for (int j = 0; j < NT; j++)
                    mma16816(acc[mt][j], af[mt], bf[j]);
        }
        if (kt + 2 < KT){
            int nbuf = buf + 2; if (nbuf >= 3) nbuf -= 3;
            load_stage(kt + 2, nbuf);
        }
        asm volatile("cp.async.commit_group;" ::: "memory");
        if (++buf == 3) buf = 0;
    }

    #pragma unroll
    for (int mt = 0; mt < 2; mt++){
        #pragma unroll
        for (int j = 0; j < NT; j++){
            const int col = n0 + warpN + j*8 + (lane & 3) * 2;
            const float b0 = bias ? bias[col]   : 0.0f;
            const float b1 = bias ? bias[col+1] : 0.0f;
            #pragma unroll
            for (int half = 0; half < 2; half++){
                const long row = m0 + warpM + mt*16 + (lane >> 2) + half*8;
                float v0 = acc[mt][j][half*2+0] * alpha + b0;
                float v1 = acc[mt][j][half*2+1] * alpha + b1;
                if (add){
                    v0 += add[row * ldadd + col];
                    v1 += add[row * ldadd + col + 1];
                }
                if (doRelu){ v0 = fmaxf(v0, 0.0f); v1 = fmaxf(v1, 0.0f); }
                const long ci = row * ldc + col;
                if (Ch){
                    *(uint32_t*)(Ch + ci) = pack2h(__float2half_rn(v0), __float2half_rn(v1));
                } else {
                    *(float2*)(Cf + ci) = make_float2(v0, v1);
                }
            }
        }
    }
}

// ---------------- fused flash attention (fp16, 2-stage, 2 CTAs/SM) ----------------
// grid (Ss/128, BH); 256 threads = 8 warps, each warp owns 16 q-rows.
// Q/K read from packed qkv [2048 s-rows, 12288] with col offset b*3072 (+1024 for K) + h*64.
#define FL_LQ 72
#define FL_LV 136
#define FL_QBYTES (128*FL_LQ*2)              // 18432
#define FL_KBYTES (128*FL_LQ*2)              // 18432
#define FL_VBYTES (64*FL_LV*2)               // 17408
#define FL_STAGE (FL_KBYTES + FL_VBYTES)     // 35840
#define FL_SMQ   0
#define FL_SMST  FL_QBYTES                   // 18432
#define FL_SMEM  (FL_SMST + 2*FL_STAGE)      // 90112 -> 2 CTAs/SM

__global__ void __launch_bounds__(256) flash_kernel(
    const __half* __restrict__ QKV,
    const __half* __restrict__ Vt,
    const __half* __restrict__ maskh,
    __half* __restrict__ AV)
{
    extern __shared__ char smc[];
    const uint32_t sbase = smem_u32(smc);
    const int tid = threadIdx.x, lane = tid & 31, wid = tid >> 5;
    const int q0 = blockIdx.x * 128;
    const int z  = blockIdx.y;
    const long qOff = (long)(z >> 4) * 3072 + (long)(z & 15) * 64;   // Q col offset
    const long kOff = qOff + 1024;                                   // K col offset

    auto load_q = [&](){
        #pragma unroll
        for (int it = 0; it < 4; it++){
            int idx = it*256 + tid;
            int row = idx >> 3, ch = idx & 7;
            long g = (long)(q0 + row) * 12288 + qOff + ch*8;
            uint32_t so = sbase + FL_SMQ + (uint32_t)(row*FL_LQ*2 + ch*16);
            cpasync16(so, QKV + g);
        }
    };
    auto load_stage = [&](int kt, int buf){
        const int t0 = kt * 128;
        const uint32_t s0 = sbase + FL_SMST + buf*FL_STAGE;
        #pragma unroll
        for (int it = 0; it < 4; it++){
            int idx = it*256 + tid;
            int row = idx >> 3, ch = idx & 7;
            long g = (long)(t0 + row) * 12288 + kOff + ch*8;
            uint32_t so = s0 + (uint32_t)(row*FL_LQ*2 + ch*16);
            cpasync16(so, QKV + g);
        }
        const uint32_t v0 = s0 + FL_KBYTES;
        #pragma unroll
        for (int it = 0; it < 4; it++){
            int idx = it*256 + tid;
            int row = idx >> 4, ch = idx & 15;
            long g = (long)z*64*2048 + (long)row*2048 + t0 + ch*8;
            uint32_t so = v0 + (uint32_t)(row*FL_LV*2 + ch*16);
            cpasync16(so, Vt + g);
        }
    };

    load_q();
    load_stage(0, 0);
    asm volatile("cp.async.commit_group;" ::: "memory");
    load_stage(1, 1);
    asm volatile("cp.async.commit_group;" ::: "memory");
    asm volatile("cp.async.wait_group 1;" ::: "memory");
    __syncthreads();

    const int aRow = lane & 15, aCol = (lane >> 4) * 8;
    const int bRow = (lane >> 4) * 8 + (lane & 7), bCol = ((lane >> 3) & 1) * 8;

    uint32_t qf[4][4];
    #pragma unroll
    for (int kc = 0; kc < 4; kc++){
        uint32_t addr = sbase + FL_SMQ + (uint32_t)(((wid*16 + aRow)*FL_LQ + kc*16 + aCol) * 2);
        ldmx4(qf[kc], addr);
    }

    float O[8][4];
    #pragma unroll
    for (int j = 0; j < 8; j++){ O[j][0]=0; O[j][1]=0; O[j][2]=0; O[j][3]=0; }
    float m0 = -INFINITY, m1 = -INFINITY, l0 = 0.0f, l1 = 0.0f;
    const int rloc = wid*16 + (lane >> 2);

    for (int kt = 0; kt < 16; kt++){
        asm volatile("cp.async.wait_group 1;" ::: "memory");
        __syncthreads();
        const uint32_t sK = sbase + FL_SMST + (kt & 1)*FL_STAGE;
        const uint32_t sV = sK + FL_KBYTES;

        float S[16][4];
        #pragma unroll
        for (int j = 0; j < 16; j++){ S[j][0]=0; S[j][1]=0; S[j][2]=0; S[j][3]=0; }

        #pragma unroll
        for (int kc = 0; kc < 4; kc++){
            #pragma unroll
            for (int g = 0; g < 8; g++){
                uint32_t addr = sK + (uint32_t)(((g*16 + bRow)*FL_LQ + kc*16 + bCol) * 2);
                uint32_t bk[4];
                ldmx4(bk, addr);
                mma16816(S[2*g],   qf[kc], bk+0);
                mma16816(S[2*g+1], qf[kc], bk+2);
            }
        }

        // scale + mask(fp16) + running max
        const int t0 = kt * 128;
        const long mr0 = (long)(q0 + rloc) * 2048 + t0;
        const long mr1 = mr0 + 8 * 2048;
        float mx0 = -INFINITY, mx1 = -INFINITY;
        #pragma unroll
        for (int j = 0; j < 16; j++){
            int c = j*8 + (lane & 3)*2;
            float2 k0v = __half22float2(*(const __half2*)(maskh + mr0 + c));
            float2 k1v = __half22float2(*(const __half2*)(maskh + mr1 + c));
            S[j][0] = S[j][0]*0.125f + k0v.x;
            S[j][1] = S[j][1]*0.125f + k0v.y;
            S[j][2] = S[j][2]*0.125f + k1v.x;
            S[j][3] = S[j][3]*0.125f + k1v.y;
            mx0 = fmaxf(mx0, fmaxf(S[j][0], S[j][1]));
            mx1 = fmaxf(mx1, fmaxf(S[j][2], S[j][3]));
        }
        mx0 = fmaxf(mx0, __shfl_xor_sync(0xFFFFFFFFu, mx0, 1));
        mx0 = fmaxf(mx0, __shfl_xor_sync(0xFFFFFFFFu, mx0, 2));
        mx1 = fmaxf(mx1, __shfl_xor_sync(0xFFFFFFFFu, mx1, 1));
        mx1 = fmaxf(mx1, __shfl_xor_sync(0xFFFFFFFFu, mx1, 2));
        float nm0 = fmaxf(m0, mx0), nm1 = fmaxf(m1, mx1);
        float f0 = (m0 > -INFINITY) ? __expf(m0 - nm0) : 0.0f;
        float f1 = (m1 > -INFINITY) ? __expf(m1 - nm1) : 0.0f;
        m0 = nm0; m1 = nm1;

        float s0 = 0.0f, s1 = 0.0f;
        #pragma unroll
        for (int j = 0; j < 16; j++){
            S[j][0] = __expf(S[j][0] - m0);
            S[j][1] = __expf(S[j][1] - m0);
            S[j][2] = __expf(S[j][2] - m1);
            S[j][3] = __expf(S[j][3] - m1);
            s0 += S[j][0] + S[j][1];
            s1 += S[j][2] + S[j][3];
        }
        s0 += __shfl_xor_sync(0xFFFFFFFFu, s0, 1);
        s0 += __shfl_xor_sync(0xFFFFFFFFu, s0, 2);
        s1 += __shfl_xor_sync(0xFFFFFFFFu, s1, 1);
        s1 += __shfl_xor_sync(0xFFFFFFFFu, s1, 2);
        l0 = l0*f0 + s0;
        l1 = l1*f1 + s1;
        #pragma unroll
        for (int j = 0; j < 8; j++){
            O[j][0]*=f0; O[j][1]*=f0; O[j][2]*=f1; O[j][3]*=f1;
        }

        // O += P @ V
        #pragma unroll
        for (int kc = 0; kc < 8; kc++){
            uint32_t ph[4];
            ph[0] = pack2h(__float2half_rn(S[2*kc][0]),   __float2half_rn(S[2*kc][1]));
            ph[1] = pack2h(__float2half_rn(S[2*kc][2]),   __float2half_rn(S[2*kc][3]));
            ph[2] = pack2h(__float2half_rn(S[2*kc+1][0]), __float2half_rn(S[2*kc+1][1]));
            ph[3] = pack2h(__float2half_rn(S[2*kc+1][2]), __float2half_rn(S[2*kc+1][3]));
            #pragma unroll
            for (int g = 0; g < 4; g++){
                uint32_t addr = sV + (uint32_t)(((g*16 + bRow)*FL_LV + kc*16 + bCol) * 2);
                uint32_t vf[4];
                ldmx4(vf, addr);
                mma16816(O[2*g],   ph, vf+0);
                mma16816(O[2*g+1], ph, vf+2);
            }
        }

        // trailing sync: all warps done reading this buffer before overwrite
        __syncthreads();
        if (kt + 2 < 16) load_stage(kt + 2, kt & 1);
        asm volatile("cp.async.commit_group;" ::: "memory");
    }

    // finalize: O /= l, write av (fp16) as [Ss, 4096] (= [NTOK,1024], col b*1024+h*64)
    const long hOff = (long)z * 64;
    const float inv0 = 1.0f / l0, inv1 = 1.0f / l1;
    #pragma unroll
    for (int j = 0; j < 8; j++){
        const int col = j*8 + (lane & 3)*2;
        const long a0 = (long)(q0 + rloc) * 4096 + hOff + col;
        const long a1 = a0 + 8L * 4096;
        *(uint32_t*)(AV + a0) = pack2h(__float2half_rn(O[j][0]*inv0), __float2half_rn(O[j][1]*inv0));
        *(uint32_t*)(AV + a1) = pack2h(__float2half_rn(O[j][2]*inv1), __float2half_rn(O[j][3]*inv1));
    }
}

// ---------------- fused fp32 -> fp16 conversion (all segments, one launch) ----------------
struct CvtSegs {
    const float4* in[8];
    uint2*        out[8];
    long          start[9];
};
__global__ void cvt_multi(CvtSegs s)
{
    long i = (long)blockIdx.x * 256 + threadIdx.x;
    if (i >= s.start[8]) return;
    int seg = 0;
    #pragma unroll
    for (int k = 1; k < 8; k++) if (i >= s.start[k]) seg = k;
    long j = i - s.start[seg];
    float4 v = s.in[seg][j];
    uint2 H;
    H.x = pack2h(__float2half_rn(v.x), __float2half_rn(v.y));
    H.y = pack2h(__float2half_rn(v.z), __float2half_rn(v.w));
    s.out[seg][j] = H;
}

// ---------------- V transpose (fp16): qkv V section -> vt[z][kk][t] ----------------
__global__ void transpose_v(const __half* __restrict__ qkv, __half* __restrict__ vt)
{
    __shared__ __half t[64][72];
    const int z  = blockIdx.y;
    const int t0 = blockIdx.x * 64;
    const int b  = z >> 4, h = z & 15;
    const __half* src = qkv + 2048 + (size_t)b*3072 + (size_t)h*64;
    for (int it = 0; it < 16; it++){
        int idx = it*256 + threadIdx.x;
        int ti = idx >> 6, kk = idx & 63;
        t[ti][kk] = src[(size_t)(t0 + ti)*12288 + kk];
    }
    __syncthreads();
    size_t obase = (size_t)z * Kh * Ss + t0;
    for (int it = 0; it < 16; it++){
        int idx = it*256 + threadIdx.x;
        int kk = idx >> 6, ti = idx & 63;
        vt[obase + (size_t)kk*Ss + ti] = t[ti][kk];
    }
}

// ---------------- layernorm over D=1024; optional fp16 output ----------------
__global__ void layernorm_kernel(const float* __restrict__ in,
                                 float* __restrict__ out,
                                 __half* __restrict__ oh,
                                 const float* __restrict__ gamma,
                                 const float* __restrict__ beta)
{
    const int row = blockIdx.x;
    const float* x = in + (size_t)row * Dd;
    const int tid = threadIdx.x;

    float v[4];
    float s = 0.0f, s2 = 0.0f;
    #pragma unroll
    for (int i = 0; i < 4; i++){
        v[i] = x[tid + i*256];
        s  += v[i];
        s2 += v[i]*v[i];
    }
    __shared__ float r1[256], r2[256];
    r1[tid] = s; r2[tid] = s2; __syncthreads();
    for (int off = 128; off > 0; off >>= 1){
        if (tid < off){ r1[tid] += r1[tid+off]; r2[tid] += r2[tid+off]; }
        __syncthreads();
    }
    float mean = r1[0] * (1.0f/Dd);
    float var  = r2[0] * (1.0f/Dd) - mean*mean;
    float inv  = rsqrtf(var + EPSL);
    #pragma unroll
    for (int i = 0; i < 4; i++){
        int c = tid + i*256;
        float y = (v[i] - mean) * inv * gamma[c] + beta[c];
        out[(size_t)row*Dd + c] = y;
        if (oh) oh[(size_t)row*Dd + c] = __float2half_rn(y);
    }
}

// ---------------- host side ----------------
static const int SMEM_GEMM = 3 * 36864;   // 110592

struct GemmArgs {
    const __half *A, *B;
    float* Cf; __half *Ch;
    int M, N, Kd; long lda, ldb, ldc;
    float alpha; const float* add; long ldadd; const float* bias; int relu;
};

static inline void run_gemm(const GemmArgs& a){
    dim3 grid(a.N / 128, a.M / 128, 1);
    mma_gemm<<<grid, 256, SMEM_GEMM>>>(a.A, a.B, a.Cf, a.Ch,
                                       a.Kd, a.lda, a.ldb, a.ldc,
                                       a.alpha, a.add, a.ldadd, a.bias, a.relu);
}

extern "C" void kernel_launch(void* const* d_in, const int* in_sizes, int n_in,
                              void* d_out, int out_size)
{
    const float* x     = (const float*)d_in[0];
    const float* mask  = (const float*)d_in[1];
    const float* wq    = (const float*)d_in[2];
    const float* wk    = (const float*)d_in[3];
    const float* wv    = (const float*)d_in[4];
    const float* wc    = (const float*)d_in[5];
    const float* w1_w  = (const float*)d_in[6];
    const float* w1_b  = (const float*)d_in[7];
    const float* w2_w  = (const float*)d_in[8];
    const float* w2_b  = (const float*)d_in[9];
    const float* ln1_g = (const float*)d_in[10];
    const float* ln1_b = (const float*)d_in[11];
    const float* ln2_g = (const float*)d_in[12];
    const float* ln2_b = (const float*)d_in[13];
    float* out = (float*)d_out;

    cudaFuncSetAttribute((const void*)mma_gemm,     cudaFuncAttributeMaxDynamicSharedMemorySize, SMEM_GEMM);
    cudaFuncSetAttribute((const void*)flash_kernel, cudaFuncAttributeMaxDynamicSharedMemorySize, FL_SMEM);

    __half *xh,*pwqkv,*pwc,*pw1,*pw2,*pmask;
    __half *qkv,*vt,*av,*uh,*h1;
    float *attn,*u,*z;
    cudaGetSymbolAddress((void**)&xh,    g_x);
    cudaGetSymbolAddress((void**)&pwqkv, g_wqkv);
    cudaGetSymbolAddress((void**)&pwc,   g_wc);
    cudaGetSymbolAddress((void**)&pw1,   g_w1);
    cudaGetSymbolAddress((void**)&pw2,   g_w2);
    cudaGetSymbolAddress((void**)&pmask, g_maskh);
    cudaGetSymbolAddress((void**)&qkv,   g_qkv);
    cudaGetSymbolAddress((void**)&vt,    g_vt);
    cudaGetSymbolAddress((void**)&av,    g_av);
    cudaGetSymbolAddress((void**)&attn,  g_attn);
    cudaGetSymbolAddress((void**)&u,     g_u);
    cudaGetSymbolAddress((void**)&uh,    g_uh);
    cudaGetSymbolAddress((void**)&h1,    g_h1);
    cudaGetSymbolAddress((void**)&z,     g_z);

    // single fused conversion launch: x, wq|wk|wv (into packed buffer), wc, w1, w2, mask
    {
        CvtSegs s;
        const float* srcs[8] = {x, wq, wk, wv, wc, w1_w, w2_w, mask};
        __half*      dsts[8] = {xh, pwqkv, pwqkv + (size_t)Dd*Dd, pwqkv + (size_t)2*Dd*Dd,
                                pwc, pw1, pw2, pmask};
        long lens[8] = {(long)NTOK*Dd, (long)Dd*Dd, (long)Dd*Dd, (long)Dd*Dd,
                        (long)Dd*Dd, (long)Mf*Dd, (long)Mf*Dd, (long)Ss*Ss};
        long acc = 0;
        for (int i = 0; i < 8; i++){
            s.in[i]  = (const float4*)srcs[i];
            s.out[i] = (uint2*)dsts[i];
            s.start[i] = acc;
            acc += lens[i] / 4;
        }
        s.start[8] = acc;
        cvt_multi<<<(unsigned)((acc + 255) / 256), 256>>>(s);
    }

    GemmArgs a;
    // QKV = x @ wqkv^T  (one fused GEMM, N=3072)
    a = {xh,pwqkv, nullptr,qkv, NTOK,3*Dd,Dd, Dd,Dd,3*Dd, 1.0f, nullptr,0, nullptr,0};
    run_gemm(a);
    // V transpose from packed qkv
    {
        dim3 g(Ss/64, BH);
        transpose_v<<<g, 256>>>(qkv, vt);
    }
    // fused attention: av = softmax(Q K^T / 8 + mask) @ V
    {
        dim3 g(Ss/128, BH);
        flash_kernel<<<g, 256, FL_SMEM>>>(qkv, vt, pmask, av);
    }
    // attn = av @ wc^T + x  (fp32)
    a = {av,pwc, attn,nullptr, NTOK,Dd,Dd, Dd,Dd,Dd, 1.0f, x,Dd, nullptr,0};
    run_gemm(a);
    // u = LN1(attn)
    layernorm_kernel<<<NTOK, 256>>>(attn, u, uh, ln1_g, ln1_b);
    // h1 = relu(u @ w1^T + b1)
    a = {uh,pw1, nullptr,h1, NTOK,Mf,Dd, Dd,Dd,Mf, 1.0f, nullptr,0, w1_b,1};
    run_gemm(a);
    // z = h1 @ w2^T + b2 + u  (fp32)
    a = {h1,pw2, z,nullptr, NTOK,Dd,Mf, Mf,Mf,Dd, 1.0f, u,Dd, w2_b,0};
    run_gemm(a);
    // out = LN2(z)
    layernorm_kernel<<<NTOK, 256>>>(z, out, nullptr, ln2_g, ln2_b);
}

// round 10
// speedup vs baseline: 11.5509x; 1.0861x over previous
#include <cuda_runtime.h>
#include <cuda_fp16.h>
#include <cstdint>
#include <math.h>

#define Hh   16
#define Kh   64
#define Dd   1024
#define Mf   4096
#define Ss   2048
#define Bb   4
#define NTOK (Ss*Bb)      // 8192
#define BH   (Bb*Hh)      // 64
#define EPSL 1e-5f

// ---------------- scratch buffers (device globals: allocation-free) ----------------
__device__ __half g_x[(size_t)NTOK*Dd];
__device__ __half g_wqkv[(size_t)3*Dd*Dd];        // rows: wq[0:1024), wk[1024:2048), wv[2048:3072)
__device__ __half g_wc[(size_t)Dd*Dd];
__device__ __half g_w1[(size_t)Mf*Dd];
__device__ __half g_w2[(size_t)Mf*Dd];
__device__ __half g_maskh[(size_t)Ss*Ss];
__device__ __half g_qkv[(size_t)NTOK*3*Dd];       // [8192 tokens, 3072]; viewed [2048, 12288]
__device__ __half g_vt[(size_t)BH*Kh*Ss];
__device__ __half g_av[(size_t)NTOK*Dd];
__device__ float  g_attn[(size_t)NTOK*Dd];
__device__ float  g_u[(size_t)NTOK*Dd];
__device__ __half g_uh[(size_t)NTOK*Dd];
__device__ __half g_h1[(size_t)NTOK*Mf];
__device__ float  g_z[(size_t)NTOK*Dd];

// ---------------- helpers ----------------
__device__ __forceinline__ uint32_t smem_u32(const void* p){
    uint32_t a;
    asm("{ .reg .u64 t; cvta.to.shared.u64 t, %1; cvt.u32.u64 %0, t; }" : "=r"(a) : "l"(p));
    return a;
}
__device__ __forceinline__ uint32_t pack2h(__half a, __half b){
    return (uint32_t)__half_as_ushort(a) | ((uint32_t)__half_as_ushort(b) << 16);
}
__device__ __forceinline__ void cpasync16(uint32_t saddr, const void* gaddr){
    asm volatile("cp.async.cg.shared.global [%0], [%1], 16;" :: "r"(saddr), "l"(gaddr) : "memory");
}
__device__ __forceinline__ void ldmx4(uint32_t* r, uint32_t addr){
    asm volatile("ldmatrix.sync.aligned.m8n8.x4.shared.b16 {%0,%1,%2,%3}, [%4];"
                 : "=r"(r[0]), "=r"(r[1]), "=r"(r[2]), "=r"(r[3]) : "r"(addr));
}
__device__ __forceinline__ void mma16816(float* c, const uint32_t* a, const uint32_t* b){
    asm volatile("mma.sync.aligned.m16n8k16.row.col.f32.f16.f16.f32 "
                 "{%0,%1,%2,%3}, {%4,%5,%6,%7}, {%8,%9}, {%0,%1,%2,%3};"
                 : "+f"(c[0]), "+f"(c[1]), "+f"(c[2]), "+f"(c[3])
                 : "r"(a[0]), "r"(a[1]), "r"(a[2]), "r"(a[3]), "r"(b[0]), "r"(b[1]));
}

// ---------------- mma.sync fp16 NT GEMM, BK=64, 3-stage pipeline ----------------
__global__ void __launch_bounds__(256) mma_gemm(
    const __half* __restrict__ A, const __half* __restrict__ B,
    float* __restrict__ Cf, __half* __restrict__ Ch,
    int Kd, long lda, long ldb, long ldc,
    float alpha, const float* __restrict__ add, long ldadd,
    const float* __restrict__ bias, int doRelu)
{
    constexpr int BN   = 128;
    constexpr int BK   = 64;
    constexpr int LDS  = BK + 8;             // 72 halves
    constexpr int WN   = BN / 2;
    constexpr int NT   = WN / 8;             // 8
    constexpr int A_BYTES = 128 * LDS * 2;   // 18432
    constexpr int B_BYTES = BN  * LDS * 2;   // 18432
    constexpr int STAGE   = A_BYTES + B_BYTES;  // 36864

    extern __shared__ char smc[];
    const uint32_t sbase = smem_u32(smc);

    const int tid  = threadIdx.x;
    const int lane = tid & 31;
    const int wid  = tid >> 5;
    const int warpM = (wid & 3) * 32;
    const int warpN = (wid >> 2) * WN;

    const int  m0   = blockIdx.y * 128;
    const int  n0   = blockIdx.x * BN;
    const int  KT   = Kd / BK;

    const int la_row = tid >> 3, la_ch = tid & 7;
    auto load_stage = [&](int kt, int buf){
        const int k0 = kt * BK;
        const uint32_t s0 = sbase + buf * STAGE;
        #pragma unroll
        for (int it = 0; it < 4; it++){
            int row = la_row + it * 32;
            long g = (long)(m0 + row) * lda + k0 + la_ch * 8;
            uint32_t so = (uint32_t)(row * (LDS * 2) + la_ch * 16);
            cpasync16(s0 + so, A + g);
        }
        #pragma unroll
        for (int it = 0; it < 4; it++){
            int row = la_row + it * 32;
            long g = (long)(n0 + row) * ldb + k0 + la_ch * 8;
            uint32_t so = (uint32_t)(row * (LDS * 2) + la_ch * 16);
            cpasync16(s0 + A_BYTES + so, B + g);
        }
    };

    load_stage(0, 0);
    asm volatile("cp.async.commit_group;" ::: "memory");
    load_stage(1, 1);
    asm volatile("cp.async.commit_group;" ::: "memory");

    float acc[2][NT][4];
    #pragma unroll
    for (int i = 0; i < 2; i++)
        #pragma unroll
        for (int j = 0; j < NT; j++)
            #pragma unroll
            for (int e = 0; e < 4; e++) acc[i][j][e] = 0.0f;

    const int aRow = (lane & 15), aColHalf = (lane >> 4) * 8;
    const int bRow = (lane >> 4) * 8 + (lane & 7), bColHalf = ((lane >> 3) & 1) * 8;

    int buf = 0;
    for (int kt = 0; kt < KT; kt++){
        asm volatile("cp.async.wait_group 1;" ::: "memory");
        __syncthreads();
        const uint32_t sA0 = sbase + buf * STAGE;
        const uint32_t sB0 = sA0 + A_BYTES;

        #pragma unroll
        for (int ks = 0; ks < 4; ks++){
            const int k16 = ks * 16;
            uint32_t af[2][4];
            #pragma unroll
            for (int mt = 0; mt < 2; mt++){
                uint32_t addr = sA0 + (uint32_t)(((warpM + mt*16 + aRow) * LDS + k16 + aColHalf) * 2);
                ldmx4(af[mt], addr);
            }
            uint32_t bf[NT][2];
            #pragma unroll
            for (int g = 0; g < NT/2; g++){
                uint32_t addr = sB0 + (uint32_t)(((warpN + g*16 + bRow) * LDS + k16 + bColHalf) * 2);
                uint32_t r[4];
                ldmx4(r, addr);
                bf[2*g][0] = r[0]; bf[2*g][1] = r[1];
                bf[2*g+1][0] = r[2]; bf[2*g+1][1] = r[3];
            }
            #pragma unroll
            for (int mt = 0; mt < 2; mt++)
                #pragma unroll
                for (int j = 0; j < NT; j++)
                    mma16816(acc[mt][j], af[mt], bf[j]);
        }
        if (kt + 2 < KT){
            int nbuf = buf + 2; if (nbuf >= 3) nbuf -= 3;
            load_stage(kt + 2, nbuf);
        }
        asm volatile("cp.async.commit_group;" ::: "memory");
        if (++buf == 3) buf = 0;
    }

    #pragma unroll
    for (int mt = 0; mt < 2; mt++){
        #pragma unroll
        for (int j = 0; j < NT; j++){
            const int col = n0 + warpN + j*8 + (lane & 3) * 2;
            const float b0 = bias ? bias[col]   : 0.0f;
            const float b1 = bias ? bias[col+1] : 0.0f;
            #pragma unroll
            for (int half = 0; half < 2; half++){
                const long row = m0 + warpM + mt*16 + (lane >> 2) + half*8;
                float v0 = acc[mt][j][half*2+0] * alpha + b0;
                float v1 = acc[mt][j][half*2+1] * alpha + b1;
                if (add){
                    v0 += add[row * ldadd + col];
                    v1 += add[row * ldadd + col + 1];
                }
                if (doRelu){ v0 = fmaxf(v0, 0.0f); v1 = fmaxf(v1, 0.0f); }
                const long ci = row * ldc + col;
                if (Ch){
                    *(uint32_t*)(Ch + ci) = pack2h(__float2half_rn(v0), __float2half_rn(v1));
                } else {
                    *(float2*)(Cf + ci) = make_float2(v0, v1);
                }
            }
        }
    }
}

// ---------------- fused flash attention (fp16, t-tile 64, 3-stage, 2 CTAs/SM) ----------------
// grid (Ss/128, BH); 256 threads = 8 warps, each warp owns 16 q-rows x 64 t-cols per iter.
#define FL_LQ 72
#define FL_QBYTES (128*FL_LQ*2)              // 18432
#define FL_KB (64*FL_LQ*2)                   // 9216 (64 t-rows)
#define FL_VB (64*FL_LQ*2)                   // 9216 (64 kk-rows x 64 t-chunk)
#define FL_STAGE (FL_KB + FL_VB)             // 18432
#define FL_SMQ   0
#define FL_SMST  FL_QBYTES                   // 18432
#define FL_SMEM  (FL_SMST + 3*FL_STAGE)      // 73728 -> 2 CTAs/SM (reg-capped via launch_bounds)

__global__ void __launch_bounds__(256,2) flash_kernel(
    const __half* __restrict__ QKV,
    const __half* __restrict__ Vt,
    const __half* __restrict__ maskh,
    __half* __restrict__ AV)
{
    extern __shared__ char smc[];
    const uint32_t sbase = smem_u32(smc);
    const int tid = threadIdx.x, lane = tid & 31, wid = tid >> 5;
    const int q0 = blockIdx.x * 128;
    const int z  = blockIdx.y;
    const long qOff = (long)(z >> 4) * 3072 + (long)(z & 15) * 64;   // Q col offset
    const long kOff = qOff + 1024;                                   // K col offset

    auto load_q = [&](){
        #pragma unroll
        for (int it = 0; it < 4; it++){
            int idx = it*256 + tid;
            int row = idx >> 3, ch = idx & 7;
            long g = (long)(q0 + row) * 12288 + qOff + ch*8;
            uint32_t so = sbase + FL_SMQ + (uint32_t)(row*FL_LQ*2 + ch*16);
            cpasync16(so, QKV + g);
        }
    };
    // stage kt covers t-range [kt*64, kt*64+64)
    auto load_stage = [&](int kt, int buf){
        const int t0 = kt * 64;
        const uint32_t s0 = sbase + FL_SMST + buf*FL_STAGE;
        #pragma unroll
        for (int it = 0; it < 2; it++){
            int idx = it*256 + tid;
            int row = idx >> 3, ch = idx & 7;       // 64 t-rows x 8 chunks
            long g = (long)(t0 + row) * 12288 + kOff + ch*8;
            uint32_t so = s0 + (uint32_t)(row*FL_LQ*2 + ch*16);
            cpasync16(so, QKV + g);
        }
        const uint32_t v0 = s0 + FL_KB;
        #pragma unroll
        for (int it = 0; it < 2; it++){
            int idx = it*256 + tid;
            int row = idx >> 3, ch = idx & 7;       // 64 kk-rows x 8 chunks of t
            long g = (long)z*64*2048 + (long)row*2048 + t0 + ch*8;
            uint32_t so = v0 + (uint32_t)(row*FL_LQ*2 + ch*16);
            cpasync16(so, Vt + g);
        }
    };

    load_q();
    load_stage(0, 0);
    asm volatile("cp.async.commit_group;" ::: "memory");
    load_stage(1, 1);
    asm volatile("cp.async.commit_group;" ::: "memory");
    asm volatile("cp.async.wait_group 1;" ::: "memory");
    __syncthreads();

    const int aRow = lane & 15, aCol = (lane >> 4) * 8;
    const int bRow = (lane >> 4) * 8 + (lane & 7), bCol = ((lane >> 3) & 1) * 8;

    uint32_t qf[4][4];
    #pragma unroll
    for (int kc = 0; kc < 4; kc++){
        uint32_t addr = sbase + FL_SMQ + (uint32_t)(((wid*16 + aRow)*FL_LQ + kc*16 + aCol) * 2);
        ldmx4(qf[kc], addr);
    }

    float O[8][4];
    #pragma unroll
    for (int j = 0; j < 8; j++){ O[j][0]=0; O[j][1]=0; O[j][2]=0; O[j][3]=0; }
    float m0 = -INFINITY, m1 = -INFINITY, l0 = 0.0f, l1 = 0.0f;
    const int rloc = wid*16 + (lane >> 2);

    int buf = 0;
    for (int kt = 0; kt < 32; kt++){
        asm volatile("cp.async.wait_group 1;" ::: "memory");
        __syncthreads();
        const uint32_t sK = sbase + FL_SMST + buf*FL_STAGE;
        const uint32_t sV = sK + FL_KB;

        float S[8][4];
        #pragma unroll
        for (int j = 0; j < 8; j++){ S[j][0]=0; S[j][1]=0; S[j][2]=0; S[j][3]=0; }

        // S = Q @ K^T over 64 t-cols
        #pragma unroll
        for (int kc = 0; kc < 4; kc++){
            #pragma unroll
            for (int g = 0; g < 4; g++){
                uint32_t addr = sK + (uint32_t)(((g*16 + bRow)*FL_LQ + kc*16 + bCol) * 2);
                uint32_t bk[4];
                ldmx4(bk, addr);
                mma16816(S[2*g],   qf[kc], bk+0);
                mma16816(S[2*g+1], qf[kc], bk+2);
            }
        }

        // scale + mask(fp16) + running max
        const int t0 = kt * 64;
        const long mr0 = (long)(q0 + rloc) * 2048 + t0;
        const long mr1 = mr0 + 8 * 2048;
        float mx0 = -INFINITY, mx1 = -INFINITY;
        #pragma unroll
        for (int j = 0; j < 8; j++){
            int c = j*8 + (lane & 3)*2;
            float2 k0v = __half22float2(*(const __half2*)(maskh + mr0 + c));
            float2 k1v = __half22float2(*(const __half2*)(maskh + mr1 + c));
            S[j][0] = S[j][0]*0.125f + k0v.x;
            S[j][1] = S[j][1]*0.125f + k0v.y;
            S[j][2] = S[j][2]*0.125f + k1v.x;
            S[j][3] = S[j][3]*0.125f + k1v.y;
            mx0 = fmaxf(mx0, fmaxf(S[j][0], S[j][1]));
            mx1 = fmaxf(mx1, fmaxf(S[j][2], S[j][3]));
        }
        mx0 = fmaxf(mx0, __shfl_xor_sync(0xFFFFFFFFu, mx0, 1));
        mx0 = fmaxf(mx0, __shfl_xor_sync(0xFFFFFFFFu, mx0, 2));
        mx1 = fmaxf(mx1, __shfl_xor_sync(0xFFFFFFFFu, mx1, 1));
        mx1 = fmaxf(mx1, __shfl_xor_sync(0xFFFFFFFFu, mx1, 2));
        float nm0 = fmaxf(m0, mx0), nm1 = fmaxf(m1, mx1);
        float f0 = (m0 > -INFINITY) ? __expf(m0 - nm0) : 0.0f;
        float f1 = (m1 > -INFINITY) ? __expf(m1 - nm1) : 0.0f;
        m0 = nm0; m1 = nm1;

        float s0 = 0.0f, s1 = 0.0f;
        #pragma unroll
        for (int j = 0; j < 8; j++){
            S[j][0] = __expf(S[j][0] - m0);
            S[j][1] = __expf(S[j][1] - m0);
            S[j][2] = __expf(S[j][2] - m1);
            S[j][3] = __expf(S[j][3] - m1);
            s0 += S[j][0] + S[j][1];
            s1 += S[j][2] + S[j][3];
        }
        s0 += __shfl_xor_sync(0xFFFFFFFFu, s0, 1);
        s0 += __shfl_xor_sync(0xFFFFFFFFu, s0, 2);
        s1 += __shfl_xor_sync(0xFFFFFFFFu, s1, 1);
        s1 += __shfl_xor_sync(0xFFFFFFFFu, s1, 2);
        l0 = l0*f0 + s0;
        l1 = l1*f1 + s1;
        #pragma unroll
        for (int j = 0; j < 8; j++){
            O[j][0]*=f0; O[j][1]*=f0; O[j][2]*=f1; O[j][3]*=f1;
        }

        // O += P @ V   (P rounded to fp16; k-dim = 64 t)
        #pragma unroll
        for (int kc = 0; kc < 4; kc++){
            uint32_t ph[4];
            ph[0] = pack2h(__float2half_rn(S[2*kc][0]),   __float2half_rn(S[2*kc][1]));
            ph[1] = pack2h(__float2half_rn(S[2*kc][2]),   __float2half_rn(S[2*kc][3]));
            ph[2] = pack2h(__float2half_rn(S[2*kc+1][0]), __float2half_rn(S[2*kc+1][1]));
            ph[3] = pack2h(__float2half_rn(S[2*kc+1][2]), __float2half_rn(S[2*kc+1][3]));
            #pragma unroll
            for (int g = 0; g < 4; g++){
                uint32_t addr = sV + (uint32_t)(((g*16 + bRow)*FL_LQ + kc*16 + bCol) * 2);
                uint32_t vf[4];
                ldmx4(vf, addr);
                mma16816(O[2*g],   ph, vf+0);
                mma16816(O[2*g+1], ph, vf+2);
            }
        }

        if (kt + 2 < 32){
            int nbuf = buf + 2; if (nbuf >= 3) nbuf -= 3;
            load_stage(kt + 2, nbuf);
        }
        asm volatile("cp.async.commit_group;" ::: "memory");
        if (++buf == 3) buf = 0;
    }

    // finalize: O /= l, write av (fp16) as [Ss, 4096] (= [NTOK,1024], col b*1024+h*64)
    const long hOff = (long)z * 64;
    const float inv0 = 1.0f / l0, inv1 = 1.0f / l1;
    #pragma unroll
    for (int j = 0; j < 8; j++){
        const int col = j*8 + (lane & 3)*2;
        const long a0 = (long)(q0 + rloc) * 4096 + hOff + col;
        const long a1 = a0 + 8L * 4096;
        *(uint32_t*)(AV + a0) = pack2h(__float2half_rn(O[j][0]*inv0), __float2half_rn(O[j][1]*inv0));
        *(uint32_t*)(AV + a1) = pack2h(__float2half_rn(O[j][2]*inv1), __float2half_rn(O[j][3]*inv1));
    }
}

// ---------------- fused fp32 -> fp16 conversion (all segments, one launch) ----------------
struct CvtSegs {
    const float4* in[8];
    uint2*        out[8];
    long          start[9];
};
__global__ void cvt_multi(CvtSegs s)
{
    long i = (long)blockIdx.x * 256 + threadIdx.x;
    if (i >= s.start[8]) return;
    int seg = 0;
    #pragma unroll
    for (int k = 1; k < 8; k++) if (i >= s.start[k]) seg = k;
    long j = i - s.start[seg];
    float4 v = s.in[seg][j];
    uint2 H;
    H.x = pack2h(__float2half_rn(v.x), __float2half_rn(v.y));
    H.y = pack2h(__float2half_rn(v.z), __float2half_rn(v.w));
    s.out[seg][j] = H;
}

// ---------------- V transpose (fp16): qkv V section -> vt[z][kk][t] ----------------
__global__ void transpose_v(const __half* __restrict__ qkv, __half* __restrict__ vt)
{
    __shared__ __half t[64][72];
    const int z  = blockIdx.y;
    const int t0 = blockIdx.x * 64;
    const int b  = z >> 4, h = z & 15;
    const __half* src = qkv + 2048 + (size_t)b*3072 + (size_t)h*64;
    for (int it = 0; it < 16; it++){
        int idx = it*256 + threadIdx.x;
        int ti = idx >> 6, kk = idx & 63;
        t[ti][kk] = src[(size_t)(t0 + ti)*12288 + kk];
    }
    __syncthreads();
    size_t obase = (size_t)z * Kh * Ss + t0;
    for (int it = 0; it < 16; it++){
        int idx = it*256 + threadIdx.x;
        int kk = idx >> 6, ti = idx & 63;
        vt[obase + (size_t)kk*Ss + ti] = t[ti][kk];
    }
}

// ---------------- layernorm over D=1024; optional fp16 output ----------------
__global__ void layernorm_kernel(const float* __restrict__ in,
                                 float* __restrict__ out,
                                 __half* __restrict__ oh,
                                 const float* __restrict__ gamma,
                                 const float* __restrict__ beta)
{
    const int row = blockIdx.x;
    const float* x = in + (size_t)row * Dd;
    const int tid = threadIdx.x;

    float v[4];
    float s = 0.0f, s2 = 0.0f;
    #pragma unroll
    for (int i = 0; i < 4; i++){
        v[i] = x[tid + i*256];
        s  += v[i];
        s2 += v[i]*v[i];
    }
    __shared__ float r1[256], r2[256];
    r1[tid] = s; r2[tid] = s2; __syncthreads();
    for (int off = 128; off > 0; off >>= 1){
        if (tid < off){ r1[tid] += r1[tid+off]; r2[tid] += r2[tid+off]; }
        __syncthreads();
    }
    float mean = r1[0] * (1.0f/Dd);
    float var  = r2[0] * (1.0f/Dd) - mean*mean;
    float inv  = rsqrtf(var + EPSL);
    #pragma unroll
    for (int i = 0; i < 4; i++){
        int c = tid + i*256;
        float y = (v[i] - mean) * inv * gamma[c] + beta[c];
        out[(size_t)row*Dd + c] = y;
        if (oh) oh[(size_t)row*Dd + c] = __float2half_rn(y);
    }
}

// ---------------- host side ----------------
static const int SMEM_GEMM = 3 * 36864;   // 110592

struct GemmArgs {
    const __half *A, *B;
    float* Cf; __half *Ch;
    int M, N, Kd; long lda, ldb, ldc;
    float alpha; const float* add; long ldadd; const float* bias; int relu;
};

static inline void run_gemm(const GemmArgs& a){
    dim3 grid(a.N / 128, a.M / 128, 1);
    mma_gemm<<<grid, 256, SMEM_GEMM>>>(a.A, a.B, a.Cf, a.Ch,
                                       a.Kd, a.lda, a.ldb, a.ldc,
                                       a.alpha, a.add, a.ldadd, a.bias, a.relu);
}

extern "C" void kernel_launch(void* const* d_in, const int* in_sizes, int n_in,
                              void* d_out, int out_size)
{
    const float* x     = (const float*)d_in[0];
    const float* mask  = (const float*)d_in[1];
    const float* wq    = (const float*)d_in[2];
    const float* wk    = (const float*)d_in[3];
    const float* wv    = (const float*)d_in[4];
    const float* wc    = (const float*)d_in[5];
    const float* w1_w  = (const float*)d_in[6];
    const float* w1_b  = (const float*)d_in[7];
    const float* w2_w  = (const float*)d_in[8];
    const float* w2_b  = (const float*)d_in[9];
    const float* ln1_g = (const float*)d_in[10];
    const float* ln1_b = (const float*)d_in[11];
    const float* ln2_g = (const float*)d_in[12];
    const float* ln2_b = (const float*)d_in[13];
    float* out = (float*)d_out;

    cudaFuncSetAttribute((const void*)mma_gemm,     cudaFuncAttributeMaxDynamicSharedMemorySize, SMEM_GEMM);
    cudaFuncSetAttribute((const void*)flash_kernel, cudaFuncAttributeMaxDynamicSharedMemorySize, FL_SMEM);

    __half *xh,*pwqkv,*pwc,*pw1,*pw2,*pmask;
    __half *qkv,*vt,*av,*uh,*h1;
    float *attn,*u,*z;
    cudaGetSymbolAddress((void**)&xh,    g_x);
    cudaGetSymbolAddress((void**)&pwqkv, g_wqkv);
    cudaGetSymbolAddress((void**)&pwc,   g_wc);
    cudaGetSymbolAddress((void**)&pw1,   g_w1);
    cudaGetSymbolAddress((void**)&pw2,   g_w2);
    cudaGetSymbolAddress((void**)&pmask, g_maskh);
    cudaGetSymbolAddress((void**)&qkv,   g_qkv);
    cudaGetSymbolAddress((void**)&vt,    g_vt);
    cudaGetSymbolAddress((void**)&av,    g_av);
    cudaGetSymbolAddress((void**)&attn,  g_attn);
    cudaGetSymbolAddress((void**)&u,     g_u);
    cudaGetSymbolAddress((void**)&uh,    g_uh);
    cudaGetSymbolAddress((void**)&h1,    g_h1);
    cudaGetSymbolAddress((void**)&z,     g_z);

    // single fused conversion launch: x, wq|wk|wv (packed), wc, w1, w2, mask
    {
        CvtSegs s;
        const float* srcs[8] = {x, wq, wk, wv, wc, w1_w, w2_w, mask};
        __half*      dsts[8] = {xh, pwqkv, pwqkv + (size_t)Dd*Dd, pwqkv + (size_t)2*Dd*Dd,
                                pwc, pw1, pw2, pmask};
        long lens[8] = {(long)NTOK*Dd, (long)Dd*Dd, (long)Dd*Dd, (long)Dd*Dd,
                        (long)Dd*Dd, (long)Mf*Dd, (long)Mf*Dd, (long)Ss*Ss};
        long acc = 0;
        for (int i = 0; i < 8; i++){
            s.in[i]  = (const float4*)srcs[i];
            s.out[i] = (uint2*)dsts[i];
            s.start[i] = acc;
            acc += lens[i] / 4;
        }
        s.start[8] = acc;
        cvt_multi<<<(unsigned)((acc + 255) / 256), 256>>>(s);
    }

    GemmArgs a;
    // QKV = x @ wqkv^T  (one fused GEMM, N=3072)
    a = {xh,pwqkv, nullptr,qkv, NTOK,3*Dd,Dd, Dd,Dd,3*Dd, 1.0f, nullptr,0, nullptr,0};
    run_gemm(a);
    // V transpose from packed qkv
    {
        dim3 g(Ss/64, BH);
        transpose_v<<<g, 256>>>(qkv, vt);
    }
    // fused attention: av = softmax(Q K^T / 8 + mask) @ V
    {
        dim3 g(Ss/128, BH);
        flash_kernel<<<g, 256, FL_SMEM>>>(qkv, vt, pmask, av);
    }
    // attn = av @ wc^T + x  (fp32)
    a = {av,pwc, attn,nullptr, NTOK,Dd,Dd, Dd,Dd,Dd, 1.0f, x,Dd, nullptr,0};
    run_gemm(a);
    // u = LN1(attn)
    layernorm_kernel<<<NTOK, 256>>>(attn, u, uh, ln1_g, ln1_b);
    // h1 = relu(u @ w1^T + b1)
    a = {uh,pw1, nullptr,h1, NTOK,Mf,Dd, Dd,Dd,Mf, 1.0f, nullptr,0, w1_b,1};
    run_gemm(a);
    // z = h1 @ w2^T + b2 + u  (fp32)
    a = {h1,pw2, z,nullptr, NTOK,Dd,Mf, Mf,Mf,Dd, 1.0f, u,Dd, w2_b,0};
    run_gemm(a);
    // out = LN2(z)
    layernorm_kernel<<<NTOK, 256>>>(z, out, nullptr, ln2_g, ln2_b);
}

// round 11
// speedup vs baseline: 11.8532x; 1.0262x over previous
#include <cuda_runtime.h>
#include <cuda_fp16.h>
#include <cstdint>
#include <math.h>

#define Hh   16
#define Kh   64
#define Dd   1024
#define Mf   4096
#define Ss   2048
#define Bb   4
#define NTOK (Ss*Bb)      // 8192
#define BH   (Bb*Hh)      // 64
#define EPSL 1e-5f
#define LOG2E 1.44269504088896340736f
#define QSCALE (0.125f * LOG2E)

// ---------------- scratch buffers (device globals: allocation-free) ----------------
__device__ __half g_x[(size_t)NTOK*Dd];
__device__ __half g_wqkv[(size_t)3*Dd*Dd];
__device__ __half g_wc[(size_t)Dd*Dd];
__device__ __half g_w1[(size_t)Mf*Dd];
__device__ __half g_w2[(size_t)Mf*Dd];
__device__ __half g_maskh[(size_t)Ss*Ss];          // pre-scaled by log2(e)
__device__ __half g_qkv[(size_t)NTOK*3*Dd];        // Q section pre-scaled by 0.125*log2(e)
__device__ __half g_vt[(size_t)BH*Kh*Ss];
__device__ __half g_av[(size_t)NTOK*Dd];
__device__ float  g_attn[(size_t)NTOK*Dd];
__device__ float  g_u[(size_t)NTOK*Dd];
__device__ __half g_uh[(size_t)NTOK*Dd];
__device__ __half g_h1[(size_t)NTOK*Mf];
__device__ float  g_z[(size_t)NTOK*Dd];

// ---------------- helpers ----------------
__device__ __forceinline__ uint32_t smem_u32(const void* p){
    uint32_t a;
    asm("{ .reg .u64 t; cvta.to.shared.u64 t, %1; cvt.u32.u64 %0, t; }" : "=r"(a) : "l"(p));
    return a;
}
__device__ __forceinline__ uint32_t packf2(float lo, float hi){
    uint32_t r;
    asm("cvt.rn.f16x2.f32 %0, %1, %2;" : "=r"(r) : "f"(hi), "f"(lo));
    return r;
}
__device__ __forceinline__ void cpasync16(uint32_t saddr, const void* gaddr){
    asm volatile("cp.async.cg.shared.global [%0], [%1], 16;" :: "r"(saddr), "l"(gaddr) : "memory");
}
__device__ __forceinline__ void ldmx4(uint32_t* r, uint32_t addr){
    asm volatile("ldmatrix.sync.aligned.m8n8.x4.shared.b16 {%0,%1,%2,%3}, [%4];"
                 : "=r"(r[0]), "=r"(r[1]), "=r"(r[2]), "=r"(r[3]) : "r"(addr));
}
__device__ __forceinline__ void mma16816(float* c, const uint32_t* a, const uint32_t* b){
    asm volatile("mma.sync.aligned.m16n8k16.row.col.f32.f16.f16.f32 "
                 "{%0,%1,%2,%3}, {%4,%5,%6,%7}, {%8,%9}, {%0,%1,%2,%3};"
                 : "+f"(c[0]), "+f"(c[1]), "+f"(c[2]), "+f"(c[3])
                 : "r"(a[0]), "r"(a[1]), "r"(a[2]), "r"(a[3]), "r"(b[0]), "r"(b[1]));
}

// ---------------- mma.sync fp16 NT GEMM, BK=64, 3-stage pipeline ----------------
// qkvMode: scale cols < 1024 by QSCALE (Q pre-scale), others by 1.0
__global__ void __launch_bounds__(256) mma_gemm(
    const __half* __restrict__ A, const __half* __restrict__ B,
    float* __restrict__ Cf, __half* __restrict__ Ch,
    int Kd, long lda, long ldb, long ldc,
    float alpha, const float* __restrict__ add, long ldadd,
    const float* __restrict__ bias, int doRelu, int qkvMode)
{
    constexpr int BN   = 128;
    constexpr int BK   = 64;
    constexpr int LDS  = BK + 8;
    constexpr int WN   = BN / 2;
    constexpr int NT   = WN / 8;
    constexpr int A_BYTES = 128 * LDS * 2;
    constexpr int B_BYTES = BN  * LDS * 2;
    constexpr int STAGE   = A_BYTES + B_BYTES;

    extern __shared__ char smc[];
    const uint32_t sbase = smem_u32(smc);

    const int tid  = threadIdx.x;
    const int lane = tid & 31;
    const int wid  = tid >> 5;
    const int warpM = (wid & 3) * 32;
    const int warpN = (wid >> 2) * WN;

    const int  m0   = blockIdx.y * 128;
    const int  n0   = blockIdx.x * BN;
    const int  KT   = Kd / BK;

    const int la_row = tid >> 3, la_ch = tid & 7;
    auto load_stage = [&](int kt, int buf){
        const int k0 = kt * BK;
        const uint32_t s0 = sbase + buf * STAGE;
        #pragma unroll
        for (int it = 0; it < 4; it++){
            int row = la_row + it * 32;
            long g = (long)(m0 + row) * lda + k0 + la_ch * 8;
            uint32_t so = (uint32_t)(row * (LDS * 2) + la_ch * 16);
            cpasync16(s0 + so, A + g);
        }
        #pragma unroll
        for (int it = 0; it < 4; it++){
            int row = la_row + it * 32;
            long g = (long)(n0 + row) * ldb + k0 + la_ch * 8;
            uint32_t so = (uint32_t)(row * (LDS * 2) + la_ch * 16);
            cpasync16(s0 + A_BYTES + so, B + g);
        }
    };

    load_stage(0, 0);
    asm volatile("cp.async.commit_group;" ::: "memory");
    load_stage(1, 1);
    asm volatile("cp.async.commit_group;" ::: "memory");

    float acc[2][NT][4];
    #pragma unroll
    for (int i = 0; i < 2; i++)
        #pragma unroll
        for (int j = 0; j < NT; j++)
            #pragma unroll
            for (int e = 0; e < 4; e++) acc[i][j][e] = 0.0f;

    const int aRow = (lane & 15), aColHalf = (lane >> 4) * 8;
    const int bRow = (lane >> 4) * 8 + (lane & 7), bColHalf = ((lane >> 3) & 1) * 8;

    int buf = 0;
    for (int kt = 0; kt < KT; kt++){
        asm volatile("cp.async.wait_group 1;" ::: "memory");
        __syncthreads();
        const uint32_t sA0 = sbase + buf * STAGE;
        const uint32_t sB0 = sA0 + A_BYTES;

        #pragma unroll
        for (int ks = 0; ks < 4; ks++){
            const int k16 = ks * 16;
            uint32_t af[2][4];
            #pragma unroll
            for (int mt = 0; mt < 2; mt++){
                uint32_t addr = sA0 + (uint32_t)(((warpM + mt*16 + aRow) * LDS + k16 + aColHalf) * 2);
                ldmx4(af[mt], addr);
            }
            uint32_t bf[NT][2];
            #pragma unroll
            for (int g = 0; g < NT/2; g++){
                uint32_t addr = sB0 + (uint32_t)(((warpN + g*16 + bRow) * LDS + k16 + bColHalf) * 2);
                uint32_t r[4];
                ldmx4(r, addr);
                bf[2*g][0] = r[0]; bf[2*g][1] = r[1];
                bf[2*g+1][0] = r[2]; bf[2*g+1][1] = r[3];
            }
            #pragma unroll
            for (int mt = 0; mt < 2; mt++)
                #pragma unroll
                for (int j = 0; j < NT; j++)
                    mma16816(acc[mt][j], af[mt], bf[j]);
        }
        if (kt + 2 < KT){
            int nbuf = buf + 2; if (nbuf >= 3) nbuf -= 3;
            load_stage(kt + 2, nbuf);
        }
        asm volatile("cp.async.commit_group;" ::: "memory");
        if (++buf == 3) buf = 0;
    }

    #pragma unroll
    for (int mt = 0; mt < 2; mt++){
        #pragma unroll
        for (int j = 0; j < NT; j++){
            const int col = n0 + warpN + j*8 + (lane & 3) * 2;
            const float sc = qkvMode ? (((col % 3072) < 1024) ? QSCALE : 1.0f) : alpha;
            const float b0 = bias ? bias[col]   : 0.0f;
            const float b1 = bias ? bias[col+1] : 0.0f;
            #pragma unroll
            for (int half = 0; half < 2; half++){
                const long row = m0 + warpM + mt*16 + (lane >> 2) + half*8;
                float v0 = acc[mt][j][half*2+0] * sc + b0;
                float v1 = acc[mt][j][half*2+1] * sc + b1;
                if (add){
                    v0 += add[row * ldadd + col];
                    v1 += add[row * ldadd + col + 1];
                }
                if (doRelu){ v0 = fmaxf(v0, 0.0f); v1 = fmaxf(v1, 0.0f); }
                const long ci = row * ldc + col;
                if (Ch){
                    *(uint32_t*)(Ch + ci) = packf2(v0, v1);
                } else {
                    *(float2*)(Cf + ci) = make_float2(v0, v1);
                }
            }
        }
    }
}

// ---------------- fused flash attention (fp16, exp2-domain, t-tile 64, 3-stage) ----------------
#define FL_LQ 72
#define FL_QBYTES (128*FL_LQ*2)
#define FL_KB (64*FL_LQ*2)
#define FL_VB (64*FL_LQ*2)
#define FL_STAGE (FL_KB + FL_VB)
#define FL_SMQ   0
#define FL_SMST  FL_QBYTES
#define FL_SMEM  (FL_SMST + 3*FL_STAGE)      // 73728

__global__ void __launch_bounds__(256,2) flash_kernel(
    const __half* __restrict__ QKV,
    const __half* __restrict__ Vt,
    const __half* __restrict__ maskh,
    __half* __restrict__ AV)
{
    extern __shared__ char smc[];
    const uint32_t sbase = smem_u32(smc);
    const int tid = threadIdx.x, lane = tid & 31, wid = tid >> 5;
    const int q0 = blockIdx.x * 128;
    const int z  = blockIdx.y;
    const long qOff = (long)(z >> 4) * 3072 + (long)(z & 15) * 64;
    const long kOff = qOff + 1024;

    auto load_q = [&](){
        #pragma unroll
        for (int it = 0; it < 4; it++){
            int idx = it*256 + tid;
            int row = idx >> 3, ch = idx & 7;
            long g = (long)(q0 + row) * 12288 + qOff + ch*8;
            uint32_t so = sbase + FL_SMQ + (uint32_t)(row*FL_LQ*2 + ch*16);
            cpasync16(so, QKV + g);
        }
    };
    auto load_stage = [&](int kt, int buf){
        const int t0 = kt * 64;
        const uint32_t s0 = sbase + FL_SMST + buf*FL_STAGE;
        #pragma unroll
        for (int it = 0; it < 2; it++){
            int idx = it*256 + tid;
            int row = idx >> 3, ch = idx & 7;
            long g = (long)(t0 + row) * 12288 + kOff + ch*8;
            uint32_t so = s0 + (uint32_t)(row*FL_LQ*2 + ch*16);
            cpasync16(so, QKV + g);
        }
        const uint32_t v0 = s0 + FL_KB;
        #pragma unroll
        for (int it = 0; it < 2; it++){
            int idx = it*256 + tid;
            int row = idx >> 3, ch = idx & 7;
            long g = (long)z*64*2048 + (long)row*2048 + t0 + ch*8;
            uint32_t so = v0 + (uint32_t)(row*FL_LQ*2 + ch*16);
            cpasync16(so, Vt + g);
        }
    };

    load_q();
    load_stage(0, 0);
    asm volatile("cp.async.commit_group;" ::: "memory");
    load_stage(1, 1);
    asm volatile("cp.async.commit_group;" ::: "memory");
    asm volatile("cp.async.wait_group 1;" ::: "memory");
    __syncthreads();

    const int aRow = lane & 15, aCol = (lane >> 4) * 8;
    const int bRow = (lane >> 4) * 8 + (lane & 7), bCol = ((lane >> 3) & 1) * 8;

    uint32_t qf[4][4];
    #pragma unroll
    for (int kc = 0; kc < 4; kc++){
        uint32_t addr = sbase + FL_SMQ + (uint32_t)(((wid*16 + aRow)*FL_LQ + kc*16 + aCol) * 2);
        ldmx4(qf[kc], addr);
    }

    float O[8][4];
    #pragma unroll
    for (int j = 0; j < 8; j++){ O[j][0]=0; O[j][1]=0; O[j][2]=0; O[j][3]=0; }
    float m0 = -INFINITY, m1 = -INFINITY, l0 = 0.0f, l1 = 0.0f;
    const int rloc = wid*16 + (lane >> 2);

    int buf = 0;
    for (int kt = 0; kt < 32; kt++){
        asm volatile("cp.async.wait_group 1;" ::: "memory");
        __syncthreads();
        const uint32_t sK = sbase + FL_SMST + buf*FL_STAGE;
        const uint32_t sV = sK + FL_KB;

        float S[8][4];
        #pragma unroll
        for (int j = 0; j < 8; j++){ S[j][0]=0; S[j][1]=0; S[j][2]=0; S[j][3]=0; }

        // S = Qs @ K^T  (already in exp2 domain; Q pre-scaled by 0.125*log2e)
        #pragma unroll
        for (int kc = 0; kc < 4; kc++){
            #pragma unroll
            for (int g = 0; g < 4; g++){
                uint32_t addr = sK + (uint32_t)(((g*16 + bRow)*FL_LQ + kc*16 + bCol) * 2);
                uint32_t bk[4];
                ldmx4(bk, addr);
                mma16816(S[2*g],   qf[kc], bk+0);
                mma16816(S[2*g+1], qf[kc], bk+2);
            }
        }

        // + mask(pre-scaled log2e) + running max (exp2 domain)
        const int t0 = kt * 64;
        const long mr0 = (long)(q0 + rloc) * 2048 + t0;
        const long mr1 = mr0 + 8 * 2048;
        float mx0 = -INFINITY, mx1 = -INFINITY;
        #pragma unroll
        for (int j = 0; j < 8; j++){
            int c = j*8 + (lane & 3)*2;
            float2 k0v = __half22float2(*(const __half2*)(maskh + mr0 + c));
            float2 k1v = __half22float2(*(const __half2*)(maskh + mr1 + c));
            S[j][0] += k0v.x;
            S[j][1] += k0v.y;
            S[j][2] += k1v.x;
            S[j][3] += k1v.y;
            mx0 = fmaxf(mx0, fmaxf(S[j][0], S[j][1]));
            mx1 = fmaxf(mx1, fmaxf(S[j][2], S[j][3]));
        }
        mx0 = fmaxf(mx0, __shfl_xor_sync(0xFFFFFFFFu, mx0, 1));
        mx0 = fmaxf(mx0, __shfl_xor_sync(0xFFFFFFFFu, mx0, 2));
        mx1 = fmaxf(mx1, __shfl_xor_sync(0xFFFFFFFFu, mx1, 1));
        mx1 = fmaxf(mx1, __shfl_xor_sync(0xFFFFFFFFu, mx1, 2));
        float nm0 = fmaxf(m0, mx0), nm1 = fmaxf(m1, mx1);
        float f0 = (m0 > -INFINITY) ? exp2f(m0 - nm0) : 0.0f;
        float f1 = (m1 > -INFINITY) ? exp2f(m1 - nm1) : 0.0f;
        m0 = nm0; m1 = nm1;

        float s0 = 0.0f, s1 = 0.0f;
        #pragma unroll
        for (int j = 0; j < 8; j++){
            S[j][0] = exp2f(S[j][0] - m0);
            S[j][1] = exp2f(S[j][1] - m0);
            S[j][2] = exp2f(S[j][2] - m1);
            S[j][3] = exp2f(S[j][3] - m1);
            s0 += S[j][0] + S[j][1];
            s1 += S[j][2] + S[j][3];
        }
        s0 += __shfl_xor_sync(0xFFFFFFFFu, s0, 1);
        s0 += __shfl_xor_sync(0xFFFFFFFFu, s0, 2);
        s1 += __shfl_xor_sync(0xFFFFFFFFu, s1, 1);
        s1 += __shfl_xor_sync(0xFFFFFFFFu, s1, 2);
        l0 = l0*f0 + s0;
        l1 = l1*f1 + s1;
        #pragma unroll
        for (int j = 0; j < 8; j++){
            O[j][0]*=f0; O[j][1]*=f0; O[j][2]*=f1; O[j][3]*=f1;
        }

        // O += P @ V   (single-instruction fp16x2 packs)
        #pragma unroll
        for (int kc = 0; kc < 4; kc++){
            uint32_t ph[4];
            ph[0] = packf2(S[2*kc][0],   S[2*kc][1]);
            ph[1] = packf2(S[2*kc][2],   S[2*kc][3]);
            ph[2] = packf2(S[2*kc+1][0], S[2*kc+1][1]);
            ph[3] = packf2(S[2*kc+1][2], S[2*kc+1][3]);
            #pragma unroll
            for (int g = 0; g < 4; g++){
                uint32_t addr = sV + (uint32_t)(((g*16 + bRow)*FL_LQ + kc*16 + bCol) * 2);
                uint32_t vf[4];
                ldmx4(vf, addr);
                mma16816(O[2*g],   ph, vf+0);
                mma16816(O[2*g+1], ph, vf+2);
            }
        }

        if (kt + 2 < 32){
            int nbuf = buf + 2; if (nbuf >= 3) nbuf -= 3;
            load_stage(kt + 2, nbuf);
        }
        asm volatile("cp.async.commit_group;" ::: "memory");
        if (++buf == 3) buf = 0;
    }

    // finalize: O /= l, write av (fp16) as [Ss, 4096]
    const long hOff = (long)z * 64;
    const float inv0 = 1.0f / l0, inv1 = 1.0f / l1;
    #pragma unroll
    for (int j = 0; j < 8; j++){
        const int col = j*8 + (lane & 3)*2;
        const long a0 = (long)(q0 + rloc) * 4096 + hOff + col;
        const long a1 = a0 + 8L * 4096;
        *(uint32_t*)(AV + a0) = packf2(O[j][0]*inv0, O[j][1]*inv0);
        *(uint32_t*)(AV + a1) = packf2(O[j][2]*inv1, O[j][3]*inv1);
    }
}

// ---------------- fused fp32 -> fp16 conversion (seg 7 = mask, pre-scaled by log2e) ----------------
struct CvtSegs {
    const float4* in[8];
    uint2*        out[8];
    long          start[9];
};
__global__ void cvt_multi(CvtSegs s)
{
    long i = (long)blockIdx.x * 256 + threadIdx.x;
    if (i >= s.start[8]) return;
    int seg = 0;
    #pragma unroll
    for (int k = 1; k < 8; k++) if (i >= s.start[k]) seg = k;
    long j = i - s.start[seg];
    float4 v = s.in[seg][j];
    float sc = (seg == 7) ? LOG2E : 1.0f;
    uint2 H;
    H.x = packf2(v.x * sc, v.y * sc);
    H.y = packf2(v.z * sc, v.w * sc);
    s.out[seg][j] = H;
}

// ---------------- V transpose (fp16): qkv V section -> vt[z][kk][t] ----------------
__global__ void transpose_v(const __half* __restrict__ qkv, __half* __restrict__ vt)
{
    __shared__ __half t[64][72];
    const int z  = blockIdx.y;
    const int t0 = blockIdx.x * 64;
    const int b  = z >> 4, h = z & 15;
    const __half* src = qkv + 2048 + (size_t)b*3072 + (size_t)h*64;
    for (int it = 0; it < 16; it++){
        int idx = it*256 + threadIdx.x;
        int ti = idx >> 6, kk = idx & 63;
        t[ti][kk] = src[(size_t)(t0 + ti)*12288 + kk];
    }
    __syncthreads();
    size_t obase = (size_t)z * Kh * Ss + t0;
    for (int it = 0; it < 16; it++){
        int idx = it*256 + threadIdx.x;
        int kk = idx >> 6, ti = idx & 63;
        vt[obase + (size_t)kk*Ss + ti] = t[ti][kk];
    }
}

// ---------------- layernorm over D=1024; optional fp16 output ----------------
__global__ void layernorm_kernel(const float* __restrict__ in,
                                 float* __restrict__ out,
                                 __half* __restrict__ oh,
                                 const float* __restrict__ gamma,
                                 const float* __restrict__ beta)
{
    const int row = blockIdx.x;
    const float* x = in + (size_t)row * Dd;
    const int tid = threadIdx.x;

    float v[4];
    float s = 0.0f, s2 = 0.0f;
    #pragma unroll
    for (int i = 0; i < 4; i++){
        v[i] = x[tid + i*256];
        s  += v[i];
        s2 += v[i]*v[i];
    }
    __shared__ float r1[256], r2[256];
    r1[tid] = s; r2[tid] = s2; __syncthreads();
    for (int off = 128; off > 0; off >>= 1){
        if (tid < off){ r1[tid] += r1[tid+off]; r2[tid] += r2[tid+off]; }
        __syncthreads();
    }
    float mean = r1[0] * (1.0f/Dd);
    float var  = r2[0] * (1.0f/Dd) - mean*mean;
    float inv  = rsqrtf(var + EPSL);
    #pragma unroll
    for (int i = 0; i < 4; i++){
        int c = tid + i*256;
        float y = (v[i] - mean) * inv * gamma[c] + beta[c];
        out[(size_t)row*Dd + c] = y;
        if (oh) oh[(size_t)row*Dd + c] = __float2half_rn(y);
    }
}

// ---------------- host side ----------------
static const int SMEM_GEMM = 3 * 36864;   // 110592

struct GemmArgs {
    const __half *A, *B;
    float* Cf; __half *Ch;
    int M, N, Kd; long lda, ldb, ldc;
    float alpha; const float* add; long ldadd; const float* bias; int relu; int qkvMode;
};

static inline void run_gemm(const GemmArgs& a){
    dim3 grid(a.N / 128, a.M / 128, 1);
    mma_gemm<<<grid, 256, SMEM_GEMM>>>(a.A, a.B, a.Cf, a.Ch,
                                       a.Kd, a.lda, a.ldb, a.ldc,
                                       a.alpha, a.add, a.ldadd, a.bias, a.relu, a.qkvMode);
}

extern "C" void kernel_launch(void* const* d_in, const int* in_sizes, int n_in,
                              void* d_out, int out_size)
{
    const float* x     = (const float*)d_in[0];
    const float* mask  = (const float*)d_in[1];
    const float* wq    = (const float*)d_in[2];
    const float* wk    = (const float*)d_in[3];
    const float* wv    = (const float*)d_in[4];
    const float* wc    = (const float*)d_in[5];
    const float* w1_w  = (const float*)d_in[6];
    const float* w1_b  = (const float*)d_in[7];
    const float* w2_w  = (const float*)d_in[8];
    const float* w2_b  = (const float*)d_in[9];
    const float* ln1_g = (const float*)d_in[10];
    const float* ln1_b = (const float*)d_in[11];
    const float* ln2_g = (const float*)d_in[12];
    const float* ln2_b = (const float*)d_in[13];
    float* out = (float*)d_out;

    cudaFuncSetAttribute((const void*)mma_gemm,     cudaFuncAttributeMaxDynamicSharedMemorySize, SMEM_GEMM);
    cudaFuncSetAttribute((const void*)flash_kernel, cudaFuncAttributeMaxDynamicSharedMemorySize, FL_SMEM);

    __half *xh,*pwqkv,*pwc,*pw1,*pw2,*pmask;
    __half *qkv,*vt,*av,*uh,*h1;
    float *attn,*u,*z;
    cudaGetSymbolAddress((void**)&xh,    g_x);
    cudaGetSymbolAddress((void**)&pwqkv, g_wqkv);
    cudaGetSymbolAddress((void**)&pwc,   g_wc);
    cudaGetSymbolAddress((void**)&pw1,   g_w1);
    cudaGetSymbolAddress((void**)&pw2,   g_w2);
    cudaGetSymbolAddress((void**)&pmask, g_maskh);
    cudaGetSymbolAddress((void**)&qkv,   g_qkv);
    cudaGetSymbolAddress((void**)&vt,    g_vt);
    cudaGetSymbolAddress((void**)&av,    g_av);
    cudaGetSymbolAddress((void**)&attn,  g_attn);
    cudaGetSymbolAddress((void**)&u,     g_u);
    cudaGetSymbolAddress((void**)&uh,    g_uh);
    cudaGetSymbolAddress((void**)&h1,    g_h1);
    cudaGetSymbolAddress((void**)&z,     g_z);

    // single fused conversion launch: x, wq|wk|wv (packed), wc, w1, w2, mask(*log2e)
    {
        CvtSegs s;
        const float* srcs[8] = {x, wq, wk, wv, wc, w1_w, w2_w, mask};
        __half*      dsts[8] = {xh, pwqkv, pwqkv + (size_t)Dd*Dd, pwqkv + (size_t)2*Dd*Dd,
                                pwc, pw1, pw2, pmask};
        long lens[8] = {(long)NTOK*Dd, (long)Dd*Dd, (long)Dd*Dd, (long)Dd*Dd,
                        (long)Dd*Dd, (long)Mf*Dd, (long)Mf*Dd, (long)Ss*Ss};
        long acc = 0;
        for (int i = 0; i < 8; i++){
            s.in[i]  = (const float4*)srcs[i];
            s.out[i] = (uint2*)dsts[i];
            s.start[i] = acc;
            acc += lens[i] / 4;
        }
        s.start[8] = acc;
        cvt_multi<<<(unsigned)((acc + 255) / 256), 256>>>(s);
    }

    GemmArgs a;
    // QKV = x @ wqkv^T  (Q section pre-scaled by 0.125*log2e)
    a = {xh,pwqkv, nullptr,qkv, NTOK,3*Dd,Dd, Dd,Dd,3*Dd, 1.0f, nullptr,0, nullptr,0, 1};
    run_gemm(a);
    // V transpose from packed qkv
    {
        dim3 g(Ss/64, BH);
        transpose_v<<<g, 256>>>(qkv, vt);
    }
    // fused attention: av = softmax(Q K^T / 8 + mask) @ V
    {
        dim3 g(Ss/128, BH);
        flash_kernel<<<g, 256, FL_SMEM>>>(qkv, vt, pmask, av);
    }
    // attn = av @ wc^T + x  (fp32)
    a = {av,pwc, attn,nullptr, NTOK,Dd,Dd, Dd,Dd,Dd, 1.0f, x,Dd, nullptr,0, 0};
    run_gemm(a);
    // u = LN1(attn)
    layernorm_kernel<<<NTOK, 256>>>(attn, u, uh, ln1_g, ln1_b);
    // h1 = relu(u @ w1^T + b1)
    a = {uh,pw1, nullptr,h1, NTOK,Mf,Dd, Dd,Dd,Mf, 1.0f, nullptr,0, w1_b,1, 0};
    run_gemm(a);
    // z = h1 @ w2^T + b2 + u  (fp32)
    a = {h1,pw2, z,nullptr, NTOK,Dd,Mf, Mf,Mf,Dd, 1.0f, u,Dd, w2_b,0, 0};
    run_gemm(a);
    // out = LN2(z)
    layernorm_kernel<<<NTOK, 256>>>(z, out, nullptr, ln2_g, ln2_b);
}

// round 12
// speedup vs baseline: 11.9702x; 1.0099x over previous
#include <cuda_runtime.h>
#include <cuda_fp16.h>
#include <cstdint>
#include <math.h>

#define Hh   16
#define Kh   64
#define Dd   1024
#define Mf   4096
#define Ss   2048
#define Bb   4
#define NTOK (Ss*Bb)      // 8192
#define BH   (Bb*Hh)      // 64
#define EPSL 1e-5f
#define LOG2E 1.44269504088896340736f
#define QSCALE (0.125f * LOG2E)

// ---------------- scratch buffers (device globals: allocation-free) ----------------
__device__ __half g_x[(size_t)NTOK*Dd];
__device__ __half g_wqkv[(size_t)3*Dd*Dd];
__device__ __half g_wc[(size_t)Dd*Dd];
__device__ __half g_w1[(size_t)Mf*Dd];
__device__ __half g_w2[(size_t)Mf*Dd];
__device__ __half g_maskh[(size_t)Ss*Ss];          // pre-scaled by log2(e)
__device__ __half g_qkv[(size_t)NTOK*3*Dd];        // Q section pre-scaled by 0.125*log2(e)
__device__ __half g_vt[(size_t)BH*Kh*Ss];
__device__ __half g_av[(size_t)NTOK*Dd];
__device__ float  g_attn[(size_t)NTOK*Dd];
__device__ float  g_u[(size_t)NTOK*Dd];
__device__ __half g_uh[(size_t)NTOK*Dd];
__device__ __half g_h1[(size_t)NTOK*Mf];
__device__ float  g_z[(size_t)NTOK*Dd];

// ---------------- helpers ----------------
__device__ __forceinline__ uint32_t smem_u32(const void* p){
    uint32_t a;
    asm("{ .reg .u64 t; cvta.to.shared.u64 t, %1; cvt.u32.u64 %0, t; }" : "=r"(a) : "l"(p));
    return a;
}
__device__ __forceinline__ uint32_t packf2(float lo, float hi){
    uint32_t r;
    asm("cvt.rn.f16x2.f32 %0, %1, %2;" : "=r"(r) : "f"(hi), "f"(lo));
    return r;
}
__device__ __forceinline__ uint32_t ex2h2(uint32_t x){
    uint32_t r;
    asm("ex2.approx.f16x2 %0, %1;" : "=r"(r) : "r"(x));
    return r;
}
__device__ __forceinline__ void cpasync16(uint32_t saddr, const void* gaddr){
    asm volatile("cp.async.cg.shared.global [%0], [%1], 16;" :: "r"(saddr), "l"(gaddr) : "memory");
}
__device__ __forceinline__ void ldmx4(uint32_t* r, uint32_t addr){
    asm volatile("ldmatrix.sync.aligned.m8n8.x4.shared.b16 {%0,%1,%2,%3}, [%4];"
                 : "=r"(r[0]), "=r"(r[1]), "=r"(r[2]), "=r"(r[3]) : "r"(addr));
}
__device__ __forceinline__ void mma16816(float* c, const uint32_t* a, const uint32_t* b){
    asm volatile("mma.sync.aligned.m16n8k16.row.col.f32.f16.f16.f32 "
                 "{%0,%1,%2,%3}, {%4,%5,%6,%7}, {%8,%9}, {%0,%1,%2,%3};"
                 : "+f"(c[0]), "+f"(c[1]), "+f"(c[2]), "+f"(c[3])
                 : "r"(a[0]), "r"(a[1]), "r"(a[2]), "r"(a[3]), "r"(b[0]), "r"(b[1]));
}

// ---------------- mma.sync fp16 NT GEMM, BK=64, 3-stage pipeline ----------------
__global__ void __launch_bounds__(256) mma_gemm(
    const __half* __restrict__ A, const __half* __restrict__ B,
    float* __restrict__ Cf, __half* __restrict__ Ch,
    int Kd, long lda, long ldb, long ldc,
    float alpha, const float* __restrict__ add, long ldadd,
    const float* __restrict__ bias, int doRelu, int qkvMode)
{
    constexpr int BN   = 128;
    constexpr int BK   = 64;
    constexpr int LDS  = BK + 8;
    constexpr int WN   = BN / 2;
    constexpr int NT   = WN / 8;
    constexpr int A_BYTES = 128 * LDS * 2;
    constexpr int B_BYTES = BN  * LDS * 2;
    constexpr int STAGE   = A_BYTES + B_BYTES;

    extern __shared__ char smc[];
    const uint32_t sbase = smem_u32(smc);

    const int tid  = threadIdx.x;
    const int lane = tid & 31;
    const int wid  = tid >> 5;
    const int warpM = (wid & 3) * 32;
    const int warpN = (wid >> 2) * WN;

    const int  m0   = blockIdx.y * 128;
    const int  n0   = blockIdx.x * BN;
    const int  KT   = Kd / BK;

    const int la_row = tid >> 3, la_ch = tid & 7;
    auto load_stage = [&](int kt, int buf){
        const int k0 = kt * BK;
        const uint32_t s0 = sbase + buf * STAGE;
        #pragma unroll
        for (int it = 0; it < 4; it++){
            int row = la_row + it * 32;
            long g = (long)(m0 + row) * lda + k0 + la_ch * 8;
            uint32_t so = (uint32_t)(row * (LDS * 2) + la_ch * 16);
            cpasync16(s0 + so, A + g);
        }
        #pragma unroll
        for (int it = 0; it < 4; it++){
            int row = la_row + it * 32;
            long g = (long)(n0 + row) * ldb + k0 + la_ch * 8;
            uint32_t so = (uint32_t)(row * (LDS * 2) + la_ch * 16);
            cpasync16(s0 + A_BYTES + so, B + g);
        }
    };

    load_stage(0, 0);
    asm volatile("cp.async.commit_group;" ::: "memory");
    load_stage(1, 1);
    asm volatile("cp.async.commit_group;" ::: "memory");

    float acc[2][NT][4];
    #pragma unroll
    for (int i = 0; i < 2; i++)
        #pragma unroll
        for (int j = 0; j < NT; j++)
            #pragma unroll
            for (int e = 0; e < 4; e++) acc[i][j][e] = 0.0f;

    const int aRow = (lane & 15), aColHalf = (lane >> 4) * 8;
    const int bRow = (lane >> 4) * 8 + (lane & 7), bColHalf = ((lane >> 3) & 1) * 8;

    int buf = 0;
    for (int kt = 0; kt < KT; kt++){
        asm volatile("cp.async.wait_group 1;" ::: "memory");
        __syncthreads();
        const uint32_t sA0 = sbase + buf * STAGE;
        const uint32_t sB0 = sA0 + A_BYTES;

        #pragma unroll
        for (int ks = 0; ks < 4; ks++){
            const int k16 = ks * 16;
            uint32_t af[2][4];
            #pragma unroll
            for (int mt = 0; mt < 2; mt++){
                uint32_t addr = sA0 + (uint32_t)(((warpM + mt*16 + aRow) * LDS + k16 + aColHalf) * 2);
                ldmx4(af[mt], addr);
            }
            uint32_t bf[NT][2];
            #pragma unroll
            for (int g = 0; g < NT/2; g++){
                uint32_t addr = sB0 + (uint32_t)(((warpN + g*16 + bRow) * LDS + k16 + bColHalf) * 2);
                uint32_t r[4];
                ldmx4(r, addr);
                bf[2*g][0] = r[0]; bf[2*g][1] = r[1];
                bf[2*g+1][0] = r[2]; bf[2*g+1][1] = r[3];
            }
            #pragma unroll
            for (int mt = 0; mt < 2; mt++)
                #pragma unroll
                for (int j = 0; j < NT; j++)
                    mma16816(acc[mt][j], af[mt], bf[j]);
        }
        if (kt + 2 < KT){
            int nbuf = buf + 2; if (nbuf >= 3) nbuf -= 3;
            load_stage(kt + 2, nbuf);
        }
        asm volatile("cp.async.commit_group;" ::: "memory");
        if (++buf == 3) buf = 0;
    }

    #pragma unroll
    for (int mt = 0; mt < 2; mt++){
        #pragma unroll
        for (int j = 0; j < NT; j++){
            const int col = n0 + warpN + j*8 + (lane & 3) * 2;
            const float sc = qkvMode ? (((col % 3072) < 1024) ? QSCALE : 1.0f) : alpha;
            const float b0 = bias ? bias[col]   : 0.0f;
            const float b1 = bias ? bias[col+1] : 0.0f;
            #pragma unroll
            for (int half = 0; half < 2; half++){
                const long row = m0 + warpM + mt*16 + (lane >> 2) + half*8;
                float v0 = acc[mt][j][half*2+0] * sc + b0;
                float v1 = acc[mt][j][half*2+1] * sc + b1;
                if (add){
                    v0 += add[row * ldadd + col];
                    v1 += add[row * ldadd + col + 1];
                }
                if (doRelu){ v0 = fmaxf(v0, 0.0f); v1 = fmaxf(v1, 0.0f); }
                const long ci = row * ldc + col;
                if (Ch){
                    *(uint32_t*)(Ch + ci) = packf2(v0, v1);
                } else {
                    *(float2*)(Cf + ci) = make_float2(v0, v1);
                }
            }
        }
    }
}

// ---------------- fused flash attention (exp2-domain, l-via-MMA, f16x2 exp) ----------------
#define FL_LQ 72
#define FL_QBYTES (128*FL_LQ*2)
#define FL_KB (64*FL_LQ*2)
#define FL_VB (64*FL_LQ*2)
#define FL_STAGE (FL_KB + FL_VB)
#define FL_SMQ   0
#define FL_SMST  FL_QBYTES
#define FL_SMEM  (FL_SMST + 3*FL_STAGE)      // 73728

__global__ void __launch_bounds__(256,2) flash_kernel(
    const __half* __restrict__ QKV,
    const __half* __restrict__ Vt,
    const __half* __restrict__ maskh,
    __half* __restrict__ AV)
{
    extern __shared__ char smc[];
    const uint32_t sbase = smem_u32(smc);
    const int tid = threadIdx.x, lane = tid & 31, wid = tid >> 5;
    const int q0 = blockIdx.x * 128;
    const int z  = blockIdx.y;
    const long qOff = (long)(z >> 4) * 3072 + (long)(z & 15) * 64;
    const long kOff = qOff + 1024;

    auto load_q = [&](){
        #pragma unroll
        for (int it = 0; it < 4; it++){
            int idx = it*256 + tid;
            int row = idx >> 3, ch = idx & 7;
            long g = (long)(q0 + row) * 12288 + qOff + ch*8;
            uint32_t so = sbase + FL_SMQ + (uint32_t)(row*FL_LQ*2 + ch*16);
            cpasync16(so, QKV + g);
        }
    };
    auto load_stage = [&](int kt, int buf){
        const int t0 = kt * 64;
        const uint32_t s0 = sbase + FL_SMST + buf*FL_STAGE;
        #pragma unroll
        for (int it = 0; it < 2; it++){
            int idx = it*256 + tid;
            int row = idx >> 3, ch = idx & 7;
            long g = (long)(t0 + row) * 12288 + kOff + ch*8;
            uint32_t so = s0 + (uint32_t)(row*FL_LQ*2 + ch*16);
            cpasync16(so, QKV + g);
        }
        const uint32_t v0 = s0 + FL_KB;
        #pragma unroll
        for (int it = 0; it < 2; it++){
            int idx = it*256 + tid;
            int row = idx >> 3, ch = idx & 7;
            long g = (long)z*64*2048 + (long)row*2048 + t0 + ch*8;
            uint32_t so = v0 + (uint32_t)(row*FL_LQ*2 + ch*16);
            cpasync16(so, Vt + g);
        }
    };

    load_q();
    load_stage(0, 0);
    asm volatile("cp.async.commit_group;" ::: "memory");
    load_stage(1, 1);
    asm volatile("cp.async.commit_group;" ::: "memory");
    asm volatile("cp.async.wait_group 1;" ::: "memory");
    __syncthreads();

    const int aRow = lane & 15, aCol = (lane >> 4) * 8;
    const int bRow = (lane >> 4) * 8 + (lane & 7), bCol = ((lane >> 3) & 1) * 8;

    uint32_t qf[4][4];
    #pragma unroll
    for (int kc = 0; kc < 4; kc++){
        uint32_t addr = sbase + FL_SMQ + (uint32_t)(((wid*16 + aRow)*FL_LQ + kc*16 + aCol) * 2);
        ldmx4(qf[kc], addr);
    }

    float O[8][4];
    #pragma unroll
    for (int j = 0; j < 8; j++){ O[j][0]=0; O[j][1]=0; O[j][2]=0; O[j][3]=0; }
    float lacc[4] = {0.0f, 0.0f, 0.0f, 0.0f};              // l via ones-MMA
    const uint32_t onesfrag[2] = {0x3C003C00u, 0x3C003C00u}; // all-ones k16n8 B-frag
    float m0 = -INFINITY, m1 = -INFINITY;
    const int rloc = wid*16 + (lane >> 2);

    int buf = 0;
    for (int kt = 0; kt < 32; kt++){
        asm volatile("cp.async.wait_group 1;" ::: "memory");
        __syncthreads();
        const uint32_t sK = sbase + FL_SMST + buf*FL_STAGE;
        const uint32_t sV = sK + FL_KB;

        float S[8][4];
        #pragma unroll
        for (int j = 0; j < 8; j++){ S[j][0]=0; S[j][1]=0; S[j][2]=0; S[j][3]=0; }

        // S = Qs @ K^T  (exp2 domain; Q pre-scaled by 0.125*log2e)
        #pragma unroll
        for (int kc = 0; kc < 4; kc++){
            #pragma unroll
            for (int g = 0; g < 4; g++){
                uint32_t addr = sK + (uint32_t)(((g*16 + bRow)*FL_LQ + kc*16 + bCol) * 2);
                uint32_t bk[4];
                ldmx4(bk, addr);
                mma16816(S[2*g],   qf[kc], bk+0);
                mma16816(S[2*g+1], qf[kc], bk+2);
            }
        }

        // + mask (pre-scaled log2e) + running max
        const int t0 = kt * 64;
        const long mr0 = (long)(q0 + rloc) * 2048 + t0;
        const long mr1 = mr0 + 8 * 2048;
        float mx0 = -INFINITY, mx1 = -INFINITY;
        #pragma unroll
        for (int j = 0; j < 8; j++){
            int c = j*8 + (lane & 3)*2;
            float2 k0v = __half22float2(*(const __half2*)(maskh + mr0 + c));
            float2 k1v = __half22float2(*(const __half2*)(maskh + mr1 + c));
            S[j][0] += k0v.x;
            S[j][1] += k0v.y;
            S[j][2] += k1v.x;
            S[j][3] += k1v.y;
            mx0 = fmaxf(mx0, fmaxf(S[j][0], S[j][1]));
            mx1 = fmaxf(mx1, fmaxf(S[j][2], S[j][3]));
        }
        mx0 = fmaxf(mx0, __shfl_xor_sync(0xFFFFFFFFu, mx0, 1));
        mx0 = fmaxf(mx0, __shfl_xor_sync(0xFFFFFFFFu, mx0, 2));
        mx1 = fmaxf(mx1, __shfl_xor_sync(0xFFFFFFFFu, mx1, 1));
        mx1 = fmaxf(mx1, __shfl_xor_sync(0xFFFFFFFFu, mx1, 2));
        float nm0 = fmaxf(m0, mx0), nm1 = fmaxf(m1, mx1);

        // rescale O and lacc only if any quad's max moved
        bool re = (nm0 != m0) || (nm1 != m1);
        if (__any_sync(0xFFFFFFFFu, re)){
            float f0 = (m0 > -INFINITY) ? exp2f(m0 - nm0) : 0.0f;
            float f1 = (m1 > -INFINITY) ? exp2f(m1 - nm1) : 0.0f;
            #pragma unroll
            for (int j = 0; j < 8; j++){
                O[j][0]*=f0; O[j][1]*=f0; O[j][2]*=f1; O[j][3]*=f1;
            }
            lacc[0]*=f0; lacc[1]*=f0; lacc[2]*=f1; lacc[3]*=f1;
        }
        m0 = nm0; m1 = nm1;

        // P = exp2(S - m) via f16x2 MUFU; l += P @ ones (tensor pipe); O += P @ V
        #pragma unroll
        for (int kc = 0; kc < 4; kc++){
            uint32_t ph[4];
            ph[0] = ex2h2(packf2(S[2*kc][0]   - m0, S[2*kc][1]   - m0));
            ph[1] = ex2h2(packf2(S[2*kc][2]   - m1, S[2*kc][3]   - m1));
            ph[2] = ex2h2(packf2(S[2*kc+1][0] - m0, S[2*kc+1][1] - m0));
            ph[3] = ex2h2(packf2(S[2*kc+1][2] - m1, S[2*kc+1][3] - m1));
            mma16816(lacc, ph, onesfrag);
            #pragma unroll
            for (int g = 0; g < 4; g++){
                uint32_t addr = sV + (uint32_t)(((g*16 + bRow)*FL_LQ + kc*16 + bCol) * 2);
                uint32_t vf[4];
                ldmx4(vf, addr);
                mma16816(O[2*g],   ph, vf+0);
                mma16816(O[2*g+1], ph, vf+2);
            }
        }

        if (kt + 2 < 32){
            int nbuf = buf + 2; if (nbuf >= 3) nbuf -= 3;
            load_stage(kt + 2, nbuf);
        }
        asm volatile("cp.async.commit_group;" ::: "memory");
        if (++buf == 3) buf = 0;
    }

    // finalize: every lane holds its rows' l in lacc[0]/lacc[2] (all ones-cols equal)
    const long hOff = (long)z * 64;
    const float inv0 = 1.0f / lacc[0], inv1 = 1.0f / lacc[2];
    #pragma unroll
    for (int j = 0; j < 8; j++){
        const int col = j*8 + (lane & 3)*2;
        const long a0 = (long)(q0 + rloc) * 4096 + hOff + col;
        const long a1 = a0 + 8L * 4096;
        *(uint32_t*)(AV + a0) = packf2(O[j][0]*inv0, O[j][1]*inv0);
        *(uint32_t*)(AV + a1) = packf2(O[j][2]*inv1, O[j][3]*inv1);
    }
}

// ---------------- fused fp32 -> fp16 conversion (seg 7 = mask, pre-scaled by log2e) ----------------
struct CvtSegs {
    const float4* in[8];
    uint2*        out[8];
    long          start[9];
};
__global__ void cvt_multi(CvtSegs s)
{
    long i = (long)blockIdx.x * 256 + threadIdx.x;
    if (i >= s.start[8]) return;
    int seg = 0;
    #pragma unroll
    for (int k = 1; k < 8; k++) if (i >= s.start[k]) seg = k;
    long j = i - s.start[seg];
    float4 v = s.in[seg][j];
    float sc = (seg == 7) ? LOG2E : 1.0f;
    uint2 H;
    H.x = packf2(v.x * sc, v.y * sc);
    H.y = packf2(v.z * sc, v.w * sc);
    s.out[seg][j] = H;
}

// ---------------- V transpose (fp16): qkv V section -> vt[z][kk][t] ----------------
__global__ void transpose_v(const __half* __restrict__ qkv, __half* __restrict__ vt)
{
    __shared__ __half t[64][72];
    const int z  = blockIdx.y;
    const int t0 = blockIdx.x * 64;
    const int b  = z >> 4, h = z & 15;
    const __half* src = qkv + 2048 + (size_t)b*3072 + (size_t)h*64;
    for (int it = 0; it < 16; it++){
        int idx = it*256 + threadIdx.x;
        int ti = idx >> 6, kk = idx & 63;
        t[ti][kk] = src[(size_t)(t0 + ti)*12288 + kk];
    }
    __syncthreads();
    size_t obase = (size_t)z * Kh * Ss + t0;
    for (int it = 0; it < 16; it++){
        int idx = it*256 + threadIdx.x;
        int kk = idx >> 6, ti = idx & 63;
        vt[obase + (size_t)kk*Ss + ti] = t[ti][kk];
    }
}

// ---------------- layernorm over D=1024; optional fp16 output ----------------
__global__ void layernorm_kernel(const float* __restrict__ in,
                                 float* __restrict__ out,
                                 __half* __restrict__ oh,
                                 const float* __restrict__ gamma,
                                 const float* __restrict__ beta)
{
    const int row = blockIdx.x;
    const float* x = in + (size_t)row * Dd;
    const int tid = threadIdx.x;

    float v[4];
    float s = 0.0f, s2 = 0.0f;
    #pragma unroll
    for (int i = 0; i < 4; i++){
        v[i] = x[tid + i*256];
        s  += v[i];
        s2 += v[i]*v[i];
    }
    __shared__ float r1[256], r2[256];
    r1[tid] = s; r2[tid] = s2; __syncthreads();
    for (int off = 128; off > 0; off >>= 1){
        if (tid < off){ r1[tid] += r1[tid+off]; r2[tid] += r2[tid+off]; }
        __syncthreads();
    }
    float mean = r1[0] * (1.0f/Dd);
    float var  = r2[0] * (1.0f/Dd) - mean*mean;
    float inv  = rsqrtf(var + EPSL);
    #pragma unroll
    for (int i = 0; i < 4; i++){
        int c = tid + i*256;
        float y = (v[i] - mean) * inv * gamma[c] + beta[c];
        out[(size_t)row*Dd + c] = y;
        if (oh) oh[(size_t)row*Dd + c] = __float2half_rn(y);
    }
}

// ---------------- host side ----------------
static const int SMEM_GEMM = 3 * 36864;   // 110592

struct GemmArgs {
    const __half *A, *B;
    float* Cf; __half *Ch;
    int M, N, Kd; long lda, ldb, ldc;
    float alpha; const float* add; long ldadd; const float* bias; int relu; int qkvMode;
};

static inline void run_gemm(const GemmArgs& a){
    dim3 grid(a.N / 128, a.M / 128, 1);
    mma_gemm<<<grid, 256, SMEM_GEMM>>>(a.A, a.B, a.Cf, a.Ch,
                                       a.Kd, a.lda, a.ldb, a.ldc,
                                       a.alpha, a.add, a.ldadd, a.bias, a.relu, a.qkvMode);
}

extern "C" void kernel_launch(void* const* d_in, const int* in_sizes, int n_in,
                              void* d_out, int out_size)
{
    const float* x     = (const float*)d_in[0];
    const float* mask  = (const float*)d_in[1];
    const float* wq    = (const float*)d_in[2];
    const float* wk    = (const float*)d_in[3];
    const float* wv    = (const float*)d_in[4];
    const float* wc    = (const float*)d_in[5];
    const float* w1_w  = (const float*)d_in[6];
    const float* w1_b  = (const float*)d_in[7];
    const float* w2_w  = (const float*)d_in[8];
    const float* w2_b  = (const float*)d_in[9];
    const float* ln1_g = (const float*)d_in[10];
    const float* ln1_b = (const float*)d_in[11];
    const float* ln2_g = (const float*)d_in[12];
    const float* ln2_b = (const float*)d_in[13];
    float* out = (float*)d_out;

    cudaFuncSetAttribute((const void*)mma_gemm,     cudaFuncAttributeMaxDynamicSharedMemorySize, SMEM_GEMM);
    cudaFuncSetAttribute((const void*)flash_kernel, cudaFuncAttributeMaxDynamicSharedMemorySize, FL_SMEM);

    __half *xh,*pwqkv,*pwc,*pw1,*pw2,*pmask;
    __half *qkv,*vt,*av,*uh,*h1;
    float *attn,*u,*z;
    cudaGetSymbolAddress((void**)&xh,    g_x);
    cudaGetSymbolAddress((void**)&pwqkv, g_wqkv);
    cudaGetSymbolAddress((void**)&pwc,   g_wc);
    cudaGetSymbolAddress((void**)&pw1,   g_w1);
    cudaGetSymbolAddress((void**)&pw2,   g_w2);
    cudaGetSymbolAddress((void**)&pmask, g_maskh);
    cudaGetSymbolAddress((void**)&qkv,   g_qkv);
    cudaGetSymbolAddress((void**)&vt,    g_vt);
    cudaGetSymbolAddress((void**)&av,    g_av);
    cudaGetSymbolAddress((void**)&attn,  g_attn);
    cudaGetSymbolAddress((void**)&u,     g_u);
    cudaGetSymbolAddress((void**)&uh,    g_uh);
    cudaGetSymbolAddress((void**)&h1,    g_h1);
    cudaGetSymbolAddress((void**)&z,     g_z);

    // single fused conversion launch: x, wq|wk|wv (packed), wc, w1, w2, mask(*log2e)
    {
        CvtSegs s;
        const float* srcs[8] = {x, wq, wk, wv, wc, w1_w, w2_w, mask};
        __half*      dsts[8] = {xh, pwqkv, pwqkv + (size_t)Dd*Dd, pwqkv + (size_t)2*Dd*Dd,
                                pwc, pw1, pw2, pmask};
        long lens[8] = {(long)NTOK*Dd, (long)Dd*Dd, (long)Dd*Dd, (long)Dd*Dd,
                        (long)Dd*Dd, (long)Mf*Dd, (long)Mf*Dd, (long)Ss*Ss};
        long acc = 0;
        for (int i = 0; i < 8; i++){
            s.in[i]  = (const float4*)srcs[i];
            s.out[i] = (uint2*)dsts[i];
            s.start[i] = acc;
            acc += lens[i] / 4;
        }
        s.start[8] = acc;
        cvt_multi<<<(unsigned)((acc + 255) / 256), 256>>>(s);
    }

    GemmArgs a;
    // QKV = x @ wqkv^T  (Q section pre-scaled by 0.125*log2e)
    a = {xh,pwqkv, nullptr,qkv, NTOK,3*Dd,Dd, Dd,Dd,3*Dd, 1.0f, nullptr,0, nullptr,0, 1};
    run_gemm(a);
    // V transpose from packed qkv
    {
        dim3 g(Ss/64, BH);
        transpose_v<<<g, 256>>>(qkv, vt);
    }
    // fused attention: av = softmax(Q K^T / 8 + mask) @ V
    {
        dim3 g(Ss/128, BH);
        flash_kernel<<<g, 256, FL_SMEM>>>(qkv, vt, pmask, av);
    }
    // attn = av @ wc^T + x  (fp32)
    a = {av,pwc, attn,nullptr, NTOK,Dd,Dd, Dd,Dd,Dd, 1.0f, x,Dd, nullptr,0, 0};
    run_gemm(a);
    // u = LN1(attn)
    layernorm_kernel<<<NTOK, 256>>>(attn, u, uh, ln1_g, ln1_b);
    // h1 = relu(u @ w1^T + b1)
    a = {uh,pw1, nullptr,h1, NTOK,Mf,Dd, Dd,Dd,Mf, 1.0f, nullptr,0, w1_b,1, 0};
    run_gemm(a);
    // z = h1 @ w2^T + b2 + u  (fp32)
    a = {h1,pw2, z,nullptr, NTOK,Dd,Mf, Mf,Mf,Dd, 1.0f, u,Dd, w2_b,0, 0};
    run_gemm(a);
    // out = LN2(z)
    layernorm_kernel<<<NTOK, 256>>>(z, out, nullptr, ln2_g, ln2_b);
}

// round 13
// speedup vs baseline: 13.6697x; 1.1420x over previous
#include <cuda_runtime.h>
#include <cuda_fp16.h>
#include <cstdint>
#include <math.h>

#define Hh   16
#define Kh   64
#define Dd   1024
#define Mf   4096
#define Ss   2048
#define Bb   4
#define NTOK (Ss*Bb)      // 8192
#define BH   (Bb*Hh)      // 64
#define EPSL 1e-5f
#define LOG2E 1.44269504088896340736f
#define QSCALE (0.125f * LOG2E)

// ---------------- scratch buffers (device globals: allocation-free) ----------------
__device__ __half g_x[(size_t)NTOK*Dd];
__device__ __half g_wqkv[(size_t)3*Dd*Dd];
__device__ __half g_wc[(size_t)Dd*Dd];
__device__ __half g_w1[(size_t)Mf*Dd];
__device__ __half g_w2[(size_t)Mf*Dd];
__device__ __half g_maskh[(size_t)Ss*Ss];          // pre-scaled by log2(e)
__device__ int    g_maskflag;                      // nonzero if mask has any nonzero
__device__ __half g_qkv[(size_t)NTOK*3*Dd];        // Q section pre-scaled by 0.125*log2(e)
__device__ __half g_av[(size_t)NTOK*Dd];
__device__ float  g_attn[(size_t)NTOK*Dd];
__device__ float  g_u[(size_t)NTOK*Dd];
__device__ __half g_uh[(size_t)NTOK*Dd];
__device__ __half g_h1[(size_t)NTOK*Mf];
__device__ float  g_z[(size_t)NTOK*Dd];

// ---------------- helpers ----------------
__device__ __forceinline__ uint32_t smem_u32(const void* p){
    uint32_t a;
    asm("{ .reg .u64 t; cvta.to.shared.u64 t, %1; cvt.u32.u64 %0, t; }" : "=r"(a) : "l"(p));
    return a;
}
__device__ __forceinline__ uint32_t packf2(float lo, float hi){
    uint32_t r;
    asm("cvt.rn.f16x2.f32 %0, %1, %2;" : "=r"(r) : "f"(hi), "f"(lo));
    return r;
}
__device__ __forceinline__ uint32_t ex2h2(uint32_t x){
    uint32_t r;
    asm("ex2.approx.f16x2 %0, %1;" : "=r"(r) : "r"(x));
    return r;
}
__device__ __forceinline__ void cpasync16(uint32_t saddr, const void* gaddr){
    asm volatile("cp.async.cg.shared.global [%0], [%1], 16;" :: "r"(saddr), "l"(gaddr) : "memory");
}
__device__ __forceinline__ void ldmx4(uint32_t* r, uint32_t addr){
    asm volatile("ldmatrix.sync.aligned.m8n8.x4.shared.b16 {%0,%1,%2,%3}, [%4];"
                 : "=r"(r[0]), "=r"(r[1]), "=r"(r[2]), "=r"(r[3]) : "r"(addr));
}
__device__ __forceinline__ void ldmx4t(uint32_t* r, uint32_t addr){
    asm volatile("ldmatrix.sync.aligned.m8n8.x4.trans.shared.b16 {%0,%1,%2,%3}, [%4];"
                 : "=r"(r[0]), "=r"(r[1]), "=r"(r[2]), "=r"(r[3]) : "r"(addr));
}
__device__ __forceinline__ void mma16816(float* c, const uint32_t* a, const uint32_t* b){
    asm volatile("mma.sync.aligned.m16n8k16.row.col.f32.f16.f16.f32 "
                 "{%0,%1,%2,%3}, {%4,%5,%6,%7}, {%8,%9}, {%0,%1,%2,%3};"
                 : "+f"(c[0]), "+f"(c[1]), "+f"(c[2]), "+f"(c[3])
                 : "r"(a[0]), "r"(a[1]), "r"(a[2]), "r"(a[3]), "r"(b[0]), "r"(b[1]));
}

// ---------------- mma.sync fp16 NT GEMM, BK=64, 3-stage pipeline ----------------
__global__ void __launch_bounds__(256) mma_gemm(
    const __half* __restrict__ A, const __half* __restrict__ B,
    float* __restrict__ Cf, __half* __restrict__ Ch,
    int Kd, long lda, long ldb, long ldc,
    float alpha, const float* __restrict__ add, long ldadd,
    const float* __restrict__ bias, int doRelu, int qkvMode)
{
    constexpr int BN   = 128;
    constexpr int BK   = 64;
    constexpr int LDS  = BK + 8;
    constexpr int WN   = BN / 2;
    constexpr int NT   = WN / 8;
    constexpr int A_BYTES = 128 * LDS * 2;
    constexpr int B_BYTES = BN  * LDS * 2;
    constexpr int STAGE   = A_BYTES + B_BYTES;

    extern __shared__ char smc[];
    const uint32_t sbase = smem_u32(smc);

    const int tid  = threadIdx.x;
    const int lane = tid & 31;
    const int wid  = tid >> 5;
    const int warpM = (wid & 3) * 32;
    const int warpN = (wid >> 2) * WN;

    const int  m0   = blockIdx.y * 128;
    const int  n0   = blockIdx.x * BN;
    const int  KT   = Kd / BK;

    const int la_row = tid >> 3, la_ch = tid & 7;
    auto load_stage = [&](int kt, int buf){
        const int k0 = kt * BK;
        const uint32_t s0 = sbase + buf * STAGE;
        #pragma unroll
        for (int it = 0; it < 4; it++){
            int row = la_row + it * 32;
            long g = (long)(m0 + row) * lda + k0 + la_ch * 8;
            uint32_t so = (uint32_t)(row * (LDS * 2) + la_ch * 16);
            cpasync16(s0 + so, A + g);
        }
        #pragma unroll
        for (int it = 0; it < 4; it++){
            int row = la_row + it * 32;
            long g = (long)(n0 + row) * ldb + k0 + la_ch * 8;
            uint32_t so = (uint32_t)(row * (LDS * 2) + la_ch * 16);
            cpasync16(s0 + A_BYTES + so, B + g);
        }
    };

    load_stage(0, 0);
    asm volatile("cp.async.commit_group;" ::: "memory");
    load_stage(1, 1);
    asm volatile("cp.async.commit_group;" ::: "memory");

    float acc[2][NT][4];
    #pragma unroll
    for (int i = 0; i < 2; i++)
        #pragma unroll
        for (int j = 0; j < NT; j++)
            #pragma unroll
            for (int e = 0; e < 4; e++) acc[i][j][e] = 0.0f;

    const int aRow = (lane & 15), aColHalf = (lane >> 4) * 8;
    const int bRow = (lane >> 4) * 8 + (lane & 7), bColHalf = ((lane >> 3) & 1) * 8;

    int buf = 0;
    for (int kt = 0; kt < KT; kt++){
        asm volatile("cp.async.wait_group 1;" ::: "memory");
        __syncthreads();
        const uint32_t sA0 = sbase + buf * STAGE;
        const uint32_t sB0 = sA0 + A_BYTES;

        #pragma unroll
        for (int ks = 0; ks < 4; ks++){
            const int k16 = ks * 16;
            uint32_t af[2][4];
            #pragma unroll
            for (int mt = 0; mt < 2; mt++){
                uint32_t addr = sA0 + (uint32_t)(((warpM + mt*16 + aRow) * LDS + k16 + aColHalf) * 2);
                ldmx4(af[mt], addr);
            }
            uint32_t bf[NT][2];
            #pragma unroll
            for (int g = 0; g < NT/2; g++){
                uint32_t addr = sB0 + (uint32_t)(((warpN + g*16 + bRow) * LDS + k16 + bColHalf) * 2);
                uint32_t r[4];
                ldmx4(r, addr);
                bf[2*g][0] = r[0]; bf[2*g][1] = r[1];
                bf[2*g+1][0] = r[2]; bf[2*g+1][1] = r[3];
            }
            #pragma unroll
            for (int mt = 0; mt < 2; mt++)
                #pragma unroll
                for (int j = 0; j < NT; j++)
                    mma16816(acc[mt][j], af[mt], bf[j]);
        }
        if (kt + 2 < KT){
            int nbuf = buf + 2; if (nbuf >= 3) nbuf -= 3;
            load_stage(kt + 2, nbuf);
        }
        asm volatile("cp.async.commit_group;" ::: "memory");
        if (++buf == 3) buf = 0;
    }

    #pragma unroll
    for (int mt = 0; mt < 2; mt++){
        #pragma unroll
        for (int j = 0; j < NT; j++){
            const int col = n0 + warpN + j*8 + (lane & 3) * 2;
            const float sc = qkvMode ? (((col % 3072) < 1024) ? QSCALE : 1.0f) : alpha;
            const float b0 = bias ? bias[col]   : 0.0f;
            const float b1 = bias ? bias[col+1] : 0.0f;
            #pragma unroll
            for (int half = 0; half < 2; half++){
                const long row = m0 + warpM + mt*16 + (lane >> 2) + half*8;
                float v0 = acc[mt][j][half*2+0] * sc + b0;
                float v1 = acc[mt][j][half*2+1] * sc + b1;
                if (add){
                    v0 += add[row * ldadd + col];
                    v1 += add[row * ldadd + col + 1];
                }
                if (doRelu){ v0 = fmaxf(v0, 0.0f); v1 = fmaxf(v1, 0.0f); }
                const long ci = row * ldc + col;
                if (Ch){
                    *(uint32_t*)(Ch + ci) = packf2(v0, v1);
                } else {
                    *(float2*)(Cf + ci) = make_float2(v0, v1);
                }
            }
        }
    }
}

// ---------------- fused flash attention (exp2, l-via-MMA, V via ldmatrix.trans) ----------------
#define FL_LQ 72
#define FL_QBYTES (128*FL_LQ*2)
#define FL_KB (64*FL_LQ*2)                   // 9216 (K: 64 t-rows x 64 cols)
#define FL_VB (64*FL_LQ*2)                   // 9216 (V: 64 t-rows x 64 kk-cols, natural layout)
#define FL_STAGE (FL_KB + FL_VB)
#define FL_SMQ   0
#define FL_SMST  FL_QBYTES
#define FL_SMEM  (FL_SMST + 3*FL_STAGE)      // 73728

__global__ void __launch_bounds__(256,2) flash_kernel(
    const __half* __restrict__ QKV,
    const __half* __restrict__ maskh,
    const int* __restrict__ maskFlag,
    __half* __restrict__ AV)
{
    extern __shared__ char smc[];
    const uint32_t sbase = smem_u32(smc);
    const int tid = threadIdx.x, lane = tid & 31, wid = tid >> 5;
    const int q0 = blockIdx.x * 128;
    const int z  = blockIdx.y;
    const long qOff = (long)(z >> 4) * 3072 + (long)(z & 15) * 64;
    const long kOff = qOff + 1024;
    const long vOff = qOff + 2048;
    const int hasMask = *maskFlag;

    auto load_q = [&](){
        #pragma unroll
        for (int it = 0; it < 4; it++){
            int idx = it*256 + tid;
            int row = idx >> 3, ch = idx & 7;
            long g = (long)(q0 + row) * 12288 + qOff + ch*8;
            uint32_t so = sbase + FL_SMQ + (uint32_t)(row*FL_LQ*2 + ch*16);
            cpasync16(so, QKV + g);
        }
    };
    auto load_stage = [&](int kt, int buf){
        const int t0 = kt * 64;
        const uint32_t s0 = sbase + FL_SMST + buf*FL_STAGE;
        #pragma unroll
        for (int it = 0; it < 2; it++){
            int idx = it*256 + tid;
            int row = idx >> 3, ch = idx & 7;
            long gk = (long)(t0 + row) * 12288 + kOff + ch*8;
            uint32_t so = s0 + (uint32_t)(row*FL_LQ*2 + ch*16);
            cpasync16(so, QKV + gk);
            long gv = (long)(t0 + row) * 12288 + vOff + ch*8;
            cpasync16(so + FL_KB, QKV + gv);
        }
    };

    load_q();
    load_stage(0, 0);
    asm volatile("cp.async.commit_group;" ::: "memory");
    load_stage(1, 1);
    asm volatile("cp.async.commit_group;" ::: "memory");
    asm volatile("cp.async.wait_group 1;" ::: "memory");
    __syncthreads();

    const int aRow = lane & 15, aCol = (lane >> 4) * 8;
    const int bRow = (lane >> 4) * 8 + (lane & 7), bCol = ((lane >> 3) & 1) * 8;

    uint32_t qf[4][4];
    #pragma unroll
    for (int kc = 0; kc < 4; kc++){
        uint32_t addr = sbase + FL_SMQ + (uint32_t)(((wid*16 + aRow)*FL_LQ + kc*16 + aCol) * 2);
        ldmx4(qf[kc], addr);
    }

    float O[8][4];
    #pragma unroll
    for (int j = 0; j < 8; j++){ O[j][0]=0; O[j][1]=0; O[j][2]=0; O[j][3]=0; }
    float lacc[4] = {0.0f, 0.0f, 0.0f, 0.0f};
    const uint32_t onesfrag[2] = {0x3C003C00u, 0x3C003C00u};
    float m0 = -INFINITY, m1 = -INFINITY;
    const int rloc = wid*16 + (lane >> 2);

    int buf = 0;
    for (int kt = 0; kt < 32; kt++){
        asm volatile("cp.async.wait_group 1;" ::: "memory");
        __syncthreads();
        const uint32_t sK = sbase + FL_SMST + buf*FL_STAGE;
        const uint32_t sV = sK + FL_KB;

        float S[8][4];
        #pragma unroll
        for (int j = 0; j < 8; j++){ S[j][0]=0; S[j][1]=0; S[j][2]=0; S[j][3]=0; }

        // S = Qs @ K^T
        #pragma unroll
        for (int kc = 0; kc < 4; kc++){
            #pragma unroll
            for (int g = 0; g < 4; g++){
                uint32_t addr = sK + (uint32_t)(((g*16 + bRow)*FL_LQ + kc*16 + bCol) * 2);
                uint32_t bk[4];
                ldmx4(bk, addr);
                mma16816(S[2*g],   qf[kc], bk+0);
                mma16816(S[2*g+1], qf[kc], bk+2);
            }
        }

        // + mask (only when mask nonzero) + running max
        const int t0 = kt * 64;
        float mx0 = -INFINITY, mx1 = -INFINITY;
        if (hasMask){
            const long mr0 = (long)(q0 + rloc) * 2048 + t0;
            const long mr1 = mr0 + 8 * 2048;
            #pragma unroll
            for (int j = 0; j < 8; j++){
                int c = j*8 + (lane & 3)*2;
                float2 k0v = __half22float2(*(const __half2*)(maskh + mr0 + c));
                float2 k1v = __half22float2(*(const __half2*)(maskh + mr1 + c));
                S[j][0] += k0v.x;
                S[j][1] += k0v.y;
                S[j][2] += k1v.x;
                S[j][3] += k1v.y;
                mx0 = fmaxf(mx0, fmaxf(S[j][0], S[j][1]));
                mx1 = fmaxf(mx1, fmaxf(S[j][2], S[j][3]));
            }
        } else {
            #pragma unroll
            for (int j = 0; j < 8; j++){
                mx0 = fmaxf(mx0, fmaxf(S[j][0], S[j][1]));
                mx1 = fmaxf(mx1, fmaxf(S[j][2], S[j][3]));
            }
        }
        mx0 = fmaxf(mx0, __shfl_xor_sync(0xFFFFFFFFu, mx0, 1));
        mx0 = fmaxf(mx0, __shfl_xor_sync(0xFFFFFFFFu, mx0, 2));
        mx1 = fmaxf(mx1, __shfl_xor_sync(0xFFFFFFFFu, mx1, 1));
        mx1 = fmaxf(mx1, __shfl_xor_sync(0xFFFFFFFFu, mx1, 2));
        float nm0 = fmaxf(m0, mx0), nm1 = fmaxf(m1, mx1);

        bool re = (nm0 != m0) || (nm1 != m1);
        if (__any_sync(0xFFFFFFFFu, re)){
            float f0 = (m0 > -INFINITY) ? exp2f(m0 - nm0) : 0.0f;
            float f1 = (m1 > -INFINITY) ? exp2f(m1 - nm1) : 0.0f;
            #pragma unroll
            for (int j = 0; j < 8; j++){
                O[j][0]*=f0; O[j][1]*=f0; O[j][2]*=f1; O[j][3]*=f1;
            }
            lacc[0]*=f0; lacc[1]*=f0; lacc[2]*=f1; lacc[3]*=f1;
        }
        m0 = nm0; m1 = nm1;

        // P = exp2(S - m); l += P @ ones; O += P @ V (V frags via ldmatrix.trans)
        #pragma unroll
        for (int kc = 0; kc < 4; kc++){
            uint32_t ph[4];
            ph[0] = ex2h2(packf2(S[2*kc][0]   - m0, S[2*kc][1]   - m0));
            ph[1] = ex2h2(packf2(S[2*kc][2]   - m1, S[2*kc][3]   - m1));
            ph[2] = ex2h2(packf2(S[2*kc+1][0] - m0, S[2*kc+1][1] - m0));
            ph[3] = ex2h2(packf2(S[2*kc+1][2] - m1, S[2*kc+1][3] - m1));
            mma16816(lacc, ph, onesfrag);
            #pragma unroll
            for (int g = 0; g < 4; g++){
                // V natural layout [t, kk]: rows = t (k-dim), cols = kk (n-dim); transpose in LDSM
                uint32_t addr = sV + (uint32_t)(((kc*16 + aRow)*FL_LQ + g*16 + aCol) * 2);
                uint32_t vf[4];
                ldmx4t(vf, addr);
                mma16816(O[2*g],   ph, vf+0);
                mma16816(O[2*g+1], ph, vf+2);
            }
        }

        if (kt + 2 < 32){
            int nbuf = buf + 2; if (nbuf >= 3) nbuf -= 3;
            load_stage(kt + 2, nbuf);
        }
        asm volatile("cp.async.commit_group;" ::: "memory");
        if (++buf == 3) buf = 0;
    }

    // finalize
    const long hOff = (long)z * 64;
    const float inv0 = 1.0f / lacc[0], inv1 = 1.0f / lacc[2];
    #pragma unroll
    for (int j = 0; j < 8; j++){
        const int col = j*8 + (lane & 3)*2;
        const long a0 = (long)(q0 + rloc) * 4096 + hOff + col;
        const long a1 = a0 + 8L * 4096;
        *(uint32_t*)(AV + a0) = packf2(O[j][0]*inv0, O[j][1]*inv0);
        *(uint32_t*)(AV + a1) = packf2(O[j][2]*inv1, O[j][3]*inv1);
    }
}

// ---------------- fused fp32 -> fp16 conversion; seg7 = mask (scaled, sets flag) ----------------
struct CvtSegs {
    const float4* in[8];
    uint2*        out[8];
    long          start[9];
    int*          maskFlag;
};
__global__ void cvt_multi(CvtSegs s)
{
    long i = (long)blockIdx.x * 256 + threadIdx.x;
    if (i >= s.start[8]) return;
    int seg = 0;
    #pragma unroll
    for (int k = 1; k < 8; k++) if (i >= s.start[k]) seg = k;
    long j = i - s.start[seg];
    float4 v = s.in[seg][j];
    if (seg == 7){
        if (v.x != 0.0f || v.y != 0.0f || v.z != 0.0f || v.w != 0.0f)
            atomicOr(s.maskFlag, 1);
        v.x *= LOG2E; v.y *= LOG2E; v.z *= LOG2E; v.w *= LOG2E;
    }
    uint2 H;
    H.x = packf2(v.x, v.y);
    H.y = packf2(v.z, v.w);
    s.out[seg][j] = H;
}

// ---------------- layernorm over D=1024; optional fp16 output ----------------
__global__ void layernorm_kernel(const float* __restrict__ in,
                                 float* __restrict__ out,
                                 __half* __restrict__ oh,
                                 const float* __restrict__ gamma,
                                 const float* __restrict__ beta)
{
    const int row = blockIdx.x;
    const float* x = in + (size_t)row * Dd;
    const int tid = threadIdx.x;

    float v[4];
    float s = 0.0f, s2 = 0.0f;
    #pragma unroll
    for (int i = 0; i < 4; i++){
        v[i] = x[tid + i*256];
        s  += v[i];
        s2 += v[i]*v[i];
    }
    __shared__ float r1[256], r2[256];
    r1[tid] = s; r2[tid] = s2; __syncthreads();
    for (int off = 128; off > 0; off >>= 1){
        if (tid < off){ r1[tid] += r1[tid+off]; r2[tid] += r2[tid+off]; }
        __syncthreads();
    }
    float mean = r1[0] * (1.0f/Dd);
    float var  = r2[0] * (1.0f/Dd) - mean*mean;
    float inv  = rsqrtf(var + EPSL);
    #pragma unroll
    for (int i = 0; i < 4; i++){
        int c = tid + i*256;
        float y = (v[i] - mean) * inv * gamma[c] + beta[c];
        out[(size_t)row*Dd + c] = y;
        if (oh) oh[(size_t)row*Dd + c] = __float2half_rn(y);
    }
}

// ---------------- host side ----------------
static const int SMEM_GEMM = 3 * 36864;   // 110592

struct GemmArgs {
    const __half *A, *B;
    float* Cf; __half *Ch;
    int M, N, Kd; long lda, ldb, ldc;
    float alpha; const float* add; long ldadd; const float* bias; int relu; int qkvMode;
};

static inline void run_gemm(const GemmArgs& a){
    dim3 grid(a.N / 128, a.M / 128, 1);
    mma_gemm<<<grid, 256, SMEM_GEMM>>>(a.A, a.B, a.Cf, a.Ch,
                                       a.Kd, a.lda, a.ldb, a.ldc,
                                       a.alpha, a.add, a.ldadd, a.bias, a.relu, a.qkvMode);
}

extern "C" void kernel_launch(void* const* d_in, const int* in_sizes, int n_in,
                              void* d_out, int out_size)
{
    const float* x     = (const float*)d_in[0];
    const float* mask  = (const float*)d_in[1];
    const float* wq    = (const float*)d_in[2];
    const float* wk    = (const float*)d_in[3];
    const float* wv    = (const float*)d_in[4];
    const float* wc    = (const float*)d_in[5];
    const float* w1_w  = (const float*)d_in[6];
    const float* w1_b  = (const float*)d_in[7];
    const float* w2_w  = (const float*)d_in[8];
    const float* w2_b  = (const float*)d_in[9];
    const float* ln1_g = (const float*)d_in[10];
    const float* ln1_b = (const float*)d_in[11];
    const float* ln2_g = (const float*)d_in[12];
    const float* ln2_b = (const float*)d_in[13];
    float* out = (float*)d_out;

    cudaFuncSetAttribute((const void*)mma_gemm,     cudaFuncAttributeMaxDynamicSharedMemorySize, SMEM_GEMM);
    cudaFuncSetAttribute((const void*)flash_kernel, cudaFuncAttributeMaxDynamicSharedMemorySize, FL_SMEM);

    __half *xh,*pwqkv,*pwc,*pw1,*pw2,*pmask;
    __half *qkv,*av,*uh,*h1;
    float *attn,*u,*z;
    int* pflag;
    cudaGetSymbolAddress((void**)&xh,    g_x);
    cudaGetSymbolAddress((void**)&pwqkv, g_wqkv);
    cudaGetSymbolAddress((void**)&pwc,   g_wc);
    cudaGetSymbolAddress((void**)&pw1,   g_w1);
    cudaGetSymbolAddress((void**)&pw2,   g_w2);
    cudaGetSymbolAddress((void**)&pmask, g_maskh);
    cudaGetSymbolAddress((void**)&pflag, g_maskflag);
    cudaGetSymbolAddress((void**)&qkv,   g_qkv);
    cudaGetSymbolAddress((void**)&av,    g_av);
    cudaGetSymbolAddress((void**)&attn,  g_attn);
    cudaGetSymbolAddress((void**)&u,     g_u);
    cudaGetSymbolAddress((void**)&uh,    g_uh);
    cudaGetSymbolAddress((void**)&h1,    g_h1);
    cudaGetSymbolAddress((void**)&z,     g_z);

    // reset mask flag (capturable memset node)
    cudaMemsetAsync(pflag, 0, sizeof(int));

    // single fused conversion launch: x, wq|wk|wv (packed), wc, w1, w2, mask(*log2e + flag)
    {
        CvtSegs s;
        const float* srcs[8] = {x, wq, wk, wv, wc, w1_w, w2_w, mask};
        __half*      dsts[8] = {xh, pwqkv, pwqkv + (size_t)Dd*Dd, pwqkv + (size_t)2*Dd*Dd,
                                pwc, pw1, pw2, pmask};
        long lens[8] = {(long)NTOK*Dd, (long)Dd*Dd, (long)Dd*Dd, (long)Dd*Dd,
                        (long)Dd*Dd, (long)Mf*Dd, (long)Mf*Dd, (long)Ss*Ss};
        long acc = 0;
        for (int i = 0; i < 8; i++){
            s.in[i]  = (const float4*)srcs[i];
            s.out[i] = (uint2*)dsts[i];
            s.start[i] = acc;
            acc += lens[i] / 4;
        }
        s.start[8] = acc;
        s.maskFlag = pflag;
        cvt_multi<<<(unsigned)((acc + 255) / 256), 256>>>(s);
    }

    GemmArgs a;
    // QKV = x @ wqkv^T  (Q section pre-scaled by 0.125*log2e)
    a = {xh,pwqkv, nullptr,qkv, NTOK,3*Dd,Dd, Dd,Dd,3*Dd, 1.0f, nullptr,0, nullptr,0, 1};
    run_gemm(a);
    // fused attention: av = softmax(Q K^T / 8 + mask) @ V   (V direct from qkv via ldmatrix.trans)
    {
        dim3 g(Ss/128, BH);
        flash_kernel<<<g, 256, FL_SMEM>>>(qkv, pmask, pflag, av);
    }
    // attn = av @ wc^T + x  (fp32)
    a = {av,pwc, attn,nullptr, NTOK,Dd,Dd, Dd,Dd,Dd, 1.0f, x,Dd, nullptr,0, 0};
    run_gemm(a);
    // u = LN1(attn)
    layernorm_kernel<<<NTOK, 256>>>(attn, u, uh, ln1_g, ln1_b);
    // h1 = relu(u @ w1^T + b1)
    a = {uh,pw1, nullptr,h1, NTOK,Mf,Dd, Dd,Dd,Mf, 1.0f, nullptr,0, w1_b,1, 0};
    run_gemm(a);
    // z = h1 @ w2^T + b2 + u  (fp32)
    a = {h1,pw2, z,nullptr, NTOK,Dd,Mf, Mf,Mf,Dd, 1.0f, u,Dd, w2_b,0, 0};
    run_gemm(a);
    // out = LN2(z)
    layernorm_kernel<<<NTOK, 256>>>(z, out, nullptr, ln2_g, ln2_b);
}

// round 14
// speedup vs baseline: 14.0771x; 1.0298x over previous
#include <cuda_runtime.h>
#include <cuda_fp16.h>
#include <cstdint>
#include <math.h>

#define Hh   16
#define Kh   64
#define Dd   1024
#define Mf   4096
#define Ss   2048
#define Bb   4
#define NTOK (Ss*Bb)      // 8192
#define BH   (Bb*Hh)      // 64
#define EPSL 1e-5f
#define LOG2E 1.44269504088896340736f
#define QSCALE (0.125f * LOG2E)

// ---------------- scratch buffers (device globals: allocation-free) ----------------
__device__ __half g_x[(size_t)NTOK*Dd];
__device__ __half g_wqkv[(size_t)3*Dd*Dd];
__device__ __half g_wc[(size_t)Dd*Dd];
__device__ __half g_w1[(size_t)Mf*Dd];
__device__ __half g_w2[(size_t)Mf*Dd];
__device__ __half g_maskh[(size_t)Ss*Ss];          // pre-scaled by log2(e)
__device__ int    g_maskflag;
__device__ __half g_qkv[(size_t)NTOK*3*Dd];        // Q section pre-scaled by 0.125*log2(e)
__device__ __half g_av[(size_t)NTOK*Dd];
__device__ float  g_attn[(size_t)NTOK*Dd];
__device__ float  g_u[(size_t)NTOK*Dd];
__device__ __half g_uh[(size_t)NTOK*Dd];
__device__ __half g_h1[(size_t)NTOK*Mf];
__device__ float  g_z[(size_t)NTOK*Dd];

// ---------------- helpers ----------------
__device__ __forceinline__ uint32_t smem_u32(const void* p){
    uint32_t a;
    asm("{ .reg .u64 t; cvta.to.shared.u64 t, %1; cvt.u32.u64 %0, t; }" : "=r"(a) : "l"(p));
    return a;
}
__device__ __forceinline__ uint32_t packf2(float lo, float hi){
    uint32_t r;
    asm("cvt.rn.f16x2.f32 %0, %1, %2;" : "=r"(r) : "f"(hi), "f"(lo));
    return r;
}
__device__ __forceinline__ uint32_t ex2h2(uint32_t x){
    uint32_t r;
    asm("ex2.approx.f16x2 %0, %1;" : "=r"(r) : "r"(x));
    return r;
}
__device__ __forceinline__ void cpasync16(uint32_t saddr, const void* gaddr){
    asm volatile("cp.async.cg.shared.global [%0], [%1], 16;" :: "r"(saddr), "l"(gaddr) : "memory");
}
__device__ __forceinline__ void ldmx4(uint32_t* r, uint32_t addr){
    asm volatile("ldmatrix.sync.aligned.m8n8.x4.shared.b16 {%0,%1,%2,%3}, [%4];"
                 : "=r"(r[0]), "=r"(r[1]), "=r"(r[2]), "=r"(r[3]) : "r"(addr));
}
__device__ __forceinline__ void ldmx4t(uint32_t* r, uint32_t addr){
    asm volatile("ldmatrix.sync.aligned.m8n8.x4.trans.shared.b16 {%0,%1,%2,%3}, [%4];"
                 : "=r"(r[0]), "=r"(r[1]), "=r"(r[2]), "=r"(r[3]) : "r"(addr));
}
__device__ __forceinline__ void mma16816(float* c, const uint32_t* a, const uint32_t* b){
    asm volatile("mma.sync.aligned.m16n8k16.row.col.f32.f16.f16.f32 "
                 "{%0,%1,%2,%3}, {%4,%5,%6,%7}, {%8,%9}, {%0,%1,%2,%3};"
                 : "+f"(c[0]), "+f"(c[1]), "+f"(c[2]), "+f"(c[3])
                 : "r"(a[0]), "r"(a[1]), "r"(a[2]), "r"(a[3]), "r"(b[0]), "r"(b[1]));
}

// ---------------- mma.sync fp16 NT GEMM, BK=64, 3-stage, ILP-pipelined ----------------
__global__ void __launch_bounds__(256,2) mma_gemm(
    const __half* __restrict__ A, const __half* __restrict__ B,
    float* __restrict__ Cf, __half* __restrict__ Ch,
    int Kd, long lda, long ldb, long ldc,
    float alpha, const float* __restrict__ add, long ldadd,
    const float* __restrict__ bias, int doRelu, int qkvMode)
{
    constexpr int BN   = 128;
    constexpr int BK   = 64;
    constexpr int LDS  = BK + 8;
    constexpr int WN   = BN / 2;
    constexpr int NT   = WN / 8;
    constexpr int A_BYTES = 128 * LDS * 2;
    constexpr int B_BYTES = BN  * LDS * 2;
    constexpr int STAGE   = A_BYTES + B_BYTES;

    extern __shared__ char smc[];
    const uint32_t sbase = smem_u32(smc);

    const int tid  = threadIdx.x;
    const int lane = tid & 31;
    const int wid  = tid >> 5;
    const int warpM = (wid & 3) * 32;
    const int warpN = (wid >> 2) * WN;

    const int  m0   = blockIdx.y * 128;
    const int  n0   = blockIdx.x * BN;
    const int  KT   = Kd / BK;

    const int la_row = tid >> 3, la_ch = tid & 7;
    // one eighth of a stage load (A or B, one 32-row pass)
    auto load_piece = [&](int kt, int buf, int piece){
        const int k0 = kt * BK;
        const uint32_t s0 = sbase + buf * STAGE;
        if (piece < 4){
            int row = la_row + piece * 32;
            long g = (long)(m0 + row) * lda + k0 + la_ch * 8;
            cpasync16(s0 + (uint32_t)(row * (LDS*2) + la_ch*16), A + g);
        } else {
            int row = la_row + (piece - 4) * 32;
            long g = (long)(n0 + row) * ldb + k0 + la_ch * 8;
            cpasync16(s0 + A_BYTES + (uint32_t)(row * (LDS*2) + la_ch*16), B + g);
        }
    };
    auto load_stage = [&](int kt, int buf){
        #pragma unroll
        for (int p = 0; p < 8; p++) load_piece(kt, buf, p);
    };

    load_stage(0, 0);
    asm volatile("cp.async.commit_group;" ::: "memory");
    load_stage(1, 1);
    asm volatile("cp.async.commit_group;" ::: "memory");

    float acc[2][NT][4];
    #pragma unroll
    for (int i = 0; i < 2; i++)
        #pragma unroll
        for (int j = 0; j < NT; j++)
            #pragma unroll
            for (int e = 0; e < 4; e++) acc[i][j][e] = 0.0f;

    const int aRow = (lane & 15), aColHalf = (lane >> 4) * 8;
    const int bRow = (lane >> 4) * 8 + (lane & 7), bColHalf = ((lane >> 3) & 1) * 8;

    int buf = 0;
    for (int kt = 0; kt < KT; kt++){
        asm volatile("cp.async.wait_group 1;" ::: "memory");
        __syncthreads();
        const uint32_t sA0 = sbase + buf * STAGE;
        const uint32_t sB0 = sA0 + A_BYTES;
        const bool pf = (kt + 2 < KT);
        int nbuf = buf + 2; if (nbuf >= 3) nbuf -= 3;

        #pragma unroll
        for (int ks = 0; ks < 4; ks++){
            const int k16 = ks * 16;
            // A frags + first B group
            uint32_t af[2][4];
            #pragma unroll
            for (int mt = 0; mt < 2; mt++){
                uint32_t addr = sA0 + (uint32_t)(((warpM + mt*16 + aRow) * LDS + k16 + aColHalf) * 2);
                ldmx4(af[mt], addr);
            }
            uint32_t bcur[4], bnext[4];
            ldmx4(bcur, sB0 + (uint32_t)(((warpN + bRow) * LDS + k16 + bColHalf) * 2));
            // spread next-stage cp.async: 2 pieces per ks
            if (pf){
                load_piece(kt + 2, nbuf, ks*2);
                load_piece(kt + 2, nbuf, ks*2 + 1);
            }
            // pipelined: LDSM group g+1 issued before MMAs of group g
            #pragma unroll
            for (int g = 0; g < NT/2; g++){
                uint32_t* bf = (g & 1) ? bnext : bcur;
                uint32_t* bl = (g & 1) ? bcur  : bnext;
                if (g + 1 < NT/2)
                    ldmx4(bl, sB0 + (uint32_t)(((warpN + (g+1)*16 + bRow) * LDS + k16 + bColHalf) * 2));
                #pragma unroll
                for (int mt = 0; mt < 2; mt++){
                    mma16816(acc[mt][2*g],   af[mt], bf+0);
                    mma16816(acc[mt][2*g+1], af[mt], bf+2);
                }
            }
        }
        asm volatile("cp.async.commit_group;" ::: "memory");
        if (++buf == 3) buf = 0;
    }

    #pragma unroll
    for (int mt = 0; mt < 2; mt++){
        #pragma unroll
        for (int j = 0; j < NT; j++){
            const int col = n0 + warpN + j*8 + (lane & 3) * 2;
            const float sc = qkvMode ? (((col % 3072) < 1024) ? QSCALE : 1.0f) : alpha;
            const float b0 = bias ? bias[col]   : 0.0f;
            const float b1 = bias ? bias[col+1] : 0.0f;
            #pragma unroll
            for (int half = 0; half < 2; half++){
                const long row = m0 + warpM + mt*16 + (lane >> 2) + half*8;
                float v0 = acc[mt][j][half*2+0] * sc + b0;
                float v1 = acc[mt][j][half*2+1] * sc + b1;
                if (add){
                    v0 += add[row * ldadd + col];
                    v1 += add[row * ldadd + col + 1];
                }
                if (doRelu){ v0 = fmaxf(v0, 0.0f); v1 = fmaxf(v1, 0.0f); }
                const long ci = row * ldc + col;
                if (Ch){
                    *(uint32_t*)(Ch + ci) = packf2(v0, v1);
                } else {
                    *(float2*)(Cf + ci) = make_float2(v0, v1);
                }
            }
        }
    }
}

// ---------------- fused flash attention (exp2, l-via-MMA, V via ldmatrix.trans) ----------------
#define FL_LQ 72
#define FL_QBYTES (128*FL_LQ*2)
#define FL_KB (64*FL_LQ*2)
#define FL_VB (64*FL_LQ*2)
#define FL_STAGE (FL_KB + FL_VB)
#define FL_SMQ   0
#define FL_SMST  FL_QBYTES
#define FL_SMEM  (FL_SMST + 3*FL_STAGE)      // 73728

__global__ void __launch_bounds__(256,2) flash_kernel(
    const __half* __restrict__ QKV,
    const __half* __restrict__ maskh,
    const int* __restrict__ maskFlag,
    __half* __restrict__ AV)
{
    extern __shared__ char smc[];
    const uint32_t sbase = smem_u32(smc);
    const int tid = threadIdx.x, lane = tid & 31, wid = tid >> 5;
    const int q0 = blockIdx.x * 128;
    const int z  = blockIdx.y;
    const long qOff = (long)(z >> 4) * 3072 + (long)(z & 15) * 64;
    const long kOff = qOff + 1024;
    const long vOff = qOff + 2048;
    const int hasMask = *maskFlag;

    auto load_q = [&](){
        #pragma unroll
        for (int it = 0; it < 4; it++){
            int idx = it*256 + tid;
            int row = idx >> 3, ch = idx & 7;
            long g = (long)(q0 + row) * 12288 + qOff + ch*8;
            uint32_t so = sbase + FL_SMQ + (uint32_t)(row*FL_LQ*2 + ch*16);
            cpasync16(so, QKV + g);
        }
    };
    auto load_stage = [&](int kt, int buf){
        const int t0 = kt * 64;
        const uint32_t s0 = sbase + FL_SMST + buf*FL_STAGE;
        #pragma unroll
        for (int it = 0; it < 2; it++){
            int idx = it*256 + tid;
            int row = idx >> 3, ch = idx & 7;
            long gk = (long)(t0 + row) * 12288 + kOff + ch*8;
            uint32_t so = s0 + (uint32_t)(row*FL_LQ*2 + ch*16);
            cpasync16(so, QKV + gk);
            long gv = (long)(t0 + row) * 12288 + vOff + ch*8;
            cpasync16(so + FL_KB, QKV + gv);
        }
    };

    load_q();
    load_stage(0, 0);
    asm volatile("cp.async.commit_group;" ::: "memory");
    load_stage(1, 1);
    asm volatile("cp.async.commit_group;" ::: "memory");
    asm volatile("cp.async.wait_group 1;" ::: "memory");
    __syncthreads();

    const int aRow = lane & 15, aCol = (lane >> 4) * 8;
    const int bRow = (lane >> 4) * 8 + (lane & 7), bCol = ((lane >> 3) & 1) * 8;

    uint32_t qf[4][4];
    #pragma unroll
    for (int kc = 0; kc < 4; kc++){
        uint32_t addr = sbase + FL_SMQ + (uint32_t)(((wid*16 + aRow)*FL_LQ + kc*16 + aCol) * 2);
        ldmx4(qf[kc], addr);
    }

    float O[8][4];
    #pragma unroll
    for (int j = 0; j < 8; j++){ O[j][0]=0; O[j][1]=0; O[j][2]=0; O[j][3]=0; }
    float lacc[4] = {0.0f, 0.0f, 0.0f, 0.0f};
    const uint32_t onesfrag[2] = {0x3C003C00u, 0x3C003C00u};
    float m0 = -INFINITY, m1 = -INFINITY;
    const int rloc = wid*16 + (lane >> 2);

    int buf = 0;
    for (int kt = 0; kt < 32; kt++){
        asm volatile("cp.async.wait_group 1;" ::: "memory");
        __syncthreads();
        const uint32_t sK = sbase + FL_SMST + buf*FL_STAGE;
        const uint32_t sV = sK + FL_KB;

        float S[8][4];
        #pragma unroll
        for (int j = 0; j < 8; j++){ S[j][0]=0; S[j][1]=0; S[j][2]=0; S[j][3]=0; }

        // S = Qs @ K^T  (B-LDSM ahead-by-one)
        {
            uint32_t bcur[4], bnext[4];
            ldmx4(bcur, sK + (uint32_t)(((bRow) * FL_LQ + bCol) * 2));
            #pragma unroll
            for (int kc = 0; kc < 4; kc++){
                #pragma unroll
                for (int g = 0; g < 4; g++){
                    uint32_t* bk = ((kc*4 + g) & 1) ? bnext : bcur;
                    uint32_t* bl = ((kc*4 + g) & 1) ? bcur  : bnext;
                    int ng = g + 1, nkc = kc;
                    if (ng == 4){ ng = 0; nkc = kc + 1; }
                    if (nkc < 4)
                        ldmx4(bl, sK + (uint32_t)(((ng*16 + bRow)*FL_LQ + nkc*16 + bCol) * 2));
                    mma16816(S[2*g],   qf[kc], bk+0);
                    mma16816(S[2*g+1], qf[kc], bk+2);
                }
            }
        }

        // + mask (only when nonzero) + running max
        const int t0 = kt * 64;
        float mx0 = -INFINITY, mx1 = -INFINITY;
        if (hasMask){
            const long mr0 = (long)(q0 + rloc) * 2048 + t0;
            const long mr1 = mr0 + 8 * 2048;
            #pragma unroll
            for (int j = 0; j < 8; j++){
                int c = j*8 + (lane & 3)*2;
                float2 k0v = __half22float2(*(const __half2*)(maskh + mr0 + c));
                float2 k1v = __half22float2(*(const __half2*)(maskh + mr1 + c));
                S[j][0] += k0v.x;
                S[j][1] += k0v.y;
                S[j][2] += k1v.x;
                S[j][3] += k1v.y;
                mx0 = fmaxf(mx0, fmaxf(S[j][0], S[j][1]));
                mx1 = fmaxf(mx1, fmaxf(S[j][2], S[j][3]));
            }
        } else {
            #pragma unroll
            for (int j = 0; j < 8; j++){
                mx0 = fmaxf(mx0, fmaxf(S[j][0], S[j][1]));
                mx1 = fmaxf(mx1, fmaxf(S[j][2], S[j][3]));
            }
        }
        mx0 = fmaxf(mx0, __shfl_xor_sync(0xFFFFFFFFu, mx0, 1));
        mx0 = fmaxf(mx0, __shfl_xor_sync(0xFFFFFFFFu, mx0, 2));
        mx1 = fmaxf(mx1, __shfl_xor_sync(0xFFFFFFFFu, mx1, 1));
        mx1 = fmaxf(mx1, __shfl_xor_sync(0xFFFFFFFFu, mx1, 2));
        float nm0 = fmaxf(m0, mx0), nm1 = fmaxf(m1, mx1);

        bool re = (nm0 != m0) || (nm1 != m1);
        if (__any_sync(0xFFFFFFFFu, re)){
            float f0 = (m0 > -INFINITY) ? exp2f(m0 - nm0) : 0.0f;
            float f1 = (m1 > -INFINITY) ? exp2f(m1 - nm1) : 0.0f;
            #pragma unroll
            for (int j = 0; j < 8; j++){
                O[j][0]*=f0; O[j][1]*=f0; O[j][2]*=f1; O[j][3]*=f1;
            }
            lacc[0]*=f0; lacc[1]*=f0; lacc[2]*=f1; lacc[3]*=f1;
        }
        m0 = nm0; m1 = nm1;

        // P = exp2(S-m); l += P@ones; O += P@V (V-LDSM ahead-by-one, trans)
        {
            uint32_t vcur[4], vnext[4];
            ldmx4t(vcur, sV + (uint32_t)(((aRow)*FL_LQ + aCol) * 2));
            #pragma unroll
            for (int kc = 0; kc < 4; kc++){
                uint32_t ph[4];
                ph[0] = ex2h2(packf2(S[2*kc][0]   - m0, S[2*kc][1]   - m0));
                ph[1] = ex2h2(packf2(S[2*kc][2]   - m1, S[2*kc][3]   - m1));
                ph[2] = ex2h2(packf2(S[2*kc+1][0] - m0, S[2*kc+1][1] - m0));
                ph[3] = ex2h2(packf2(S[2*kc+1][2] - m1, S[2*kc+1][3] - m1));
                mma16816(lacc, ph, onesfrag);
                #pragma unroll
                for (int g = 0; g < 4; g++){
                    uint32_t* vf = ((kc*4 + g) & 1) ? vnext : vcur;
                    uint32_t* vl = ((kc*4 + g) & 1) ? vcur  : vnext;
                    int ng = g + 1, nkc = kc;
                    if (ng == 4){ ng = 0; nkc = kc + 1; }
                    if (nkc < 4)
                        ldmx4t(vl, sV + (uint32_t)(((nkc*16 + aRow)*FL_LQ + ng*16 + aCol) * 2));
                    mma16816(O[2*g],   ph, vf+0);
                    mma16816(O[2*g+1], ph, vf+2);
                }
            }
        }

        if (kt + 2 < 32){
            int nbuf = buf + 2; if (nbuf >= 3) nbuf -= 3;
            load_stage(kt + 2, nbuf);
        }
        asm volatile("cp.async.commit_group;" ::: "memory");
        if (++buf == 3) buf = 0;
    }

    // finalize
    const long hOff = (long)z * 64;
    const float inv0 = 1.0f / lacc[0], inv1 = 1.0f / lacc[2];
    #pragma unroll
    for (int j = 0; j < 8; j++){
        const int col = j*8 + (lane & 3)*2;
        const long a0 = (long)(q0 + rloc) * 4096 + hOff + col;
        const long a1 = a0 + 8L * 4096;
        *(uint32_t*)(AV + a0) = packf2(O[j][0]*inv0, O[j][1]*inv0);
        *(uint32_t*)(AV + a1) = packf2(O[j][2]*inv1, O[j][3]*inv1);
    }
}

// ---------------- fused fp32 -> fp16 conversion; seg7 = mask (scaled, sets flag) ----------------
struct CvtSegs {
    const float4* in[8];
    uint2*        out[8];
    long          start[9];
    int*          maskFlag;
};
__global__ void cvt_multi(CvtSegs s)
{
    long i = (long)blockIdx.x * 256 + threadIdx.x;
    if (i >= s.start[8]) return;
    int seg = 0;
    #pragma unroll
    for (int k = 1; k < 8; k++) if (i >= s.start[k]) seg = k;
    long j = i - s.start[seg];
    float4 v = s.in[seg][j];
    if (seg == 7){
        if (v.x != 0.0f || v.y != 0.0f || v.z != 0.0f || v.w != 0.0f)
            atomicOr(s.maskFlag, 1);
        v.x *= LOG2E; v.y *= LOG2E; v.z *= LOG2E; v.w *= LOG2E;
    }
    uint2 H;
    H.x = packf2(v.x, v.y);
    H.y = packf2(v.z, v.w);
    s.out[seg][j] = H;
}

// ---------------- layernorm over D=1024; optional fp16 output ----------------
__global__ void layernorm_kernel(const float* __restrict__ in,
                                 float* __restrict__ out,
                                 __half* __restrict__ oh,
                                 const float* __restrict__ gamma,
                                 const float* __restrict__ beta)
{
    const int row = blockIdx.x;
    const float* x = in + (size_t)row * Dd;
    const int tid = threadIdx.x;

    float v[4];
    float s = 0.0f, s2 = 0.0f;
    #pragma unroll
    for (int i = 0; i < 4; i++){
        v[i] = x[tid + i*256];
        s  += v[i];
        s2 += v[i]*v[i];
    }
    __shared__ float r1[256], r2[256];
    r1[tid] = s; r2[tid] = s2; __syncthreads();
    for (int off = 128; off > 0; off >>= 1){
        if (tid < off){ r1[tid] += r1[tid+off]; r2[tid] += r2[tid+off]; }
        __syncthreads();
    }
    float mean = r1[0] * (1.0f/Dd);
    float var  = r2[0] * (1.0f/Dd) - mean*mean;
    float inv  = rsqrtf(var + EPSL);
    #pragma unroll
    for (int i = 0; i < 4; i++){
        int c = tid + i*256;
        float y = (v[i] - mean) * inv * gamma[c] + beta[c];
        out[(size_t)row*Dd + c] = y;
        if (oh) oh[(size_t)row*Dd + c] = __float2half_rn(y);
    }
}

// ---------------- host side ----------------
static const int SMEM_GEMM = 3 * 36864;   // 110592

struct GemmArgs {
    const __half *A, *B;
    float* Cf; __half *Ch;
    int M, N, Kd; long lda, ldb, ldc;
    float alpha; const float* add; long ldadd; const float* bias; int relu; int qkvMode;
};

static inline void run_gemm(const GemmArgs& a){
    dim3 grid(a.N / 128, a.M / 128, 1);
    mma_gemm<<<grid, 256, SMEM_GEMM>>>(a.A, a.B, a.Cf, a.Ch,
                                       a.Kd, a.lda, a.ldb, a.ldc,
                                       a.alpha, a.add, a.ldadd, a.bias, a.relu, a.qkvMode);
}

extern "C" void kernel_launch(void* const* d_in, const int* in_sizes, int n_in,
                              void* d_out, int out_size)
{
    const float* x     = (const float*)d_in[0];
    const float* mask  = (const float*)d_in[1];
    const float* wq    = (const float*)d_in[2];
    const float* wk    = (const float*)d_in[3];
    const float* wv    = (const float*)d_in[4];
    const float* wc    = (const float*)d_in[5];
    const float* w1_w  = (const float*)d_in[6];
    const float* w1_b  = (const float*)d_in[7];
    const float* w2_w  = (const float*)d_in[8];
    const float* w2_b  = (const float*)d_in[9];
    const float* ln1_g = (const float*)d_in[10];
    const float* ln1_b = (const float*)d_in[11];
    const float* ln2_g = (const float*)d_in[12];
    const float* ln2_b = (const float*)d_in[13];
    float* out = (float*)d_out;

    cudaFuncSetAttribute((const void*)mma_gemm,     cudaFuncAttributeMaxDynamicSharedMemorySize, SMEM_GEMM);
    cudaFuncSetAttribute((const void*)flash_kernel, cudaFuncAttributeMaxDynamicSharedMemorySize, FL_SMEM);

    __half *xh,*pwqkv,*pwc,*pw1,*pw2,*pmask;
    __half *qkv,*av,*uh,*h1;
    float *attn,*u,*z;
    int* pflag;
    cudaGetSymbolAddress((void**)&xh,    g_x);
    cudaGetSymbolAddress((void**)&pwqkv, g_wqkv);
    cudaGetSymbolAddress((void**)&pwc,   g_wc);
    cudaGetSymbolAddress((void**)&pw1,   g_w1);
    cudaGetSymbolAddress((void**)&pw2,   g_w2);
    cudaGetSymbolAddress((void**)&pmask, g_maskh);
    cudaGetSymbolAddress((void**)&pflag, g_maskflag);
    cudaGetSymbolAddress((void**)&qkv,   g_qkv);
    cudaGetSymbolAddress((void**)&av,    g_av);
    cudaGetSymbolAddress((void**)&attn,  g_attn);
    cudaGetSymbolAddress((void**)&u,     g_u);
    cudaGetSymbolAddress((void**)&uh,    g_uh);
    cudaGetSymbolAddress((void**)&h1,    g_h1);
    cudaGetSymbolAddress((void**)&z,     g_z);

    cudaMemsetAsync(pflag, 0, sizeof(int));

    {
        CvtSegs s;
        const float* srcs[8] = {x, wq, wk, wv, wc, w1_w, w2_w, mask};
        __half*      dsts[8] = {xh, pwqkv, pwqkv + (size_t)Dd*Dd, pwqkv + (size_t)2*Dd*Dd,
                                pwc, pw1, pw2, pmask};
        long lens[8] = {(long)NTOK*Dd, (long)Dd*Dd, (long)Dd*Dd, (long)Dd*Dd,
                        (long)Dd*Dd, (long)Mf*Dd, (long)Mf*Dd, (long)Ss*Ss};
        long acc = 0;
        for (int i = 0; i < 8; i++){
            s.in[i]  = (const float4*)srcs[i];
            s.out[i] = (uint2*)dsts[i];
            s.start[i] = acc;
            acc += lens[i] / 4;
        }
        s.start[8] = acc;
        s.maskFlag = pflag;
        cvt_multi<<<(unsigned)((acc + 255) / 256), 256>>>(s);
    }

    GemmArgs a;
    // QKV = x @ wqkv^T
    a = {xh,pwqkv, nullptr,qkv, NTOK,3*Dd,Dd, Dd,Dd,3*Dd, 1.0f, nullptr,0, nullptr,0, 1};
    run_gemm(a);
    // fused attention
    {
        dim3 g(Ss/128, BH);
        flash_kernel<<<g, 256, FL_SMEM>>>(qkv, pmask, pflag, av);
    }
    // attn = av @ wc^T + x  (fp32)
    a = {av,pwc, attn,nullptr, NTOK,Dd,Dd, Dd,Dd,Dd, 1.0f, x,Dd, nullptr,0, 0};
    run_gemm(a);
    // u = LN1(attn)
    layernorm_kernel<<<NTOK, 256>>>(attn, u, uh, ln1_g, ln1_b);
    // h1 = relu(u @ w1^T + b1)
    a = {uh,pw1, nullptr,h1, NTOK,Mf,Dd, Dd,Dd,Mf, 1.0f, nullptr,0, w1_b,1, 0};
    run_gemm(a);
    // z = h1 @ w2^T + b2 + u  (fp32)
    a = {h1,pw2, z,nullptr, NTOK,Dd,Mf, Mf,Mf,Dd, 1.0f, u,Dd, w2_b,0, 0};
    run_gemm(a);
    // out = LN2(z)
    layernorm_kernel<<<NTOK, 256>>>(z, out, nullptr, ln2_g, ln2_b);
}